// round 7
// baseline (speedup 1.0000x reference)
#include <cuda_runtime.h>
#include <cuda_bf16.h>
#include <math.h>
#include <stdint.h>

// ---------------- problem constants ----------------
#define BB   16
#define TT   4096
#define NR   (BB*TT)
#define TSD  64
#define DE   128
#define HH   256
#define LDF  512
#define LDH  256
#define OD   10
#define NBLKS 6
#define EPSV 1e-5f
#define NCH  16
#define CLEN 256

// ---------------- activation planes (hi/lo bf16 = fp32-equivalent) ----------------
static __device__ __align__(256) __nv_bfloat16 g_xh [(size_t)NR*TSD];
static __device__ __align__(256) __nv_bfloat16 g_xl [(size_t)NR*TSD];
static __device__ __align__(256) __nv_bfloat16 g_yeh[(size_t)NR*DE];
static __device__ __align__(256) __nv_bfloat16 g_yel[(size_t)NR*DE];
static __device__ __align__(256) __nv_bfloat16 g_hh [(size_t)NR*DE];
static __device__ __align__(256) __nv_bfloat16 g_hl [(size_t)NR*DE];
static __device__ __align__(256) __nv_bfloat16 g_buh[(size_t)NR*512];   // Bu, then state (in place)
static __device__ __align__(256) __nv_bfloat16 g_bul[(size_t)NR*512];
static __device__ __align__(256) __nv_bfloat16 g_lrh[(size_t)NR*DE];
static __device__ __align__(256) __nv_bfloat16 g_lrl[(size_t)NR*DE];
static __device__ __align__(256) __nv_bfloat16 g_glh[(size_t)NR*LDH];
static __device__ __align__(256) __nv_bfloat16 g_gll[(size_t)NR*LDH];

static __device__ float2 g_lam [NBLKS*HH];
static __device__ float  g_gamma[NBLKS*HH];
static __device__ float  g_bnpart[512*2*DE];
static __device__ float  g_bna[DE];
static __device__ float  g_bnb[DE];
static __device__ float  g_bubias[512];
static __device__ float2 g_carry[BB*NCH*HH];
static __device__ float2 g_inc  [BB*NCH*HH];

// weights: fp32 master for WB (BN folded per block), split planes for the rest
static __device__ __align__(256) float          g_WBf[(size_t)NBLKS*512*128];
static __device__ __align__(256) __nv_bfloat16  g_WBbh[512*128];
static __device__ __align__(256) __nv_bfloat16  g_WBbl[512*128];
static __device__ __align__(256) __nv_bfloat16 g_WCh[(size_t)NBLKS*128*512];
static __device__ __align__(256) __nv_bfloat16 g_WCl[(size_t)NBLKS*128*512];
static __device__ __align__(256) __nv_bfloat16 g_W1h[(size_t)NBLKS*512*128];
static __device__ __align__(256) __nv_bfloat16 g_W1l[(size_t)NBLKS*512*128];
static __device__ __align__(256) __nv_bfloat16 g_W2h[(size_t)NBLKS*128*256];
static __device__ __align__(256) __nv_bfloat16 g_W2l[(size_t)NBLKS*128*256];
static __device__ __align__(256) __nv_bfloat16 g_WEh[128*64];
static __device__ __align__(256) __nv_bfloat16 g_WEl[128*64];

// ---------------- helpers ----------------
__device__ __forceinline__ uint32_t smem_u32(const void* p) {
    uint32_t a;
    asm("{ .reg .u64 t; cvta.to.shared.u64 t, %1; cvt.u32.u64 %0, t; }" : "=r"(a) : "l"(p));
    return a;
}
__device__ __forceinline__ void cp16(uint32_t dst, const void* src) {
    asm volatile("cp.async.cg.shared.global [%0], [%1], 16;" :: "r"(dst), "l"(src));
}
#define CP_COMMIT() asm volatile("cp.async.commit_group;" ::: "memory")
#define CP_WAIT0()  asm volatile("cp.async.wait_group 0;" ::: "memory")

#define MMA_BF16(d, a0, a1, a2, a3, b0, b1) \
    asm volatile("mma.sync.aligned.m16n8k16.row.col.f32.bf16.bf16.f32 " \
        "{%0,%1,%2,%3}, {%4,%5,%6,%7}, {%8,%9}, {%0,%1,%2,%3};" \
        : "+f"((d)[0]), "+f"((d)[1]), "+f"((d)[2]), "+f"((d)[3]) \
        : "r"(a0), "r"(a1), "r"(a2), "r"(a3), "r"(b0), "r"(b1))

__device__ __forceinline__ void wr_planes(__nv_bfloat16* ph, __nv_bfloat16* pl, size_t off, float2 v) {
    __nv_bfloat162 h2, l2;
    h2.x = __float2bfloat16(v.x);
    h2.y = __float2bfloat16(v.y);
    l2.x = __float2bfloat16(v.x - __bfloat162float(h2.x));
    l2.y = __float2bfloat16(v.y - __bfloat162float(h2.y));
    *(__nv_bfloat162*)(ph + off) = h2;
    *(__nv_bfloat162*)(pl + off) = l2;
}
__device__ __forceinline__ float2 rd_planes(const __nv_bfloat16* ph, const __nv_bfloat16* pl, size_t off) {
    __nv_bfloat162 h2 = *(const __nv_bfloat162*)(ph + off);
    __nv_bfloat162 l2 = *(const __nv_bfloat162*)(pl + off);
    return make_float2(__bfloat162float(h2.x) + __bfloat162float(l2.x),
                       __bfloat162float(h2.y) + __bfloat162float(l2.y));
}
__device__ __forceinline__ void split_store(float v, __nv_bfloat16* hi, __nv_bfloat16* lo, size_t i) {
    __nv_bfloat16 h = __float2bfloat16(v);
    hi[i] = h;
    lo[i] = __float2bfloat16(v - __bfloat162float(h));
}

// ---------------- prep ----------------
__global__ void prep_lam_kernel(const float* __restrict__ nu_log,
                                const float* __restrict__ theta_log) {
    int blk = blockIdx.x;
    int h   = threadIdx.x;
    float nu = nu_log[blk*HH + h];
    float th = theta_log[blk*HH + h];
    float r  = expf(-expf(nu));
    float ang = expf(th);
    float sn, cs;
    sincosf(ang, &sn, &cs);
    float2 lam; lam.x = r*cs; lam.y = r*sn;
    g_lam[blk*HH + h]   = lam;
    g_gamma[blk*HH + h] = sqrtf(fmaxf(1.f - r*r, 1e-8f));
}
__global__ void prep_WBf_kernel(const float* __restrict__ Bre, const float* __restrict__ Bim) {
    int idx = blockIdx.x*256 + threadIdx.x;
    if (idx >= NBLKS*512*DE) return;
    int k = idx & 127;
    int n = (idx >> 7) & 511;
    int blk = idx >> 16;
    int h = n >> 1;
    float g = g_gamma[blk*HH + h];
    g_WBf[idx] = ((n & 1) ? Bim : Bre)[((size_t)blk*HH + h)*DE + k] * g;
}
__global__ void prep_WC_kernel(const float* __restrict__ Cre, const float* __restrict__ Cim) {
    int idx = blockIdx.x*256 + threadIdx.x;
    if (idx >= NBLKS*DE*512) return;
    int k = idx & 511;
    int n = (idx >> 9) & 127;
    int blk = idx >> 16;
    int h = k >> 1;
    float v = (k & 1) ? -Cim[((size_t)blk*DE + n)*HH + h] : Cre[((size_t)blk*DE + n)*HH + h];
    split_store(v, g_WCh, g_WCl, idx);
}
__global__ void prep_W1_kernel(const float* __restrict__ W1) {
    int idx = blockIdx.x*256 + threadIdx.x;
    if (idx >= NBLKS*512*DE) return;
    int k = idx & 127;
    int n = (idx >> 7) & 511;
    int blk = idx >> 16;
    split_store(W1[((size_t)blk*DE + k)*LDF + n], g_W1h, g_W1l, idx);
}
__global__ void prep_W2_kernel(const float* __restrict__ W2) {
    int idx = blockIdx.x*256 + threadIdx.x;
    if (idx >= NBLKS*DE*256) return;
    int k = idx & 255;
    int n = (idx >> 8) & 127;
    int blk = idx >> 15;
    split_store(W2[((size_t)blk*LDH + k)*DE + n], g_W2h, g_W2l, idx);
}
__global__ void prep_WE_kernel(const float* __restrict__ We) {
    int idx = blockIdx.x*256 + threadIdx.x;
    if (idx >= DE*TSD) return;
    int k = idx & 63;
    int n = idx >> 6;
    split_store(We[(size_t)k*DE + n], g_WEh, g_WEl, idx);
}
__global__ void split_x_kernel(const float* __restrict__ x) {
    int idx = blockIdx.x*256 + threadIdx.x;
    if (idx >= NR*TSD) return;
    split_store(x[idx], g_xh, g_xl, idx);
}

// ---------------- BN: finalize stats + fold into Bu weights ----------------
__global__ void bn_stats2_kernel(const float* __restrict__ scale,
                                 const float* __restrict__ bias) {
    int f = threadIdx.x;
    float s = 0.f, s2 = 0.f;
    for (int i = 0; i < 512; i++) {
        s  += g_bnpart[i*(2*DE) + f];
        s2 += g_bnpart[i*(2*DE) + DE + f];
    }
    float mean = s * (1.f/NR);
    float var  = s2 * (1.f/NR) - mean*mean;
    float a = scale[f] * rsqrtf(var + EPSV);
    g_bna[f] = a;
    g_bnb[f] = fmaf(-mean, a, bias[f]);
}
__global__ void fold_WB_kernel(int blk) {
    int idx = blockIdx.x*256 + threadIdx.x;   // 65536
    int k = idx & 127;
    float v = g_WBf[(size_t)blk*512*128 + idx] * g_bna[k];
    split_store(v, g_WBbh, g_WBbl, idx);
}
__global__ void fold_bias_kernel(int blk) {
    int n = blockIdx.x*256 + threadIdx.x;     // 512
    const float* w = g_WBf + (size_t)blk*512*128 + (size_t)n*128;
    float s = 0.f;
    #pragma unroll 4
    for (int k = 0; k < 128; k++) s = fmaf(g_bnb[k], w[k], s);
    g_bubias[n] = s;
}

// ---------------- pipelined bf16x3 plane GEMM, K-chunk 64, pitch 72 ----------------
// A given as pre-split hi/lo planes -> mainloop = cp.async + LDS + MMA only.
// D = Ahi*Bhi + Alo*Bhi + Ahi*Blo.
// EPI: 0 = +bias?;  1 = + (bna*aux+bnb)*dvec (aux = planes);  2 = +bias + aux planes residual.
// DUAL: fused GLU.  STATS: per-CTA BN partials (grid.x must be 1).
#define PITCH 72
#define UNITE (128*PITCH)
#define STAGEE (4*UNITE)
#define SMEM_BYTES (2*STAGEE*2)   // 147456

template<int KDIM, int OUTW, int EPI, int DUAL, int STATS>
__global__ void __launch_bounds__(256) gemm_mma(
    const __nv_bfloat16* __restrict__ Ahi, const __nv_bfloat16* __restrict__ Alo,
    const __nv_bfloat16* __restrict__ Bhi, const __nv_bfloat16* __restrict__ Blo,
    __nv_bfloat16* __restrict__ Chi, __nv_bfloat16* __restrict__ Clo,
    const float* __restrict__ bias,
    const __nv_bfloat16* __restrict__ auxh, const __nv_bfloat16* __restrict__ auxl,
    const float* __restrict__ dvec)
{
    constexpr int O_AH = 0, O_AL = UNITE, O_BH = 2*UNITE, O_BL = 3*UNITE;
    constexpr int NCHK = KDIM / 64;

    extern __shared__ __nv_bfloat16 sm[];
    const uint32_t smb = smem_u32(sm);
    const int tid  = threadIdx.x;
    const int wid  = tid >> 5;
    const int lane = tid & 31;
    const int wr   = wid & 3;
    const int wc2  = wid >> 2;
    const int g    = lane >> 2;
    const int t    = lane & 3;
    const int bm   = blockIdx.y << 7;
    const int bn   = DUAL ? (blockIdx.x << 6) : (blockIdx.x << 7);

    float accg[2][DUAL ? 4 : 8][4];
    float accs[DUAL ? 2 : 1][DUAL ? 4 : 1][4];
    #pragma unroll
    for (int rb = 0; rb < 2; rb++)
        #pragma unroll
        for (int nb = 0; nb < (DUAL ? 4 : 8); nb++)
            #pragma unroll
            for (int j = 0; j < 4; j++) {
                accg[rb][nb][j] = 0.f;
                if (DUAL) accs[rb][nb][j] = 0.f;
            }

    auto cpA = [&](int cc, int so) {
        #pragma unroll
        for (int i = 0; i < 8; i++) {
            int idx = tid + 256*i;               // 0..2047
            int pl  = idx >> 10;                 // 0 hi, 1 lo
            int rem = idx & 1023;
            int r   = rem >> 3;
            int q   = rem & 7;
            const __nv_bfloat16* src = pl ? Alo : Ahi;
            cp16(smb + (uint32_t)((so + (pl ? O_AL : O_AH) + r*PITCH + q*8)*2),
                 src + (size_t)(bm + r)*KDIM + cc*64 + q*8);
        }
    };
    auto cpB = [&](int cc, int so) {
        #pragma unroll
        for (int i = 0; i < 8; i++) {
            int idx = tid + 256*i;
            int pl  = idx >> 10;
            int rem = idx & 1023;
            int r   = rem >> 3;
            int q   = rem & 7;
            int rowg = DUAL ? (r < 64 ? bn + r : bn + 256 + (r - 64)) : (bn + r);
            const __nv_bfloat16* src = pl ? Blo : Bhi;
            cp16(smb + (uint32_t)((so + (pl ? O_BL : O_BH) + r*PITCH + q*8)*2),
                 src + (size_t)rowg*KDIM + cc*64 + q*8);
        }
    };

    cpA(0, 0);
    cpB(0, 0);
    CP_COMMIT();

    #pragma unroll 1
    for (int c = 0; c < NCHK; c++) {
        const int so = (c & 1)*STAGEE;
        CP_WAIT0();
        __syncthreads();
        if (c + 1 < NCHK) {
            const int nso = ((c+1) & 1)*STAGEE;
            cpA(c+1, nso);
            cpB(c+1, nso);
            CP_COMMIT();
        }

        #pragma unroll
        for (int kk = 0; kk < 4; kk++) {
            const int kb = kk*16 + 2*t;
            uint32_t ah[2][4], al[2][4];
            #pragma unroll
            for (int rb = 0; rb < 2; rb++) {
                int ao = so + (32*wr + 16*rb + g)*PITCH + kb;
                ah[rb][0] = *(const uint32_t*)(sm + O_AH + ao);
                ah[rb][1] = *(const uint32_t*)(sm + O_AH + ao + 8*PITCH);
                ah[rb][2] = *(const uint32_t*)(sm + O_AH + ao + 8);
                ah[rb][3] = *(const uint32_t*)(sm + O_AH + ao + 8*PITCH + 8);
                al[rb][0] = *(const uint32_t*)(sm + O_AL + ao);
                al[rb][1] = *(const uint32_t*)(sm + O_AL + ao + 8*PITCH);
                al[rb][2] = *(const uint32_t*)(sm + O_AL + ao + 8);
                al[rb][3] = *(const uint32_t*)(sm + O_AL + ao + 8*PITCH + 8);
            }
            if (!DUAL) {
                #pragma unroll
                for (int nb = 0; nb < 8; nb++) {
                    int bo = so + (64*wc2 + 8*nb + g)*PITCH + kb;
                    uint32_t b0 = *(const uint32_t*)(sm + O_BH + bo);
                    uint32_t b1 = *(const uint32_t*)(sm + O_BH + bo + 8);
                    uint32_t c0 = *(const uint32_t*)(sm + O_BL + bo);
                    uint32_t c1 = *(const uint32_t*)(sm + O_BL + bo + 8);
                    #pragma unroll
                    for (int rb = 0; rb < 2; rb++) {
                        MMA_BF16(accg[rb][nb], ah[rb][0], ah[rb][1], ah[rb][2], ah[rb][3], b0, b1);
                        MMA_BF16(accg[rb][nb], al[rb][0], al[rb][1], al[rb][2], al[rb][3], b0, b1);
                        MMA_BF16(accg[rb][nb], ah[rb][0], ah[rb][1], ah[rb][2], ah[rb][3], c0, c1);
                    }
                }
            } else {
                #pragma unroll
                for (int nb = 0; nb < 4; nb++) {
                    int rg = 32*wc2 + 8*nb + g;
                    int bo  = so + rg*PITCH + kb;
                    int so2 = so + (64 + rg)*PITCH + kb;
                    uint32_t b0 = *(const uint32_t*)(sm + O_BH + bo);
                    uint32_t b1 = *(const uint32_t*)(sm + O_BH + bo + 8);
                    uint32_t c0 = *(const uint32_t*)(sm + O_BL + bo);
                    uint32_t c1 = *(const uint32_t*)(sm + O_BL + bo + 8);
                    uint32_t d0 = *(const uint32_t*)(sm + O_BH + so2);
                    uint32_t d1 = *(const uint32_t*)(sm + O_BH + so2 + 8);
                    uint32_t e0 = *(const uint32_t*)(sm + O_BL + so2);
                    uint32_t e1 = *(const uint32_t*)(sm + O_BL + so2 + 8);
                    #pragma unroll
                    for (int rb = 0; rb < 2; rb++) {
                        MMA_BF16(accg[rb][nb], ah[rb][0], ah[rb][1], ah[rb][2], ah[rb][3], b0, b1);
                        MMA_BF16(accg[rb][nb], al[rb][0], al[rb][1], al[rb][2], al[rb][3], b0, b1);
                        MMA_BF16(accg[rb][nb], ah[rb][0], ah[rb][1], ah[rb][2], ah[rb][3], c0, c1);
                        MMA_BF16(accs[rb][nb], ah[rb][0], ah[rb][1], ah[rb][2], ah[rb][3], d0, d1);
                        MMA_BF16(accs[rb][nb], al[rb][0], al[rb][1], al[rb][2], al[rb][3], d0, d1);
                        MMA_BF16(accs[rb][nb], ah[rb][0], ah[rb][1], ah[rb][2], ah[rb][3], e0, e1);
                    }
                }
            }
        }
    }

    // ---- epilogue ----
    float cs0[STATS ? 8 : 1], cs1[STATS ? 8 : 1], cq0[STATS ? 8 : 1], cq1[STATS ? 8 : 1];
    if (STATS) {
        #pragma unroll
        for (int nb = 0; nb < 8; nb++) { cs0[nb]=0.f; cs1[nb]=0.f; cq0[nb]=0.f; cq1[nb]=0.f; }
    }
    #pragma unroll
    for (int rb = 0; rb < 2; rb++) {
        int m0 = bm + 32*wr + 16*rb + g;
        #pragma unroll
        for (int nb = 0; nb < (DUAL ? 4 : 8); nb++) {
            if (!DUAL) {
                int col = bn + 64*wc2 + 8*nb + 2*t;
                float2 v0 = make_float2(accg[rb][nb][0], accg[rb][nb][1]);
                float2 v1 = make_float2(accg[rb][nb][2], accg[rb][nb][3]);
                if (EPI == 0) {
                    if (bias != nullptr) {
                        float2 bv = *(const float2*)(bias + col);
                        v0.x += bv.x; v0.y += bv.y; v1.x += bv.x; v1.y += bv.y;
                    }
                } else if (EPI == 1) {
                    float2 aa = *(const float2*)(g_bna + col);
                    float2 ab = *(const float2*)(g_bnb + col);
                    float2 dv = *(const float2*)(dvec + col);
                    float2 h0 = rd_planes(auxh, auxl, (size_t)m0*DE + col);
                    float2 h1 = rd_planes(auxh, auxl, (size_t)(m0+8)*DE + col);
                    v0.x += fmaf(aa.x, h0.x, ab.x)*dv.x;
                    v0.y += fmaf(aa.y, h0.y, ab.y)*dv.y;
                    v1.x += fmaf(aa.x, h1.x, ab.x)*dv.x;
                    v1.y += fmaf(aa.y, h1.y, ab.y)*dv.y;
                } else if (EPI == 2) {
                    float2 bv = *(const float2*)(bias + col);
                    float2 y0 = rd_planes(auxh, auxl, (size_t)m0*OUTW + col);
                    float2 y1 = rd_planes(auxh, auxl, (size_t)(m0+8)*OUTW + col);
                    v0.x += bv.x + y0.x; v0.y += bv.y + y0.y;
                    v1.x += bv.x + y1.x; v1.y += bv.y + y1.y;
                }
                if (STATS) {
                    cs0[nb] += v0.x + v1.x;
                    cs1[nb] += v0.y + v1.y;
                    cq0[nb] += v0.x*v0.x + v1.x*v1.x;
                    cq1[nb] += v0.y*v0.y + v1.y*v1.y;
                }
                wr_planes(Chi, Clo, (size_t)m0*OUTW + col,     v0);
                wr_planes(Chi, Clo, (size_t)(m0+8)*OUTW + col, v1);
            } else {
                int jc = bn + 32*wc2 + 8*nb + 2*t;
                float2 bg = *(const float2*)(bias + jc);
                float2 bs = *(const float2*)(bias + 256 + jc);
                float g0 = accg[rb][nb][0] + bg.x, s0 = accs[rb][nb][0] + bs.x;
                float g1 = accg[rb][nb][1] + bg.y, s1 = accs[rb][nb][1] + bs.y;
                float g2 = accg[rb][nb][2] + bg.x, s2 = accs[rb][nb][2] + bs.x;
                float g3 = accg[rb][nb][3] + bg.y, s3 = accs[rb][nb][3] + bs.y;
                float2 v0, v1;
                v0.x = g0 * (1.f/(1.f + expf(-s0)));
                v0.y = g1 * (1.f/(1.f + expf(-s1)));
                v1.x = g2 * (1.f/(1.f + expf(-s2)));
                v1.y = g3 * (1.f/(1.f + expf(-s3)));
                wr_planes(Chi, Clo, (size_t)m0*OUTW + jc,     v0);
                wr_planes(Chi, Clo, (size_t)(m0+8)*OUTW + jc, v1);
            }
        }
    }

    if (STATS && !DUAL) {
        #pragma unroll
        for (int nb = 0; nb < 8; nb++) {
            #pragma unroll
            for (int m = 4; m <= 16; m <<= 1) {
                cs0[nb] += __shfl_xor_sync(0xffffffffu, cs0[nb], m);
                cs1[nb] += __shfl_xor_sync(0xffffffffu, cs1[nb], m);
                cq0[nb] += __shfl_xor_sync(0xffffffffu, cq0[nb], m);
                cq1[nb] += __shfl_xor_sync(0xffffffffu, cq1[nb], m);
            }
        }
        __syncthreads();
        float* spart = (float*)sm;
        if (lane < 4) {
            #pragma unroll
            for (int nb = 0; nb < 8; nb++) {
                int col = 64*wc2 + 8*nb + 2*lane;
                spart[wr*128 + col]           = cs0[nb];
                spart[wr*128 + col + 1]       = cs1[nb];
                spart[512 + wr*128 + col]     = cq0[nb];
                spart[512 + wr*128 + col + 1] = cq1[nb];
            }
        }
        __syncthreads();
        if (tid < 128) {
            float s  = spart[tid] + spart[128+tid] + spart[256+tid] + spart[384+tid];
            float s2 = spart[512+tid] + spart[640+tid] + spart[768+tid] + spart[896+tid];
            g_bnpart[blockIdx.y*(2*DE) + tid]      = s;
            g_bnpart[blockIdx.y*(2*DE) + DE + tid] = s2;
        }
    }
}

// ---------------- LRU scan (hi/lo planes in, in-place state planes out) ----------------
__device__ __forceinline__ float2 cstep(float2 lam, float2 s, float2 u) {
    float2 t;
    t.x = fmaf(lam.x, s.x, fmaf(-lam.y, s.y, u.x));
    t.y = fmaf(lam.x, s.y, fmaf( lam.y, s.x, u.y));
    return t;
}
__device__ __forceinline__ float2 ldp(const uint32_t* ph, const uint32_t* pl, size_t off) {
    uint32_t rh = ph[off], rl = pl[off];
    __nv_bfloat162 h2 = *(__nv_bfloat162*)&rh;
    __nv_bfloat162 l2 = *(__nv_bfloat162*)&rl;
    return make_float2(__bfloat162float(h2.x) + __bfloat162float(l2.x),
                       __bfloat162float(h2.y) + __bfloat162float(l2.y));
}
__global__ void scanA_kernel(int blk) {
    int g  = blockIdx.x*256 + threadIdx.x;
    int h  = g & 255;
    int bc = g >> 8;
    int b  = bc >> 4;
    int c  = bc & 15;
    float2 lam = g_lam[blk*HH + h];
    float2 s = make_float2(0.f, 0.f);
    size_t base = (size_t)(b*TT + c*CLEN)*256 + h;
    const uint32_t* ph = (const uint32_t*)g_buh;
    const uint32_t* pl = (const uint32_t*)g_bul;
    #pragma unroll 8
    for (int i = 0; i < CLEN; i++)
        s = cstep(lam, s, ldp(ph, pl, base + (size_t)i*256));
    g_carry[bc*HH + h] = s;
}
__global__ void scanB_kernel(int blk) {
    int b = blockIdx.x;
    int h = threadIdx.x;
    float2 lam = g_lam[blk*HH + h];
    float2 lp = lam;
    #pragma unroll
    for (int i = 0; i < 8; i++) {
        float2 t;
        t.x = lp.x*lp.x - lp.y*lp.y;
        t.y = 2.f*lp.x*lp.y;
        lp = t;
    }
    float2 s = make_float2(0.f, 0.f);
    for (int c = 0; c < NCH; c++) {
        g_inc[(b*NCH + c)*HH + h] = s;
        float2 cr = g_carry[(b*NCH + c)*HH + h];
        s = cstep(lp, s, cr);
    }
}
__global__ void scanC_kernel(int blk) {
    int g  = blockIdx.x*256 + threadIdx.x;
    int h  = g & 255;
    int bc = g >> 8;
    int b  = bc >> 4;
    int c  = bc & 15;
    float2 lam = g_lam[blk*HH + h];
    float2 s = g_inc[bc*HH + h];
    size_t base = (size_t)(b*TT + c*CLEN)*256 + h;
    uint32_t* ph = (uint32_t*)g_buh;
    uint32_t* pl = (uint32_t*)g_bul;
    #pragma unroll 8
    for (int i = 0; i < CLEN; i++) {
        size_t off = base + (size_t)i*256;
        s = cstep(lam, s, ldp(ph, pl, off));
        __nv_bfloat162 h2, l2;
        h2.x = __float2bfloat16(s.x);
        h2.y = __float2bfloat16(s.y);
        l2.x = __float2bfloat16(s.x - __bfloat162float(h2.x));
        l2.y = __float2bfloat16(s.y - __bfloat162float(h2.y));
        ph[off] = *(uint32_t*)&h2;
        pl[off] = *(uint32_t*)&l2;
    }
}

// ---------------- final: mean-pool + head ----------------
__global__ void final_kernel(const float* __restrict__ Wout,
                             const float* __restrict__ bout,
                             float* __restrict__ out) {
    __shared__ float pooled[DE];
    int b = blockIdx.x;
    int f = threadIdx.x;
    float s = 0.f;
    size_t base = (size_t)b*TT*DE + f;
    #pragma unroll 4
    for (int t = 0; t < TT; t++) {
        size_t off = base + (size_t)t*DE;
        s += __bfloat162float(g_hh[off]) + __bfloat162float(g_hl[off]);
    }
    pooled[f] = s * (1.f/TT);
    __syncthreads();
    if (f < OD) {
        float acc = bout[f];
        #pragma unroll 4
        for (int d = 0; d < DE; d++) acc = fmaf(pooled[d], Wout[d*OD + f], acc);
        out[b*OD + f] = acc;
    }
}

// ---------------- launch ----------------
extern "C" void kernel_launch(void* const* d_in, const int* in_sizes, int n_in,
                              void* d_out, int out_size) {
    const float* x         = (const float*)d_in[0];
    const float* nu_log    = (const float*)d_in[1];
    const float* theta_log = (const float*)d_in[2];
    const float* B_re      = (const float*)d_in[3];
    const float* B_im      = (const float*)d_in[4];
    const float* C_re      = (const float*)d_in[5];
    const float* C_im      = (const float*)d_in[6];
    const float* D_lru     = (const float*)d_in[7];
    const float* W1        = (const float*)d_in[8];
    const float* b1        = (const float*)d_in[9];
    const float* W2        = (const float*)d_in[10];
    const float* b2        = (const float*)d_in[11];
    const float* bn_scale  = (const float*)d_in[12];
    const float* bn_bias   = (const float*)d_in[13];
    const float* W_enc     = (const float*)d_in[14];
    const float* b_enc     = (const float*)d_in[15];
    const float* W_out     = (const float*)d_in[16];
    const float* b_out     = (const float*)d_in[17];
    float* out = (float*)d_out;

    __nv_bfloat16 *xh,*xl,*yeh,*yel,*hh,*hl,*buh,*bul,*lrh,*lrl,*glh,*gll;
    __nv_bfloat16 *wbbh,*wbbl,*wch,*wcl,*w1h,*w1l,*w2h,*w2l,*weh,*wel;
    float *bubias;
    cudaGetSymbolAddress((void**)&xh,  g_xh);
    cudaGetSymbolAddress((void**)&xl,  g_xl);
    cudaGetSymbolAddress((void**)&yeh, g_yeh);
    cudaGetSymbolAddress((void**)&yel, g_yel);
    cudaGetSymbolAddress((void**)&hh,  g_hh);
    cudaGetSymbolAddress((void**)&hl,  g_hl);
    cudaGetSymbolAddress((void**)&buh, g_buh);
    cudaGetSymbolAddress((void**)&bul, g_bul);
    cudaGetSymbolAddress((void**)&lrh, g_lrh);
    cudaGetSymbolAddress((void**)&lrl, g_lrl);
    cudaGetSymbolAddress((void**)&glh, g_glh);
    cudaGetSymbolAddress((void**)&gll, g_gll);
    cudaGetSymbolAddress((void**)&wbbh, g_WBbh);
    cudaGetSymbolAddress((void**)&wbbl, g_WBbl);
    cudaGetSymbolAddress((void**)&wch, g_WCh);
    cudaGetSymbolAddress((void**)&wcl, g_WCl);
    cudaGetSymbolAddress((void**)&w1h, g_W1h);
    cudaGetSymbolAddress((void**)&w1l, g_W1l);
    cudaGetSymbolAddress((void**)&w2h, g_W2h);
    cudaGetSymbolAddress((void**)&w2l, g_W2l);
    cudaGetSymbolAddress((void**)&weh, g_WEh);
    cudaGetSymbolAddress((void**)&wel, g_WEl);
    cudaGetSymbolAddress((void**)&bubias, g_bubias);

    cudaFuncSetAttribute(gemm_mma<64, 128, 0, 0, 1>,  cudaFuncAttributeMaxDynamicSharedMemorySize, SMEM_BYTES);
    cudaFuncSetAttribute(gemm_mma<128, 512, 0, 0, 0>, cudaFuncAttributeMaxDynamicSharedMemorySize, SMEM_BYTES);
    cudaFuncSetAttribute(gemm_mma<512, 128, 1, 0, 0>, cudaFuncAttributeMaxDynamicSharedMemorySize, SMEM_BYTES);
    cudaFuncSetAttribute(gemm_mma<128, 256, 0, 1, 0>, cudaFuncAttributeMaxDynamicSharedMemorySize, SMEM_BYTES);
    cudaFuncSetAttribute(gemm_mma<256, 128, 2, 0, 1>, cudaFuncAttributeMaxDynamicSharedMemorySize, SMEM_BYTES);

    prep_lam_kernel<<<NBLKS, HH>>>(nu_log, theta_log);
    prep_WE_kernel<<<(DE*TSD + 255)/256, 256>>>(W_enc);
    split_x_kernel<<<(NR*TSD + 255)/256, 256>>>(x);
    prep_WBf_kernel<<<(NBLKS*512*DE + 255)/256, 256>>>(B_re, B_im);
    prep_WC_kernel<<<(NBLKS*DE*512 + 255)/256, 256>>>(C_re, C_im);
    prep_W1_kernel<<<(NBLKS*512*DE + 255)/256, 256>>>(W1);
    prep_W2_kernel<<<(NBLKS*DE*256 + 255)/256, 256>>>(W2);

    // encoder: yenc = x @ W_enc + b_enc  (+ BN partials for block 0)
    gemm_mma<64, 128, 0, 0, 1><<<dim3(1, NR/128), 256, SMEM_BYTES>>>(
        xh, xl, weh, wel, yeh, yel, b_enc, nullptr, nullptr, nullptr);

    const __nv_bfloat16* hph = yeh;
    const __nv_bfloat16* hpl = yel;
    for (int blk = 0; blk < NBLKS; blk++) {
        bn_stats2_kernel<<<1, 128>>>(bn_scale + blk*DE, bn_bias + blk*DE);
        fold_WB_kernel<<<256, 256>>>(blk);
        fold_bias_kernel<<<2, 256>>>(blk);

        // Bu = h @ (diag(bna)*WB) + (bnb.WB)
        gemm_mma<128, 512, 0, 0, 0><<<dim3(4, NR/128), 256, SMEM_BYTES>>>(
            hph, hpl, wbbh, wbbl, buh, bul, bubias, nullptr, nullptr, nullptr);

        scanA_kernel<<<NR/256, 256>>>(blk);
        scanB_kernel<<<BB, HH>>>(blk);
        scanC_kernel<<<NR/256, 256>>>(blk);

        // lru = Re(state @ C) + BN(h) * D
        gemm_mma<512, 128, 1, 0, 0><<<dim3(1, NR/128), 256, SMEM_BYTES>>>(
            buh, bul, wch + (size_t)blk*128*512, wcl + (size_t)blk*128*512,
            lrh, lrl, nullptr, hph, hpl, D_lru + blk*DE);

        // glu = GLU(lru @ W1 + b1)
        gemm_mma<128, 256, 0, 1, 0><<<dim3(4, NR/128), 256, SMEM_BYTES>>>(
            lrh, lrl, w1h + (size_t)blk*512*128, w1l + (size_t)blk*512*128,
            glh, gll, b1 + (size_t)blk*LDF, nullptr, nullptr, nullptr);

        // h = glu @ W2 + b2 + yenc  (+ BN partials for next block)
        gemm_mma<256, 128, 2, 0, 1><<<dim3(1, NR/128), 256, SMEM_BYTES>>>(
            glh, gll, w2h + (size_t)blk*128*256, w2l + (size_t)blk*128*256,
            hh, hl, b2 + blk*DE, yeh, yel, nullptr);

        hph = hh;
        hpl = hl;
    }

    final_kernel<<<BB, DE>>>(W_out, b_out, out);
}

// round 8
// speedup vs baseline: 1.0575x; 1.0575x over previous
#include <cuda_runtime.h>
#include <cuda_bf16.h>
#include <math.h>
#include <stdint.h>

// ---------------- problem constants ----------------
#define BB   16
#define TT   4096
#define NR   (BB*TT)
#define TSD  64
#define DE   128
#define HH   256
#define LDF  512
#define LDH  256
#define OD   10
#define NBLKS 6
#define EPSV 1e-5f
#define NCH  16
#define CLEN 256

// ---------------- scratch ----------------
static __device__ __align__(256) float g_yenc[(size_t)NR*DE];
static __device__ __align__(256) float g_h   [(size_t)NR*DE];
static __device__ __align__(256) float g_lru [(size_t)NR*DE];
static __device__ __align__(256) float g_glu [(size_t)NR*LDH];
static __device__ __align__(256) __nv_bfloat16 g_buh[(size_t)NR*512];  // Bu -> state (in place), hi plane
static __device__ __align__(256) __nv_bfloat16 g_bul[(size_t)NR*512];  // lo plane
static __device__ float2 g_lam [NBLKS*HH];
static __device__ float  g_gamma[NBLKS*HH];
static __device__ float  g_bnpart[512*2*DE];
static __device__ float  g_bna[DE];
static __device__ float  g_bnb[DE];
static __device__ float2 g_carry[BB*NCH*HH];
static __device__ float2 g_inc  [BB*NCH*HH];

// split bf16 weights [blk][n][k]
static __device__ __align__(256) __nv_bfloat16 g_WBh[(size_t)NBLKS*512*128];
static __device__ __align__(256) __nv_bfloat16 g_WBl[(size_t)NBLKS*512*128];
static __device__ __align__(256) __nv_bfloat16 g_WCh[(size_t)NBLKS*128*512];
static __device__ __align__(256) __nv_bfloat16 g_WCl[(size_t)NBLKS*128*512];
static __device__ __align__(256) __nv_bfloat16 g_W1h[(size_t)NBLKS*512*128];
static __device__ __align__(256) __nv_bfloat16 g_W1l[(size_t)NBLKS*512*128];
static __device__ __align__(256) __nv_bfloat16 g_W2h[(size_t)NBLKS*128*256];
static __device__ __align__(256) __nv_bfloat16 g_W2l[(size_t)NBLKS*128*256];
static __device__ __align__(256) __nv_bfloat16 g_WEh[128*64];
static __device__ __align__(256) __nv_bfloat16 g_WEl[128*64];

// ---------------- helpers ----------------
__device__ __forceinline__ uint32_t smem_u32(const void* p) {
    uint32_t a;
    asm("{ .reg .u64 t; cvta.to.shared.u64 t, %1; cvt.u32.u64 %0, t; }" : "=r"(a) : "l"(p));
    return a;
}
__device__ __forceinline__ void cp16(uint32_t dst, const void* src) {
    asm volatile("cp.async.cg.shared.global [%0], [%1], 16;" :: "r"(dst), "l"(src));
}
#define CP_COMMIT() asm volatile("cp.async.commit_group;" ::: "memory")
#define CP_WAIT0()  asm volatile("cp.async.wait_group 0;" ::: "memory")

#define MMA_BF16(d, a, b0, b1) \
    asm volatile("mma.sync.aligned.m16n8k16.row.col.f32.bf16.bf16.f32 " \
        "{%0,%1,%2,%3}, {%4,%5,%6,%7}, {%8,%9}, {%0,%1,%2,%3};" \
        : "+f"((d)[0]), "+f"((d)[1]), "+f"((d)[2]), "+f"((d)[3]) \
        : "r"((a)[0]), "r"((a)[1]), "r"((a)[2]), "r"((a)[3]), "r"(b0), "r"(b1))

#define LDSM4(r, addr) \
    asm volatile("ldmatrix.sync.aligned.m8n8.x4.shared.b16 {%0,%1,%2,%3}, [%4];" \
        : "=r"((r)[0]), "=r"((r)[1]), "=r"((r)[2]), "=r"((r)[3]) : "r"(addr))

__device__ __forceinline__ void split_store(float v, __nv_bfloat16* hi, __nv_bfloat16* lo, size_t i) {
    __nv_bfloat16 h = __float2bfloat16(v);
    hi[i] = h;
    lo[i] = __float2bfloat16(v - __bfloat162float(h));
}

// ---------------- prep ----------------
__global__ void prep_lam_kernel(const float* __restrict__ nu_log,
                                const float* __restrict__ theta_log) {
    int blk = blockIdx.x;
    int h   = threadIdx.x;
    float nu = nu_log[blk*HH + h];
    float th = theta_log[blk*HH + h];
    float r  = expf(-expf(nu));
    float ang = expf(th);
    float sn, cs;
    sincosf(ang, &sn, &cs);
    float2 lam; lam.x = r*cs; lam.y = r*sn;
    g_lam[blk*HH + h]   = lam;
    g_gamma[blk*HH + h] = sqrtf(fmaxf(1.f - r*r, 1e-8f));
}
__global__ void prep_WB_kernel(const float* __restrict__ Bre, const float* __restrict__ Bim) {
    int idx = blockIdx.x*256 + threadIdx.x;
    if (idx >= NBLKS*512*DE) return;
    int k = idx & 127;
    int n = (idx >> 7) & 511;
    int blk = idx >> 16;
    int h = n >> 1;
    float g = g_gamma[blk*HH + h];
    float v = ((n & 1) ? Bim : Bre)[((size_t)blk*HH + h)*DE + k] * g;
    split_store(v, g_WBh, g_WBl, idx);
}
__global__ void prep_WC_kernel(const float* __restrict__ Cre, const float* __restrict__ Cim) {
    int idx = blockIdx.x*256 + threadIdx.x;
    if (idx >= NBLKS*DE*512) return;
    int k = idx & 511;
    int n = (idx >> 9) & 127;
    int blk = idx >> 16;
    int h = k >> 1;
    float v = (k & 1) ? -Cim[((size_t)blk*DE + n)*HH + h] : Cre[((size_t)blk*DE + n)*HH + h];
    split_store(v, g_WCh, g_WCl, idx);
}
__global__ void prep_W1_kernel(const float* __restrict__ W1) {
    int idx = blockIdx.x*256 + threadIdx.x;
    if (idx >= NBLKS*512*DE) return;
    int k = idx & 127;
    int n = (idx >> 7) & 511;
    int blk = idx >> 16;
    split_store(W1[((size_t)blk*DE + k)*LDF + n], g_W1h, g_W1l, idx);
}
__global__ void prep_W2_kernel(const float* __restrict__ W2) {
    int idx = blockIdx.x*256 + threadIdx.x;
    if (idx >= NBLKS*DE*256) return;
    int k = idx & 255;
    int n = (idx >> 8) & 127;
    int blk = idx >> 15;
    split_store(W2[((size_t)blk*LDH + k)*DE + n], g_W2h, g_W2l, idx);
}
__global__ void prep_WE_kernel(const float* __restrict__ We) {
    int idx = blockIdx.x*256 + threadIdx.x;
    if (idx >= DE*TSD) return;
    int k = idx & 63;
    int n = idx >> 6;
    split_store(We[(size_t)k*DE + n], g_WEh, g_WEl, idx);
}

// ---------------- batchnorm stage-2 ----------------
__global__ void bn_stats2_kernel(const float* __restrict__ scale,
                                 const float* __restrict__ bias) {
    int f = threadIdx.x;
    float s = 0.f, s2 = 0.f;
    for (int i = 0; i < 512; i++) {
        s  += g_bnpart[i*(2*DE) + f];
        s2 += g_bnpart[i*(2*DE) + DE + f];
    }
    float mean = s * (1.f/NR);
    float var  = s2 * (1.f/NR) - mean*mean;
    float a = scale[f] * rsqrtf(var + EPSV);
    g_bna[f] = a;
    g_bnb[f] = fmaf(-mean, a, bias[f]);
}

// ---------------- ldmatrix bf16x3 GEMM, K-chunk 64, pitch 72, double-buffered ----------------
// APLANES=0: A fp32, staged via regs + split-convert (MODE_A applies BN affine).
// APLANES=1: A pre-split planes, staged via cp.async (3-term exact).
// EPI: 0 +bias?; 1 + (bna*aux+bnb)*dvec; 2 +bias + aux residual. DUAL: fused GLU.
// OUTPL: write hi/lo plane output. STATS: per-CTA BN partials (grid.x==1).
#define PITCH 72
#define UNITE (128*PITCH)
#define STAGEE (4*UNITE)
#define SMEM_BYTES (2*STAGEE*2)   // 147456

template<int KDIM, int OUTW, int MODE_A, int EPI, int DUAL, int APLANES, int OUTPL, int STATS>
__global__ void __launch_bounds__(256) gemm_mma(
    const float* __restrict__ Af,
    const __nv_bfloat16* __restrict__ Aph, const __nv_bfloat16* __restrict__ Apl,
    const __nv_bfloat16* __restrict__ Bhi, const __nv_bfloat16* __restrict__ Blo,
    float* __restrict__ Cf, __nv_bfloat16* __restrict__ Cph, __nv_bfloat16* __restrict__ Cpl,
    const float* __restrict__ bias,
    const float* __restrict__ auxf,
    const float* __restrict__ dvec)
{
    constexpr int O_AH = 0, O_AL = UNITE, O_BH = 2*UNITE, O_BL = 3*UNITE;
    constexpr int NCHK = KDIM / 64;

    extern __shared__ __nv_bfloat16 sm[];
    const uint32_t smb = smem_u32(sm);
    const int tid  = threadIdx.x;
    const int wid  = tid >> 5;
    const int lane = tid & 31;
    const int wr   = wid & 3;
    const int wc2  = wid >> 2;
    const int g    = lane >> 2;
    const int t    = lane & 3;
    const int bm   = blockIdx.y << 7;
    const int bn   = DUAL ? (blockIdx.x << 6) : (blockIdx.x << 7);

    // ldmatrix per-lane offsets (bf16-element units)
    const int aLaneE = (lane & 15)*PITCH + (lane >> 4)*8;
    const int bLaneE = (lane & 7)*PITCH + ((lane >> 4) & 1)*(8*PITCH) + ((lane >> 3) & 1)*8;

    float accg[2][DUAL ? 4 : 8][4];
    float accs[DUAL ? 2 : 1][DUAL ? 4 : 1][4];
    #pragma unroll
    for (int rb = 0; rb < 2; rb++)
        #pragma unroll
        for (int nb = 0; nb < (DUAL ? 4 : 8); nb++)
            #pragma unroll
            for (int j = 0; j < 4; j++) {
                accg[rb][nb][j] = 0.f;
                if (DUAL) accs[rb][nb][j] = 0.f;
            }

    float4 areg[8];
    auto loadA = [&](int cc) {
        #pragma unroll
        for (int i = 0; i < 8; i++) {
            int idx = tid + 256*i;
            int row = idx >> 4;
            int col4 = (idx & 15) << 2;
            areg[i] = *(const float4*)(Af + (size_t)(bm + row)*KDIM + cc*64 + col4);
        }
    };
    auto storeA = [&](int cc, int so) {
        #pragma unroll
        for (int i = 0; i < 8; i++) {
            int idx = tid + 256*i;
            int row = idx >> 4;
            int col4 = (idx & 15) << 2;
            float4 v = areg[i];
            if (MODE_A) {
                float4 aa = *(const float4*)(g_bna + cc*64 + col4);
                float4 ab = *(const float4*)(g_bnb + cc*64 + col4);
                v.x = fmaf(aa.x, v.x, ab.x);
                v.y = fmaf(aa.y, v.y, ab.y);
                v.z = fmaf(aa.z, v.z, ab.z);
                v.w = fmaf(aa.w, v.w, ab.w);
            }
            __nv_bfloat16 h0 = __float2bfloat16(v.x), h1 = __float2bfloat16(v.y);
            __nv_bfloat16 h2 = __float2bfloat16(v.z), h3 = __float2bfloat16(v.w);
            __nv_bfloat16 l0 = __float2bfloat16(v.x - __bfloat162float(h0));
            __nv_bfloat16 l1 = __float2bfloat16(v.y - __bfloat162float(h1));
            __nv_bfloat16 l2 = __float2bfloat16(v.z - __bfloat162float(h2));
            __nv_bfloat16 l3 = __float2bfloat16(v.w - __bfloat162float(h3));
            uint32_t hu0 = ((uint32_t)__bfloat16_as_ushort(h1) << 16) | __bfloat16_as_ushort(h0);
            uint32_t hu1 = ((uint32_t)__bfloat16_as_ushort(h3) << 16) | __bfloat16_as_ushort(h2);
            uint32_t lu0 = ((uint32_t)__bfloat16_as_ushort(l1) << 16) | __bfloat16_as_ushort(l0);
            uint32_t lu1 = ((uint32_t)__bfloat16_as_ushort(l3) << 16) | __bfloat16_as_ushort(l2);
            int off = row*PITCH + col4;
            *(uint2*)(sm + so + O_AH + off) = make_uint2(hu0, hu1);
            *(uint2*)(sm + so + O_AL + off) = make_uint2(lu0, lu1);
        }
    };
    auto cpA = [&](int cc, int so) {
        #pragma unroll
        for (int i = 0; i < 8; i++) {
            int idx = tid + 256*i;
            int pl  = idx >> 10;
            int rem = idx & 1023;
            int r   = rem >> 3;
            int q   = rem & 7;
            const __nv_bfloat16* src = pl ? Apl : Aph;
            cp16(smb + (uint32_t)((so + (pl ? O_AL : O_AH) + r*PITCH + q*8)*2),
                 src + (size_t)(bm + r)*KDIM + cc*64 + q*8);
        }
    };
    auto cpB = [&](int cc, int so) {
        #pragma unroll
        for (int i = 0; i < 8; i++) {
            int idx = tid + 256*i;
            int pl  = idx >> 10;
            int rem = idx & 1023;
            int r   = rem >> 3;
            int q   = rem & 7;
            int rowg = DUAL ? (r < 64 ? bn + r : bn + 256 + (r - 64)) : (bn + r);
            const __nv_bfloat16* src = pl ? Blo : Bhi;
            cp16(smb + (uint32_t)((so + (pl ? O_BL : O_BH) + r*PITCH + q*8)*2),
                 src + (size_t)rowg*KDIM + cc*64 + q*8);
        }
    };

    // prologue
    if (APLANES) cpA(0, 0); else loadA(0);
    cpB(0, 0);
    CP_COMMIT();
    if (!APLANES) {
        storeA(0, 0);
        if (NCHK > 1) loadA(1);
    }

    #pragma unroll 1
    for (int c = 0; c < NCHK; c++) {
        const int so = (c & 1)*STAGEE;
        CP_WAIT0();
        __syncthreads();
        if (c + 1 < NCHK) {
            const int nso = ((c+1) & 1)*STAGEE;
            cpB(c+1, nso);
            if (APLANES) cpA(c+1, nso);
            CP_COMMIT();
            if (!APLANES) {
                storeA(c+1, nso);
                if (c + 2 < NCHK) loadA(c+2);
            }
        }

        #pragma unroll
        for (int kk = 0; kk < 4; kk++) {
            const int kkE = kk*16;
            uint32_t ah[2][4], al[2][4];
            #pragma unroll
            for (int rb = 0; rb < 2; rb++) {
                int abase = so + (32*wr + 16*rb)*PITCH + kkE + aLaneE;
                LDSM4(ah[rb], smb + (uint32_t)((O_AH + abase)*2));
                LDSM4(al[rb], smb + (uint32_t)((O_AL + abase)*2));
            }
            if (!DUAL) {
                #pragma unroll
                for (int nb2 = 0; nb2 < 4; nb2++) {
                    uint32_t bh[4], bl[4];
                    int bbase = so + (64*wc2 + 16*nb2)*PITCH + kkE + bLaneE;
                    LDSM4(bh, smb + (uint32_t)((O_BH + bbase)*2));
                    LDSM4(bl, smb + (uint32_t)((O_BL + bbase)*2));
                    #pragma unroll
                    for (int rb = 0; rb < 2; rb++)
                        #pragma unroll
                        for (int j = 0; j < 2; j++) {
                            float* d = accg[rb][2*nb2 + j];
                            MMA_BF16(d, ah[rb], bh[2*j], bh[2*j+1]);
                            if (!APLANES || 1) { /* always 3-term */ }
                            MMA_BF16(d, al[rb], bh[2*j], bh[2*j+1]);
                            MMA_BF16(d, ah[rb], bl[2*j], bl[2*j+1]);
                        }
                }
            } else {
                #pragma unroll
                for (int nb2 = 0; nb2 < 2; nb2++) {
                    uint32_t bh[4], bl[4], dh[4], el[4];
                    int bbase = so + (32*wc2 + 16*nb2)*PITCH + kkE + bLaneE;
                    int sbase = bbase + 64*PITCH;
                    LDSM4(bh, smb + (uint32_t)((O_BH + bbase)*2));
                    LDSM4(bl, smb + (uint32_t)((O_BL + bbase)*2));
                    LDSM4(dh, smb + (uint32_t)((O_BH + sbase)*2));
                    LDSM4(el, smb + (uint32_t)((O_BL + sbase)*2));
                    #pragma unroll
                    for (int rb = 0; rb < 2; rb++)
                        #pragma unroll
                        for (int j = 0; j < 2; j++) {
                            float* dg = accg[rb][2*nb2 + j];
                            float* ds = accs[rb][2*nb2 + j];
                            MMA_BF16(dg, ah[rb], bh[2*j], bh[2*j+1]);
                            MMA_BF16(dg, al[rb], bh[2*j], bh[2*j+1]);
                            MMA_BF16(dg, ah[rb], bl[2*j], bl[2*j+1]);
                            MMA_BF16(ds, ah[rb], dh[2*j], dh[2*j+1]);
                            MMA_BF16(ds, al[rb], dh[2*j], dh[2*j+1]);
                            MMA_BF16(ds, ah[rb], el[2*j], el[2*j+1]);
                        }
                }
            }
        }
    }

    // ---- epilogue ----
    float cs0[STATS ? 8 : 1], cs1[STATS ? 8 : 1], cq0[STATS ? 8 : 1], cq1[STATS ? 8 : 1];
    if (STATS) {
        #pragma unroll
        for (int nb = 0; nb < 8; nb++) { cs0[nb]=0.f; cs1[nb]=0.f; cq0[nb]=0.f; cq1[nb]=0.f; }
    }
    #pragma unroll
    for (int rb = 0; rb < 2; rb++) {
        int m0 = bm + 32*wr + 16*rb + g;
        #pragma unroll
        for (int nb = 0; nb < (DUAL ? 4 : 8); nb++) {
            if (!DUAL) {
                int col = bn + 64*wc2 + 8*nb + 2*t;
                float2 v0 = make_float2(accg[rb][nb][0], accg[rb][nb][1]);
                float2 v1 = make_float2(accg[rb][nb][2], accg[rb][nb][3]);
                if (EPI == 0) {
                    if (bias != nullptr) {
                        float2 bv = *(const float2*)(bias + col);
                        v0.x += bv.x; v0.y += bv.y; v1.x += bv.x; v1.y += bv.y;
                    }
                } else if (EPI == 1) {
                    float2 aa = *(const float2*)(g_bna + col);
                    float2 ab = *(const float2*)(g_bnb + col);
                    float2 dv = *(const float2*)(dvec + col);
                    float2 h0 = *(const float2*)(auxf + (size_t)m0*DE + col);
                    float2 h1 = *(const float2*)(auxf + (size_t)(m0+8)*DE + col);
                    v0.x += fmaf(aa.x, h0.x, ab.x)*dv.x;
                    v0.y += fmaf(aa.y, h0.y, ab.y)*dv.y;
                    v1.x += fmaf(aa.x, h1.x, ab.x)*dv.x;
                    v1.y += fmaf(aa.y, h1.y, ab.y)*dv.y;
                } else if (EPI == 2) {
                    float2 bv = *(const float2*)(bias + col);
                    float2 y0 = *(const float2*)(auxf + (size_t)m0*OUTW + col);
                    float2 y1 = *(const float2*)(auxf + (size_t)(m0+8)*OUTW + col);
                    v0.x += bv.x + y0.x; v0.y += bv.y + y0.y;
                    v1.x += bv.x + y1.x; v1.y += bv.y + y1.y;
                }
                if (STATS) {
                    cs0[nb] += v0.x + v1.x;
                    cs1[nb] += v0.y + v1.y;
                    cq0[nb] += v0.x*v0.x + v1.x*v1.x;
                    cq1[nb] += v0.y*v0.y + v1.y*v1.y;
                }
                if (OUTPL) {
                    __nv_bfloat162 h2, l2;
                    h2.x = __float2bfloat16(v0.x);
                    h2.y = __float2bfloat16(v0.y);
                    l2.x = __float2bfloat16(v0.x - __bfloat162float(h2.x));
                    l2.y = __float2bfloat16(v0.y - __bfloat162float(h2.y));
                    *(__nv_bfloat162*)(Cph + (size_t)m0*OUTW + col) = h2;
                    *(__nv_bfloat162*)(Cpl + (size_t)m0*OUTW + col) = l2;
                    h2.x = __float2bfloat16(v1.x);
                    h2.y = __float2bfloat16(v1.y);
                    l2.x = __float2bfloat16(v1.x - __bfloat162float(h2.x));
                    l2.y = __float2bfloat16(v1.y - __bfloat162float(h2.y));
                    *(__nv_bfloat162*)(Cph + (size_t)(m0+8)*OUTW + col) = h2;
                    *(__nv_bfloat162*)(Cpl + (size_t)(m0+8)*OUTW + col) = l2;
                } else {
                    *(float2*)(Cf + (size_t)m0*OUTW + col)     = v0;
                    *(float2*)(Cf + (size_t)(m0+8)*OUTW + col) = v1;
                }
            } else {
                int jc = bn + 32*wc2 + 8*nb + 2*t;
                float2 bg = *(const float2*)(bias + jc);
                float2 bs = *(const float2*)(bias + 256 + jc);
                float g0 = accg[rb][nb][0] + bg.x, s0 = accs[rb][nb][0] + bs.x;
                float g1 = accg[rb][nb][1] + bg.y, s1 = accs[rb][nb][1] + bs.y;
                float g2 = accg[rb][nb][2] + bg.x, s2 = accs[rb][nb][2] + bs.x;
                float g3 = accg[rb][nb][3] + bg.y, s3 = accs[rb][nb][3] + bs.y;
                float2 v0, v1;
                v0.x = g0 * (1.f/(1.f + expf(-s0)));
                v0.y = g1 * (1.f/(1.f + expf(-s1)));
                v1.x = g2 * (1.f/(1.f + expf(-s2)));
                v1.y = g3 * (1.f/(1.f + expf(-s3)));
                *(float2*)(Cf + (size_t)m0*OUTW + jc)     = v0;
                *(float2*)(Cf + (size_t)(m0+8)*OUTW + jc) = v1;
            }
        }
    }

    if (STATS && !DUAL) {
        #pragma unroll
        for (int nb = 0; nb < 8; nb++) {
            #pragma unroll
            for (int m = 4; m <= 16; m <<= 1) {
                cs0[nb] += __shfl_xor_sync(0xffffffffu, cs0[nb], m);
                cs1[nb] += __shfl_xor_sync(0xffffffffu, cs1[nb], m);
                cq0[nb] += __shfl_xor_sync(0xffffffffu, cq0[nb], m);
                cq1[nb] += __shfl_xor_sync(0xffffffffu, cq1[nb], m);
            }
        }
        __syncthreads();
        float* spart = (float*)sm;
        if (lane < 4) {
            #pragma unroll
            for (int nb = 0; nb < 8; nb++) {
                int col = 64*wc2 + 8*nb + 2*lane;
                spart[wr*128 + col]           = cs0[nb];
                spart[wr*128 + col + 1]       = cs1[nb];
                spart[512 + wr*128 + col]     = cq0[nb];
                spart[512 + wr*128 + col + 1] = cq1[nb];
            }
        }
        __syncthreads();
        if (tid < 128) {
            float s  = spart[tid] + spart[128+tid] + spart[256+tid] + spart[384+tid];
            float s2 = spart[512+tid] + spart[640+tid] + spart[768+tid] + spart[896+tid];
            g_bnpart[blockIdx.y*(2*DE) + tid]      = s;
            g_bnpart[blockIdx.y*(2*DE) + DE + tid] = s2;
        }
    }
}

// ---------------- LRU scan (plane Bu in, in-place plane state out) ----------------
__device__ __forceinline__ float2 cstep(float2 lam, float2 s, float2 u) {
    float2 t;
    t.x = fmaf(lam.x, s.x, fmaf(-lam.y, s.y, u.x));
    t.y = fmaf(lam.x, s.y, fmaf( lam.y, s.x, u.y));
    return t;
}
__device__ __forceinline__ float2 ldp(const uint32_t* ph, const uint32_t* pl, size_t off) {
    uint32_t rh = ph[off], rl = pl[off];
    __nv_bfloat162 h2 = *(__nv_bfloat162*)&rh;
    __nv_bfloat162 l2 = *(__nv_bfloat162*)&rl;
    return make_float2(__bfloat162float(h2.x) + __bfloat162float(l2.x),
                       __bfloat162float(h2.y) + __bfloat162float(l2.y));
}
__global__ void scanA_kernel(int blk) {
    int g  = blockIdx.x*256 + threadIdx.x;
    int h  = g & 255;
    int bc = g >> 8;
    int b  = bc >> 4;
    int c  = bc & 15;
    float2 lam = g_lam[blk*HH + h];
    float2 s = make_float2(0.f, 0.f);
    size_t base = (size_t)(b*TT + c*CLEN)*256 + h;
    const uint32_t* ph = (const uint32_t*)g_buh;
    const uint32_t* pl = (const uint32_t*)g_bul;
    #pragma unroll 8
    for (int i = 0; i < CLEN; i++)
        s = cstep(lam, s, ldp(ph, pl, base + (size_t)i*256));
    g_carry[bc*HH + h] = s;
}
__global__ void scanB_kernel(int blk) {
    int b = blockIdx.x;
    int h = threadIdx.x;
    float2 lam = g_lam[blk*HH + h];
    float2 lp = lam;
    #pragma unroll
    for (int i = 0; i < 8; i++) {
        float2 t;
        t.x = lp.x*lp.x - lp.y*lp.y;
        t.y = 2.f*lp.x*lp.y;
        lp = t;
    }
    float2 s = make_float2(0.f, 0.f);
    for (int c = 0; c < NCH; c++) {
        g_inc[(b*NCH + c)*HH + h] = s;
        float2 cr = g_carry[(b*NCH + c)*HH + h];
        s = cstep(lp, s, cr);
    }
}
__global__ void scanC_kernel(int blk) {
    int g  = blockIdx.x*256 + threadIdx.x;
    int h  = g & 255;
    int bc = g >> 8;
    int b  = bc >> 4;
    int c  = bc & 15;
    float2 lam = g_lam[blk*HH + h];
    float2 s = g_inc[bc*HH + h];
    size_t base = (size_t)(b*TT + c*CLEN)*256 + h;
    uint32_t* ph = (uint32_t*)g_buh;
    uint32_t* pl = (uint32_t*)g_bul;
    #pragma unroll 8
    for (int i = 0; i < CLEN; i++) {
        size_t off = base + (size_t)i*256;
        s = cstep(lam, s, ldp(ph, pl, off));
        __nv_bfloat162 h2, l2;
        h2.x = __float2bfloat16(s.x);
        h2.y = __float2bfloat16(s.y);
        l2.x = __float2bfloat16(s.x - __bfloat162float(h2.x));
        l2.y = __float2bfloat16(s.y - __bfloat162float(h2.y));
        ph[off] = *(uint32_t*)&h2;
        pl[off] = *(uint32_t*)&l2;
    }
}

// ---------------- final: mean-pool + head ----------------
__global__ void final_kernel(const float* __restrict__ h,
                             const float* __restrict__ Wout,
                             const float* __restrict__ bout,
                             float* __restrict__ out) {
    __shared__ float pooled[DE];
    int b = blockIdx.x;
    int f = threadIdx.x;
    float s = 0.f;
    const float* p = h + (size_t)b*TT*DE + f;
    #pragma unroll 4
    for (int t = 0; t < TT; t++) s += p[(size_t)t*DE];
    pooled[f] = s * (1.f/TT);
    __syncthreads();
    if (f < OD) {
        float acc = bout[f];
        #pragma unroll 4
        for (int d = 0; d < DE; d++) acc = fmaf(pooled[d], Wout[d*OD + f], acc);
        out[b*OD + f] = acc;
    }
}

// ---------------- launch ----------------
extern "C" void kernel_launch(void* const* d_in, const int* in_sizes, int n_in,
                              void* d_out, int out_size) {
    const float* x         = (const float*)d_in[0];
    const float* nu_log    = (const float*)d_in[1];
    const float* theta_log = (const float*)d_in[2];
    const float* B_re      = (const float*)d_in[3];
    const float* B_im      = (const float*)d_in[4];
    const float* C_re      = (const float*)d_in[5];
    const float* C_im      = (const float*)d_in[6];
    const float* D_lru     = (const float*)d_in[7];
    const float* W1        = (const float*)d_in[8];
    const float* b1        = (const float*)d_in[9];
    const float* W2        = (const float*)d_in[10];
    const float* b2        = (const float*)d_in[11];
    const float* bn_scale  = (const float*)d_in[12];
    const float* bn_bias   = (const float*)d_in[13];
    const float* W_enc     = (const float*)d_in[14];
    const float* b_enc     = (const float*)d_in[15];
    const float* W_out     = (const float*)d_in[16];
    const float* b_out     = (const float*)d_in[17];
    float* out = (float*)d_out;

    float *yenc, *h, *lru, *glu;
    __nv_bfloat16 *buh, *bul, *wbh, *wbl, *wch, *wcl, *w1h, *w1l, *w2h, *w2l, *weh, *wel;
    cudaGetSymbolAddress((void**)&yenc, g_yenc);
    cudaGetSymbolAddress((void**)&h,    g_h);
    cudaGetSymbolAddress((void**)&lru,  g_lru);
    cudaGetSymbolAddress((void**)&glu,  g_glu);
    cudaGetSymbolAddress((void**)&buh,  g_buh);
    cudaGetSymbolAddress((void**)&bul,  g_bul);
    cudaGetSymbolAddress((void**)&wbh,  g_WBh);
    cudaGetSymbolAddress((void**)&wbl,  g_WBl);
    cudaGetSymbolAddress((void**)&wch,  g_WCh);
    cudaGetSymbolAddress((void**)&wcl,  g_WCl);
    cudaGetSymbolAddress((void**)&w1h,  g_W1h);
    cudaGetSymbolAddress((void**)&w1l,  g_W1l);
    cudaGetSymbolAddress((void**)&w2h,  g_W2h);
    cudaGetSymbolAddress((void**)&w2l,  g_W2l);
    cudaGetSymbolAddress((void**)&weh,  g_WEh);
    cudaGetSymbolAddress((void**)&wel,  g_WEl);

    cudaFuncSetAttribute(gemm_mma<64, 128, 0, 0, 0, 0, 0, 1>,  cudaFuncAttributeMaxDynamicSharedMemorySize, SMEM_BYTES);
    cudaFuncSetAttribute(gemm_mma<128, 512, 1, 0, 0, 0, 1, 0>, cudaFuncAttributeMaxDynamicSharedMemorySize, SMEM_BYTES);
    cudaFuncSetAttribute(gemm_mma<512, 128, 0, 1, 0, 1, 0, 0>, cudaFuncAttributeMaxDynamicSharedMemorySize, SMEM_BYTES);
    cudaFuncSetAttribute(gemm_mma<128, 256, 0, 0, 1, 0, 0, 0>, cudaFuncAttributeMaxDynamicSharedMemorySize, SMEM_BYTES);
    cudaFuncSetAttribute(gemm_mma<256, 128, 0, 2, 0, 0, 0, 1>, cudaFuncAttributeMaxDynamicSharedMemorySize, SMEM_BYTES);

    prep_lam_kernel<<<NBLKS, HH>>>(nu_log, theta_log);
    prep_WE_kernel<<<(DE*TSD + 255)/256, 256>>>(W_enc);
    prep_WB_kernel<<<(NBLKS*512*DE + 255)/256, 256>>>(B_re, B_im);

    // encoder: yenc = x @ W_enc + b_enc  (+ BN partials for block 0)
    gemm_mma<64, 128, 0, 0, 0, 0, 0, 1><<<dim3(1, NR/128), 256, SMEM_BYTES>>>(
        x, nullptr, nullptr, weh, wel, yenc, nullptr, nullptr, b_enc, nullptr, nullptr);

    prep_WC_kernel<<<(NBLKS*DE*512 + 255)/256, 256>>>(C_re, C_im);
    prep_W1_kernel<<<(NBLKS*512*DE + 255)/256, 256>>>(W1);
    prep_W2_kernel<<<(NBLKS*DE*256 + 255)/256, 256>>>(W2);

    const float* hp = yenc;
    for (int blk = 0; blk < NBLKS; blk++) {
        bn_stats2_kernel<<<1, 128>>>(bn_scale + blk*DE, bn_bias + blk*DE);

        // Bu = BN(h) @ WB  (plane output)
        gemm_mma<128, 512, 1, 0, 0, 0, 1, 0><<<dim3(4, NR/128), 256, SMEM_BYTES>>>(
            hp, nullptr, nullptr, wbh + (size_t)blk*512*128, wbl + (size_t)blk*512*128,
            nullptr, buh, bul, nullptr, nullptr, nullptr);

        scanA_kernel<<<NR/256, 256>>>(blk);
        scanB_kernel<<<BB, HH>>>(blk);
        scanC_kernel<<<NR/256, 256>>>(blk);

        // lru = Re(state @ C) + BN(h) * D   (plane A, exact)
        gemm_mma<512, 128, 0, 1, 0, 1, 0, 0><<<dim3(1, NR/128), 256, SMEM_BYTES>>>(
            nullptr, buh, bul, wch + (size_t)blk*128*512, wcl + (size_t)blk*128*512,
            lru, nullptr, nullptr, nullptr, hp, D_lru + blk*DE);

        // glu = GLU(lru @ W1 + b1)
        gemm_mma<128, 256, 0, 0, 1, 0, 0, 0><<<dim3(4, NR/128), 256, SMEM_BYTES>>>(
            lru, nullptr, nullptr, w1h + (size_t)blk*512*128, w1l + (size_t)blk*512*128,
            glu, nullptr, nullptr, b1 + (size_t)blk*LDF, nullptr, nullptr);

        // h = glu @ W2 + b2 + yenc  (+ BN partials for next block)
        gemm_mma<256, 128, 0, 2, 0, 0, 0, 1><<<dim3(1, NR/128), 256, SMEM_BYTES>>>(
            glu, nullptr, nullptr, w2h + (size_t)blk*128*256, w2l + (size_t)blk*128*256,
            h, nullptr, nullptr, b2 + blk*DE, yenc, nullptr);

        hp = h;
    }

    final_kernel<<<BB, DE>>>(hp, W_out, b_out, out);
}

// round 9
// speedup vs baseline: 1.0796x; 1.0209x over previous
#include <cuda_runtime.h>
#include <cuda_bf16.h>
#include <math.h>
#include <stdint.h>

// ---------------- problem constants ----------------
#define BB   16
#define TT   4096
#define NR   (BB*TT)
#define TSD  64
#define DE   128
#define HH   256
#define LDF  512
#define LDH  256
#define OD   10
#define NBLKS 6
#define EPSV 1e-5f
#define NCH  16
#define CLEN 256

// ---------------- scratch ----------------
static __device__ __align__(256) float g_yenc[(size_t)NR*DE];
static __device__ __align__(256) float g_h   [(size_t)NR*DE];
static __device__ __align__(256) float g_lru [(size_t)NR*DE];
static __device__ __align__(256) float g_glu [(size_t)NR*LDH];
static __device__ __align__(256) __nv_bfloat16 g_buh[(size_t)NR*512];  // Bu -> state (in place), hi plane
static __device__ __align__(256) __nv_bfloat16 g_bul[(size_t)NR*512];  // lo plane
static __device__ float2 g_lam [NBLKS*HH];
static __device__ float  g_gamma[NBLKS*HH];
static __device__ float  g_bnpart[512*2*DE];
static __device__ float  g_bna[DE];
static __device__ float  g_bnb[DE];
static __device__ float2 g_carry[BB*NCH*HH];
static __device__ float2 g_inc  [BB*NCH*HH];

// split bf16 weights [blk][n][k]
static __device__ __align__(256) __nv_bfloat16 g_WBh[(size_t)NBLKS*512*128];
static __device__ __align__(256) __nv_bfloat16 g_WBl[(size_t)NBLKS*512*128];
static __device__ __align__(256) __nv_bfloat16 g_WCh[(size_t)NBLKS*128*512];
static __device__ __align__(256) __nv_bfloat16 g_WCl[(size_t)NBLKS*128*512];
static __device__ __align__(256) __nv_bfloat16 g_W1h[(size_t)NBLKS*512*128];
static __device__ __align__(256) __nv_bfloat16 g_W1l[(size_t)NBLKS*512*128];
static __device__ __align__(256) __nv_bfloat16 g_W2h[(size_t)NBLKS*128*256];
static __device__ __align__(256) __nv_bfloat16 g_W2l[(size_t)NBLKS*128*256];
static __device__ __align__(256) __nv_bfloat16 g_WEh[128*64];
static __device__ __align__(256) __nv_bfloat16 g_WEl[128*64];

// ---------------- helpers ----------------
__device__ __forceinline__ uint32_t smem_u32(const void* p) {
    uint32_t a;
    asm("{ .reg .u64 t; cvta.to.shared.u64 t, %1; cvt.u32.u64 %0, t; }" : "=r"(a) : "l"(p));
    return a;
}
__device__ __forceinline__ void cp16(uint32_t dst, const void* src) {
    asm volatile("cp.async.cg.shared.global [%0], [%1], 16;" :: "r"(dst), "l"(src));
}
#define CP_COMMIT() asm volatile("cp.async.commit_group;" ::: "memory")
#define CP_WAIT0()  asm volatile("cp.async.wait_group 0;" ::: "memory")

#define MMA_BF16(d, a, b0, b1) \
    asm volatile("mma.sync.aligned.m16n8k16.row.col.f32.bf16.bf16.f32 " \
        "{%0,%1,%2,%3}, {%4,%5,%6,%7}, {%8,%9}, {%0,%1,%2,%3};" \
        : "+f"((d)[0]), "+f"((d)[1]), "+f"((d)[2]), "+f"((d)[3]) \
        : "r"((a)[0]), "r"((a)[1]), "r"((a)[2]), "r"((a)[3]), "r"(b0), "r"(b1))

#define LDSM4(r, addr) \
    asm volatile("ldmatrix.sync.aligned.m8n8.x4.shared.b16 {%0,%1,%2,%3}, [%4];" \
        : "=r"((r)[0]), "=r"((r)[1]), "=r"((r)[2]), "=r"((r)[3]) : "r"(addr))

__device__ __forceinline__ void split_store(float v, __nv_bfloat16* hi, __nv_bfloat16* lo, size_t i) {
    __nv_bfloat16 h = __float2bfloat16(v);
    hi[i] = h;
    lo[i] = __float2bfloat16(v - __bfloat162float(h));
}

// ---------------- prep ----------------
__global__ void prep_lam_kernel(const float* __restrict__ nu_log,
                                const float* __restrict__ theta_log) {
    int blk = blockIdx.x;
    int h   = threadIdx.x;
    float nu = nu_log[blk*HH + h];
    float th = theta_log[blk*HH + h];
    float r  = expf(-expf(nu));
    float ang = expf(th);
    float sn, cs;
    sincosf(ang, &sn, &cs);
    float2 lam; lam.x = r*cs; lam.y = r*sn;
    g_lam[blk*HH + h]   = lam;
    g_gamma[blk*HH + h] = sqrtf(fmaxf(1.f - r*r, 1e-8f));
}
__global__ void prep_WB_kernel(const float* __restrict__ Bre, const float* __restrict__ Bim) {
    int idx = blockIdx.x*256 + threadIdx.x;
    if (idx >= NBLKS*512*DE) return;
    int k = idx & 127;
    int n = (idx >> 7) & 511;
    int blk = idx >> 16;
    int h = n >> 1;
    float g = g_gamma[blk*HH + h];
    float v = ((n & 1) ? Bim : Bre)[((size_t)blk*HH + h)*DE + k] * g;
    split_store(v, g_WBh, g_WBl, idx);
}
__global__ void prep_WC_kernel(const float* __restrict__ Cre, const float* __restrict__ Cim) {
    int idx = blockIdx.x*256 + threadIdx.x;
    if (idx >= NBLKS*DE*512) return;
    int k = idx & 511;
    int n = (idx >> 9) & 127;
    int blk = idx >> 16;
    int h = k >> 1;
    float v = (k & 1) ? -Cim[((size_t)blk*DE + n)*HH + h] : Cre[((size_t)blk*DE + n)*HH + h];
    split_store(v, g_WCh, g_WCl, idx);
}
__global__ void prep_W1_kernel(const float* __restrict__ W1) {
    int idx = blockIdx.x*256 + threadIdx.x;
    if (idx >= NBLKS*512*DE) return;
    int k = idx & 127;
    int n = (idx >> 7) & 511;
    int blk = idx >> 16;
    split_store(W1[((size_t)blk*DE + k)*LDF + n], g_W1h, g_W1l, idx);
}
__global__ void prep_W2_kernel(const float* __restrict__ W2) {
    int idx = blockIdx.x*256 + threadIdx.x;
    if (idx >= NBLKS*DE*256) return;
    int k = idx & 255;
    int n = (idx >> 8) & 127;
    int blk = idx >> 15;
    split_store(W2[((size_t)blk*LDH + k)*DE + n], g_W2h, g_W2l, idx);
}
__global__ void prep_WE_kernel(const float* __restrict__ We) {
    int idx = blockIdx.x*256 + threadIdx.x;
    if (idx >= DE*TSD) return;
    int k = idx & 63;
    int n = idx >> 6;
    split_store(We[(size_t)k*DE + n], g_WEh, g_WEl, idx);
}

// ---------------- batchnorm stage-2 ----------------
__global__ void bn_stats2_kernel(const float* __restrict__ scale,
                                 const float* __restrict__ bias) {
    int f = threadIdx.x;
    float s = 0.f, s2 = 0.f;
    for (int i = 0; i < 512; i++) {
        s  += g_bnpart[i*(2*DE) + f];
        s2 += g_bnpart[i*(2*DE) + DE + f];
    }
    float mean = s * (1.f/NR);
    float var  = s2 * (1.f/NR) - mean*mean;
    float a = scale[f] * rsqrtf(var + EPSV);
    g_bna[f] = a;
    g_bnb[f] = fmaf(-mean, a, bias[f]);
}

// ---------------- ldmatrix bf16x3 GEMM: 512 threads, 16 warps (4x4), 32x32 warp tiles ----------------
// APLANES=0: A fp32, reg-staged + split-convert (MODE_A = BN affine).
// APLANES=1: A pre-split planes via cp.async. 3-term: Ahi*Bhi + Alo*Bhi + Ahi*Blo.
// EPI: 0 +bias?; 1 + (bna*aux+bnb)*dvec; 2 +bias + aux residual. DUAL: fused GLU.
// OUTPL: plane output. STATS: per-CTA BN partials (grid.x==1).
#define PITCH 72
#define UNITE (128*PITCH)
#define STAGEE (4*UNITE)
#define SMEM_BYTES (2*STAGEE*2)   // 147456
#define NTHR 512

template<int KDIM, int OUTW, int MODE_A, int EPI, int DUAL, int APLANES, int OUTPL, int STATS>
__global__ void __launch_bounds__(NTHR) gemm_mma(
    const float* __restrict__ Af,
    const __nv_bfloat16* __restrict__ Aph, const __nv_bfloat16* __restrict__ Apl,
    const __nv_bfloat16* __restrict__ Bhi, const __nv_bfloat16* __restrict__ Blo,
    float* __restrict__ Cf, __nv_bfloat16* __restrict__ Cph, __nv_bfloat16* __restrict__ Cpl,
    const float* __restrict__ bias,
    const float* __restrict__ auxf,
    const float* __restrict__ dvec)
{
    constexpr int O_AH = 0, O_AL = UNITE, O_BH = 2*UNITE, O_BL = 3*UNITE;
    constexpr int NCHK = KDIM / 64;

    extern __shared__ __nv_bfloat16 sm[];
    const uint32_t smb = smem_u32(sm);
    const int tid  = threadIdx.x;
    const int wid  = tid >> 5;
    const int lane = tid & 31;
    const int wr   = wid & 3;     // row warp: rows 32*wr
    const int wc4  = wid >> 2;    // col warp: 0..3
    const int g    = lane >> 2;
    const int t    = lane & 3;
    const int bm   = blockIdx.y << 7;
    const int bn   = DUAL ? (blockIdx.x << 6) : (blockIdx.x << 7);

    const int aLaneE = (lane & 15)*PITCH + (lane >> 4)*8;
    const int bLaneE = (lane & 7)*PITCH + ((lane >> 4) & 1)*(8*PITCH) + ((lane >> 3) & 1)*8;

    // non-dual: 4 n8-tiles (32 cols); dual: 2 gate + 2 sig n8-tiles (16 cols each)
    float accg[2][DUAL ? 2 : 4][4];
    float accs[DUAL ? 2 : 1][DUAL ? 2 : 1][4];
    #pragma unroll
    for (int rb = 0; rb < 2; rb++)
        #pragma unroll
        for (int nb = 0; nb < (DUAL ? 2 : 4); nb++)
            #pragma unroll
            for (int j = 0; j < 4; j++) {
                accg[rb][nb][j] = 0.f;
                if (DUAL) accs[rb][nb][j] = 0.f;
            }

    float4 areg[4];
    auto loadA = [&](int cc) {
        #pragma unroll
        for (int i = 0; i < 4; i++) {
            int idx = tid + NTHR*i;            // 2048 float4
            int row = idx >> 4;
            int col4 = (idx & 15) << 2;
            areg[i] = *(const float4*)(Af + (size_t)(bm + row)*KDIM + cc*64 + col4);
        }
    };
    auto storeA = [&](int cc, int so) {
        #pragma unroll
        for (int i = 0; i < 4; i++) {
            int idx = tid + NTHR*i;
            int row = idx >> 4;
            int col4 = (idx & 15) << 2;
            float4 v = areg[i];
            if (MODE_A) {
                float4 aa = *(const float4*)(g_bna + cc*64 + col4);
                float4 ab = *(const float4*)(g_bnb + cc*64 + col4);
                v.x = fmaf(aa.x, v.x, ab.x);
                v.y = fmaf(aa.y, v.y, ab.y);
                v.z = fmaf(aa.z, v.z, ab.z);
                v.w = fmaf(aa.w, v.w, ab.w);
            }
            __nv_bfloat16 h0 = __float2bfloat16(v.x), h1 = __float2bfloat16(v.y);
            __nv_bfloat16 h2 = __float2bfloat16(v.z), h3 = __float2bfloat16(v.w);
            __nv_bfloat16 l0 = __float2bfloat16(v.x - __bfloat162float(h0));
            __nv_bfloat16 l1 = __float2bfloat16(v.y - __bfloat162float(h1));
            __nv_bfloat16 l2 = __float2bfloat16(v.z - __bfloat162float(h2));
            __nv_bfloat16 l3 = __float2bfloat16(v.w - __bfloat162float(h3));
            uint32_t hu0 = ((uint32_t)__bfloat16_as_ushort(h1) << 16) | __bfloat16_as_ushort(h0);
            uint32_t hu1 = ((uint32_t)__bfloat16_as_ushort(h3) << 16) | __bfloat16_as_ushort(h2);
            uint32_t lu0 = ((uint32_t)__bfloat16_as_ushort(l1) << 16) | __bfloat16_as_ushort(l0);
            uint32_t lu1 = ((uint32_t)__bfloat16_as_ushort(l3) << 16) | __bfloat16_as_ushort(l2);
            int off = row*PITCH + col4;
            *(uint2*)(sm + so + O_AH + off) = make_uint2(hu0, hu1);
            *(uint2*)(sm + so + O_AL + off) = make_uint2(lu0, lu1);
        }
    };
    auto cpA = [&](int cc, int so) {
        #pragma unroll
        for (int i = 0; i < 4; i++) {
            int idx = tid + NTHR*i;            // 2048
            int pl  = idx >> 10;
            int rem = idx & 1023;
            int r   = rem >> 3;
            int q   = rem & 7;
            const __nv_bfloat16* src = pl ? Apl : Aph;
            cp16(smb + (uint32_t)((so + (pl ? O_AL : O_AH) + r*PITCH + q*8)*2),
                 src + (size_t)(bm + r)*KDIM + cc*64 + q*8);
        }
    };
    auto cpB = [&](int cc, int so) {
        #pragma unroll
        for (int i = 0; i < 4; i++) {
            int idx = tid + NTHR*i;
            int pl  = idx >> 10;
            int rem = idx & 1023;
            int r   = rem >> 3;
            int q   = rem & 7;
            int rowg = DUAL ? (r < 64 ? bn + r : bn + 256 + (r - 64)) : (bn + r);
            const __nv_bfloat16* src = pl ? Blo : Bhi;
            cp16(smb + (uint32_t)((so + (pl ? O_BL : O_BH) + r*PITCH + q*8)*2),
                 src + (size_t)rowg*KDIM + cc*64 + q*8);
        }
    };

    // prologue
    if (APLANES) cpA(0, 0); else loadA(0);
    cpB(0, 0);
    CP_COMMIT();
    if (!APLANES) {
        storeA(0, 0);
        if (NCHK > 1) loadA(1);
    }

    #pragma unroll 1
    for (int c = 0; c < NCHK; c++) {
        const int so = (c & 1)*STAGEE;
        CP_WAIT0();
        __syncthreads();
        if (c + 1 < NCHK) {
            const int nso = ((c+1) & 1)*STAGEE;
            cpB(c+1, nso);
            if (APLANES) cpA(c+1, nso);
            CP_COMMIT();
            if (!APLANES) {
                storeA(c+1, nso);
                if (c + 2 < NCHK) loadA(c+2);
            }
        }

        #pragma unroll
        for (int kk = 0; kk < 4; kk++) {
            const int kkE = kk*16;
            uint32_t ah[2][4], al[2][4];
            #pragma unroll
            for (int rb = 0; rb < 2; rb++) {
                int abase = so + (32*wr + 16*rb)*PITCH + kkE + aLaneE;
                LDSM4(ah[rb], smb + (uint32_t)((O_AH + abase)*2));
                LDSM4(al[rb], smb + (uint32_t)((O_AL + abase)*2));
            }
            if (!DUAL) {
                #pragma unroll
                for (int nb2 = 0; nb2 < 2; nb2++) {
                    uint32_t bh[4], bl[4];
                    int bbase = so + (32*wc4 + 16*nb2)*PITCH + kkE + bLaneE;
                    LDSM4(bh, smb + (uint32_t)((O_BH + bbase)*2));
                    LDSM4(bl, smb + (uint32_t)((O_BL + bbase)*2));
                    #pragma unroll
                    for (int rb = 0; rb < 2; rb++)
                        #pragma unroll
                        for (int j = 0; j < 2; j++) {
                            float* d = accg[rb][2*nb2 + j];
                            MMA_BF16(d, ah[rb], bh[2*j], bh[2*j+1]);
                            MMA_BF16(d, al[rb], bh[2*j], bh[2*j+1]);
                            MMA_BF16(d, ah[rb], bl[2*j], bl[2*j+1]);
                        }
                }
            } else {
                uint32_t bh[4], bl[4], dh[4], el[4];
                int bbase = so + (16*wc4)*PITCH + kkE + bLaneE;
                int sbase = bbase + 64*PITCH;
                LDSM4(bh, smb + (uint32_t)((O_BH + bbase)*2));
                LDSM4(bl, smb + (uint32_t)((O_BL + bbase)*2));
                LDSM4(dh, smb + (uint32_t)((O_BH + sbase)*2));
                LDSM4(el, smb + (uint32_t)((O_BL + sbase)*2));
                #pragma unroll
                for (int rb = 0; rb < 2; rb++)
                    #pragma unroll
                    for (int j = 0; j < 2; j++) {
                        float* dg = accg[rb][j];
                        float* ds = accs[rb][j];
                        MMA_BF16(dg, ah[rb], bh[2*j], bh[2*j+1]);
                        MMA_BF16(dg, al[rb], bh[2*j], bh[2*j+1]);
                        MMA_BF16(dg, ah[rb], bl[2*j], bl[2*j+1]);
                        MMA_BF16(ds, ah[rb], dh[2*j], dh[2*j+1]);
                        MMA_BF16(ds, al[rb], dh[2*j], dh[2*j+1]);
                        MMA_BF16(ds, ah[rb], el[2*j], el[2*j+1]);
                    }
            }
        }
    }

    // ---- epilogue ----
    float cs0[STATS ? 4 : 1], cs1[STATS ? 4 : 1], cq0[STATS ? 4 : 1], cq1[STATS ? 4 : 1];
    if (STATS) {
        #pragma unroll
        for (int nb = 0; nb < 4; nb++) { cs0[nb]=0.f; cs1[nb]=0.f; cq0[nb]=0.f; cq1[nb]=0.f; }
    }
    #pragma unroll
    for (int rb = 0; rb < 2; rb++) {
        int m0 = bm + 32*wr + 16*rb + g;
        #pragma unroll
        for (int nb = 0; nb < (DUAL ? 2 : 4); nb++) {
            if (!DUAL) {
                int col = bn + 32*wc4 + 8*nb + 2*t;
                float2 v0 = make_float2(accg[rb][nb][0], accg[rb][nb][1]);
                float2 v1 = make_float2(accg[rb][nb][2], accg[rb][nb][3]);
                if (EPI == 0) {
                    if (bias != nullptr) {
                        float2 bv = *(const float2*)(bias + col);
                        v0.x += bv.x; v0.y += bv.y; v1.x += bv.x; v1.y += bv.y;
                    }
                } else if (EPI == 1) {
                    float2 aa = *(const float2*)(g_bna + col);
                    float2 ab = *(const float2*)(g_bnb + col);
                    float2 dv = *(const float2*)(dvec + col);
                    float2 h0 = *(const float2*)(auxf + (size_t)m0*DE + col);
                    float2 h1 = *(const float2*)(auxf + (size_t)(m0+8)*DE + col);
                    v0.x += fmaf(aa.x, h0.x, ab.x)*dv.x;
                    v0.y += fmaf(aa.y, h0.y, ab.y)*dv.y;
                    v1.x += fmaf(aa.x, h1.x, ab.x)*dv.x;
                    v1.y += fmaf(aa.y, h1.y, ab.y)*dv.y;
                } else if (EPI == 2) {
                    float2 bv = *(const float2*)(bias + col);
                    float2 y0 = *(const float2*)(auxf + (size_t)m0*OUTW + col);
                    float2 y1 = *(const float2*)(auxf + (size_t)(m0+8)*OUTW + col);
                    v0.x += bv.x + y0.x; v0.y += bv.y + y0.y;
                    v1.x += bv.x + y1.x; v1.y += bv.y + y1.y;
                }
                if (STATS) {
                    cs0[nb] += v0.x + v1.x;
                    cs1[nb] += v0.y + v1.y;
                    cq0[nb] += v0.x*v0.x + v1.x*v1.x;
                    cq1[nb] += v0.y*v0.y + v1.y*v1.y;
                }
                if (OUTPL) {
                    __nv_bfloat162 h2, l2;
                    h2.x = __float2bfloat16(v0.x);
                    h2.y = __float2bfloat16(v0.y);
                    l2.x = __float2bfloat16(v0.x - __bfloat162float(h2.x));
                    l2.y = __float2bfloat16(v0.y - __bfloat162float(h2.y));
                    *(__nv_bfloat162*)(Cph + (size_t)m0*OUTW + col) = h2;
                    *(__nv_bfloat162*)(Cpl + (size_t)m0*OUTW + col) = l2;
                    h2.x = __float2bfloat16(v1.x);
                    h2.y = __float2bfloat16(v1.y);
                    l2.x = __float2bfloat16(v1.x - __bfloat162float(h2.x));
                    l2.y = __float2bfloat16(v1.y - __bfloat162float(h2.y));
                    *(__nv_bfloat162*)(Cph + (size_t)(m0+8)*OUTW + col) = h2;
                    *(__nv_bfloat162*)(Cpl + (size_t)(m0+8)*OUTW + col) = l2;
                } else {
                    *(float2*)(Cf + (size_t)m0*OUTW + col)     = v0;
                    *(float2*)(Cf + (size_t)(m0+8)*OUTW + col) = v1;
                }
            } else {
                int jc = bn + 16*wc4 + 8*nb + 2*t;
                float2 bg = *(const float2*)(bias + jc);
                float2 bs = *(const float2*)(bias + 256 + jc);
                float g0 = accg[rb][nb][0] + bg.x, s0 = accs[rb][nb][0] + bs.x;
                float g1 = accg[rb][nb][1] + bg.y, s1 = accs[rb][nb][1] + bs.y;
                float g2 = accg[rb][nb][2] + bg.x, s2 = accs[rb][nb][2] + bs.x;
                float g3 = accg[rb][nb][3] + bg.y, s3 = accs[rb][nb][3] + bs.y;
                float2 v0, v1;
                v0.x = g0 * (1.f/(1.f + expf(-s0)));
                v0.y = g1 * (1.f/(1.f + expf(-s1)));
                v1.x = g2 * (1.f/(1.f + expf(-s2)));
                v1.y = g3 * (1.f/(1.f + expf(-s3)));
                *(float2*)(Cf + (size_t)m0*OUTW + jc)     = v0;
                *(float2*)(Cf + (size_t)(m0+8)*OUTW + jc) = v1;
            }
        }
    }

    if (STATS && !DUAL) {
        #pragma unroll
        for (int nb = 0; nb < 4; nb++) {
            #pragma unroll
            for (int m = 4; m <= 16; m <<= 1) {
                cs0[nb] += __shfl_xor_sync(0xffffffffu, cs0[nb], m);
                cs1[nb] += __shfl_xor_sync(0xffffffffu, cs1[nb], m);
                cq0[nb] += __shfl_xor_sync(0xffffffffu, cq0[nb], m);
                cq1[nb] += __shfl_xor_sync(0xffffffffu, cq1[nb], m);
            }
        }
        __syncthreads();
        float* spart = (float*)sm;   // [4][128] sums + [4][128] sumsq
        if (lane < 4) {
            #pragma unroll
            for (int nb = 0; nb < 4; nb++) {
                int col = 32*wc4 + 8*nb + 2*lane;
                spart[wr*128 + col]           = cs0[nb];
                spart[wr*128 + col + 1]       = cs1[nb];
                spart[512 + wr*128 + col]     = cq0[nb];
                spart[512 + wr*128 + col + 1] = cq1[nb];
            }
        }
        __syncthreads();
        if (tid < 128) {
            float s  = spart[tid] + spart[128+tid] + spart[256+tid] + spart[384+tid];
            float s2 = spart[512+tid] + spart[640+tid] + spart[768+tid] + spart[896+tid];
            g_bnpart[blockIdx.y*(2*DE) + tid]      = s;
            g_bnpart[blockIdx.y*(2*DE) + DE + tid] = s2;
        }
    }
}

// ---------------- LRU scan (plane Bu in, in-place plane state out) ----------------
__device__ __forceinline__ float2 cstep(float2 lam, float2 s, float2 u) {
    float2 t;
    t.x = fmaf(lam.x, s.x, fmaf(-lam.y, s.y, u.x));
    t.y = fmaf(lam.x, s.y, fmaf( lam.y, s.x, u.y));
    return t;
}
__device__ __forceinline__ float2 ldp(const uint32_t* ph, const uint32_t* pl, size_t off) {
    uint32_t rh = ph[off], rl = pl[off];
    __nv_bfloat162 h2 = *(__nv_bfloat162*)&rh;
    __nv_bfloat162 l2 = *(__nv_bfloat162*)&rl;
    return make_float2(__bfloat162float(h2.x) + __bfloat162float(l2.x),
                       __bfloat162float(h2.y) + __bfloat162float(l2.y));
}
__global__ void scanA_kernel(int blk) {
    int g  = blockIdx.x*256 + threadIdx.x;
    int h  = g & 255;
    int bc = g >> 8;
    int b  = bc >> 4;
    int c  = bc & 15;
    float2 lam = g_lam[blk*HH + h];
    float2 s = make_float2(0.f, 0.f);
    size_t base = (size_t)(b*TT + c*CLEN)*256 + h;
    const uint32_t* ph = (const uint32_t*)g_buh;
    const uint32_t* pl = (const uint32_t*)g_bul;
    #pragma unroll 8
    for (int i = 0; i < CLEN; i++)
        s = cstep(lam, s, ldp(ph, pl, base + (size_t)i*256));
    g_carry[bc*HH + h] = s;
}
__global__ void scanB_kernel(int blk) {
    int b = blockIdx.x;
    int h = threadIdx.x;
    float2 lam = g_lam[blk*HH + h];
    float2 lp = lam;
    #pragma unroll
    for (int i = 0; i < 8; i++) {
        float2 t;
        t.x = lp.x*lp.x - lp.y*lp.y;
        t.y = 2.f*lp.x*lp.y;
        lp = t;
    }
    float2 s = make_float2(0.f, 0.f);
    for (int c = 0; c < NCH; c++) {
        g_inc[(b*NCH + c)*HH + h] = s;
        float2 cr = g_carry[(b*NCH + c)*HH + h];
        s = cstep(lp, s, cr);
    }
}
__global__ void scanC_kernel(int blk) {
    int g  = blockIdx.x*256 + threadIdx.x;
    int h  = g & 255;
    int bc = g >> 8;
    int b  = bc >> 4;
    int c  = bc & 15;
    float2 lam = g_lam[blk*HH + h];
    float2 s = g_inc[bc*HH + h];
    size_t base = (size_t)(b*TT + c*CLEN)*256 + h;
    uint32_t* ph = (uint32_t*)g_buh;
    uint32_t* pl = (uint32_t*)g_bul;
    #pragma unroll 8
    for (int i = 0; i < CLEN; i++) {
        size_t off = base + (size_t)i*256;
        s = cstep(lam, s, ldp(ph, pl, off));
        __nv_bfloat162 h2, l2;
        h2.x = __float2bfloat16(s.x);
        h2.y = __float2bfloat16(s.y);
        l2.x = __float2bfloat16(s.x - __bfloat162float(h2.x));
        l2.y = __float2bfloat16(s.y - __bfloat162float(h2.y));
        ph[off] = *(uint32_t*)&h2;
        pl[off] = *(uint32_t*)&l2;
    }
}

// ---------------- final: mean-pool + head ----------------
__global__ void final_kernel(const float* __restrict__ h,
                             const float* __restrict__ Wout,
                             const float* __restrict__ bout,
                             float* __restrict__ out) {
    __shared__ float pooled[DE];
    int b = blockIdx.x;
    int f = threadIdx.x;
    float s = 0.f;
    const float* p = h + (size_t)b*TT*DE + f;
    #pragma unroll 4
    for (int t = 0; t < TT; t++) s += p[(size_t)t*DE];
    pooled[f] = s * (1.f/TT);
    __syncthreads();
    if (f < OD) {
        float acc = bout[f];
        #pragma unroll 4
        for (int d = 0; d < DE; d++) acc = fmaf(pooled[d], Wout[d*OD + f], acc);
        out[b*OD + f] = acc;
    }
}

// ---------------- launch ----------------
extern "C" void kernel_launch(void* const* d_in, const int* in_sizes, int n_in,
                              void* d_out, int out_size) {
    const float* x         = (const float*)d_in[0];
    const float* nu_log    = (const float*)d_in[1];
    const float* theta_log = (const float*)d_in[2];
    const float* B_re      = (const float*)d_in[3];
    const float* B_im      = (const float*)d_in[4];
    const float* C_re      = (const float*)d_in[5];
    const float* C_im      = (const float*)d_in[6];
    const float* D_lru     = (const float*)d_in[7];
    const float* W1        = (const float*)d_in[8];
    const float* b1        = (const float*)d_in[9];
    const float* W2        = (const float*)d_in[10];
    const float* b2        = (const float*)d_in[11];
    const float* bn_scale  = (const float*)d_in[12];
    const float* bn_bias   = (const float*)d_in[13];
    const float* W_enc     = (const float*)d_in[14];
    const float* b_enc     = (const float*)d_in[15];
    const float* W_out     = (const float*)d_in[16];
    const float* b_out     = (const float*)d_in[17];
    float* out = (float*)d_out;

    float *yenc, *h, *lru, *glu;
    __nv_bfloat16 *buh, *bul, *wbh, *wbl, *wch, *wcl, *w1h, *w1l, *w2h, *w2l, *weh, *wel;
    cudaGetSymbolAddress((void**)&yenc, g_yenc);
    cudaGetSymbolAddress((void**)&h,    g_h);
    cudaGetSymbolAddress((void**)&lru,  g_lru);
    cudaGetSymbolAddress((void**)&glu,  g_glu);
    cudaGetSymbolAddress((void**)&buh,  g_buh);
    cudaGetSymbolAddress((void**)&bul,  g_bul);
    cudaGetSymbolAddress((void**)&wbh,  g_WBh);
    cudaGetSymbolAddress((void**)&wbl,  g_WBl);
    cudaGetSymbolAddress((void**)&wch,  g_WCh);
    cudaGetSymbolAddress((void**)&wcl,  g_WCl);
    cudaGetSymbolAddress((void**)&w1h,  g_W1h);
    cudaGetSymbolAddress((void**)&w1l,  g_W1l);
    cudaGetSymbolAddress((void**)&w2h,  g_W2h);
    cudaGetSymbolAddress((void**)&w2l,  g_W2l);
    cudaGetSymbolAddress((void**)&weh,  g_WEh);
    cudaGetSymbolAddress((void**)&wel,  g_WEl);

    cudaFuncSetAttribute(gemm_mma<64, 128, 0, 0, 0, 0, 0, 1>,  cudaFuncAttributeMaxDynamicSharedMemorySize, SMEM_BYTES);
    cudaFuncSetAttribute(gemm_mma<128, 512, 1, 0, 0, 0, 1, 0>, cudaFuncAttributeMaxDynamicSharedMemorySize, SMEM_BYTES);
    cudaFuncSetAttribute(gemm_mma<512, 128, 0, 1, 0, 1, 0, 0>, cudaFuncAttributeMaxDynamicSharedMemorySize, SMEM_BYTES);
    cudaFuncSetAttribute(gemm_mma<128, 256, 0, 0, 1, 0, 0, 0>, cudaFuncAttributeMaxDynamicSharedMemorySize, SMEM_BYTES);
    cudaFuncSetAttribute(gemm_mma<256, 128, 0, 2, 0, 0, 0, 1>, cudaFuncAttributeMaxDynamicSharedMemorySize, SMEM_BYTES);

    prep_lam_kernel<<<NBLKS, HH>>>(nu_log, theta_log);
    prep_WE_kernel<<<(DE*TSD + 255)/256, 256>>>(W_enc);
    prep_WB_kernel<<<(NBLKS*512*DE + 255)/256, 256>>>(B_re, B_im);

    // encoder: yenc = x @ W_enc + b_enc  (+ BN partials for block 0)
    gemm_mma<64, 128, 0, 0, 0, 0, 0, 1><<<dim3(1, NR/128), NTHR, SMEM_BYTES>>>(
        x, nullptr, nullptr, weh, wel, yenc, nullptr, nullptr, b_enc, nullptr, nullptr);

    prep_WC_kernel<<<(NBLKS*DE*512 + 255)/256, 256>>>(C_re, C_im);
    prep_W1_kernel<<<(NBLKS*512*DE + 255)/256, 256>>>(W1);
    prep_W2_kernel<<<(NBLKS*DE*256 + 255)/256, 256>>>(W2);

    const float* hp = yenc;
    for (int blk = 0; blk < NBLKS; blk++) {
        bn_stats2_kernel<<<1, 128>>>(bn_scale + blk*DE, bn_bias + blk*DE);

        // Bu = BN(h) @ WB  (plane output)
        gemm_mma<128, 512, 1, 0, 0, 0, 1, 0><<<dim3(4, NR/128), NTHR, SMEM_BYTES>>>(
            hp, nullptr, nullptr, wbh + (size_t)blk*512*128, wbl + (size_t)blk*512*128,
            nullptr, buh, bul, nullptr, nullptr, nullptr);

        scanA_kernel<<<NR/256, 256>>>(blk);
        scanB_kernel<<<BB, HH>>>(blk);
        scanC_kernel<<<NR/256, 256>>>(blk);

        // lru = Re(state @ C) + BN(h) * D   (plane A, exact)
        gemm_mma<512, 128, 0, 1, 0, 1, 0, 0><<<dim3(1, NR/128), NTHR, SMEM_BYTES>>>(
            nullptr, buh, bul, wch + (size_t)blk*128*512, wcl + (size_t)blk*128*512,
            lru, nullptr, nullptr, nullptr, hp, D_lru + blk*DE);

        // glu = GLU(lru @ W1 + b1)
        gemm_mma<128, 256, 0, 0, 1, 0, 0, 0><<<dim3(4, NR/128), NTHR, SMEM_BYTES>>>(
            lru, nullptr, nullptr, w1h + (size_t)blk*512*128, w1l + (size_t)blk*512*128,
            glu, nullptr, nullptr, b1 + (size_t)blk*LDF, nullptr, nullptr);

        // h = glu @ W2 + b2 + yenc  (+ BN partials for next block)
        gemm_mma<256, 128, 0, 2, 0, 0, 0, 1><<<dim3(1, NR/128), NTHR, SMEM_BYTES>>>(
            glu, nullptr, nullptr, w2h + (size_t)blk*128*256, w2l + (size_t)blk*128*256,
            h, nullptr, nullptr, b2 + blk*DE, yenc, nullptr);

        hp = h;
    }

    final_kernel<<<BB, DE>>>(hp, W_out, b_out, out);
}

// round 10
// speedup vs baseline: 1.8488x; 1.7126x over previous
#include <cuda_runtime.h>
#include <cuda_bf16.h>
#include <cuda_fp16.h>
#include <math.h>
#include <stdint.h>

// ---------------- problem constants ----------------
#define BB   16
#define TT   4096
#define NR   (BB*TT)
#define TSD  64
#define DE   128
#define HH   256
#define LDF  512
#define LDH  256
#define OD   10
#define NBLKS 6
#define EPSV 1e-5f
#define NCH  16
#define CLEN 256

// ---------------- scratch ----------------
static __device__ __align__(256) float g_yenc[(size_t)NR*DE];
static __device__ __align__(256) float g_h   [(size_t)NR*DE];
static __device__ __align__(256) __half g_lru[(size_t)NR*DE];
static __device__ __align__(256) __half g_glu[(size_t)NR*LDH];
static __device__ __align__(256) __half g_bu [(size_t)NR*512];   // Bu -> state (in place), fp16
static __device__ float2 g_lam [NBLKS*HH];
static __device__ float  g_gamma[NBLKS*HH];
static __device__ float  g_bnpart[512*2*DE];
static __device__ float  g_bna[DE];
static __device__ float  g_bnb[DE];
static __device__ float2 g_carry[BB*NCH*HH];
static __device__ float2 g_inc  [BB*NCH*HH];

// weights: bf16 split for fp32-A GEMMs (encoder, Bu); fp16 split for fp16-A GEMMs
static __device__ __align__(256) __nv_bfloat16 g_WBh[(size_t)NBLKS*512*128];
static __device__ __align__(256) __nv_bfloat16 g_WBl[(size_t)NBLKS*512*128];
static __device__ __align__(256) __nv_bfloat16 g_WEh[128*64];
static __device__ __align__(256) __nv_bfloat16 g_WEl[128*64];
static __device__ __align__(256) __half g_WCh[(size_t)NBLKS*128*512];
static __device__ __align__(256) __half g_WCl[(size_t)NBLKS*128*512];
static __device__ __align__(256) __half g_W1h[(size_t)NBLKS*512*128];
static __device__ __align__(256) __half g_W1l[(size_t)NBLKS*512*128];
static __device__ __align__(256) __half g_W2h[(size_t)NBLKS*128*256];
static __device__ __align__(256) __half g_W2l[(size_t)NBLKS*128*256];

// ---------------- helpers ----------------
__device__ __forceinline__ uint32_t smem_u32(const void* p) {
    uint32_t a;
    asm("{ .reg .u64 t; cvta.to.shared.u64 t, %1; cvt.u32.u64 %0, t; }" : "=r"(a) : "l"(p));
    return a;
}
__device__ __forceinline__ void cp16(uint32_t dst, const void* src) {
    asm volatile("cp.async.cg.shared.global [%0], [%1], 16;" :: "r"(dst), "l"(src));
}
#define CP_COMMIT() asm volatile("cp.async.commit_group;" ::: "memory")
#define CP_WAIT0()  asm volatile("cp.async.wait_group 0;" ::: "memory")

#define MMA_BF16(d, a, b0, b1) \
    asm volatile("mma.sync.aligned.m16n8k16.row.col.f32.bf16.bf16.f32 " \
        "{%0,%1,%2,%3}, {%4,%5,%6,%7}, {%8,%9}, {%0,%1,%2,%3};" \
        : "+f"((d)[0]), "+f"((d)[1]), "+f"((d)[2]), "+f"((d)[3]) \
        : "r"((a)[0]), "r"((a)[1]), "r"((a)[2]), "r"((a)[3]), "r"(b0), "r"(b1))

#define MMA_F16(d, a, b0, b1) \
    asm volatile("mma.sync.aligned.m16n8k16.row.col.f32.f16.f16.f32 " \
        "{%0,%1,%2,%3}, {%4,%5,%6,%7}, {%8,%9}, {%0,%1,%2,%3};" \
        : "+f"((d)[0]), "+f"((d)[1]), "+f"((d)[2]), "+f"((d)[3]) \
        : "r"((a)[0]), "r"((a)[1]), "r"((a)[2]), "r"((a)[3]), "r"(b0), "r"(b1))

#define LDSM4(r, addr) \
    asm volatile("ldmatrix.sync.aligned.m8n8.x4.shared.b16 {%0,%1,%2,%3}, [%4];" \
        : "=r"((r)[0]), "=r"((r)[1]), "=r"((r)[2]), "=r"((r)[3]) : "r"(addr))

__device__ __forceinline__ void split_store(float v, __nv_bfloat16* hi, __nv_bfloat16* lo, size_t i) {
    __nv_bfloat16 h = __float2bfloat16(v);
    hi[i] = h;
    lo[i] = __float2bfloat16(v - __bfloat162float(h));
}
__device__ __forceinline__ void split_store_h(float v, __half* hi, __half* lo, size_t i) {
    __half h = __float2half_rn(v);
    hi[i] = h;
    lo[i] = __float2half_rn(v - __half2float(h));
}

// ---------------- prep ----------------
__global__ void prep_lam_kernel(const float* __restrict__ nu_log,
                                const float* __restrict__ theta_log) {
    int blk = blockIdx.x;
    int h   = threadIdx.x;
    float nu = nu_log[blk*HH + h];
    float th = theta_log[blk*HH + h];
    float r  = expf(-expf(nu));
    float ang = expf(th);
    float sn, cs;
    sincosf(ang, &sn, &cs);
    float2 lam; lam.x = r*cs; lam.y = r*sn;
    g_lam[blk*HH + h]   = lam;
    g_gamma[blk*HH + h] = sqrtf(fmaxf(1.f - r*r, 1e-8f));
}
__global__ void prep_WB_kernel(const float* __restrict__ Bre, const float* __restrict__ Bim) {
    int idx = blockIdx.x*256 + threadIdx.x;
    if (idx >= NBLKS*512*DE) return;
    int k = idx & 127;
    int n = (idx >> 7) & 511;
    int blk = idx >> 16;
    int h = n >> 1;
    float g = g_gamma[blk*HH + h];
    float v = ((n & 1) ? Bim : Bre)[((size_t)blk*HH + h)*DE + k] * g;
    split_store(v, g_WBh, g_WBl, idx);
}
__global__ void prep_WC_kernel(const float* __restrict__ Cre, const float* __restrict__ Cim) {
    int idx = blockIdx.x*256 + threadIdx.x;
    if (idx >= NBLKS*DE*512) return;
    int k = idx & 511;
    int n = (idx >> 9) & 127;
    int blk = idx >> 16;
    int h = k >> 1;
    float v = (k & 1) ? -Cim[((size_t)blk*DE + n)*HH + h] : Cre[((size_t)blk*DE + n)*HH + h];
    split_store_h(v, g_WCh, g_WCl, idx);
}
__global__ void prep_W1_kernel(const float* __restrict__ W1) {
    int idx = blockIdx.x*256 + threadIdx.x;
    if (idx >= NBLKS*512*DE) return;
    int k = idx & 127;
    int n = (idx >> 7) & 511;
    int blk = idx >> 16;
    split_store_h(W1[((size_t)blk*DE + k)*LDF + n], g_W1h, g_W1l, idx);
}
__global__ void prep_W2_kernel(const float* __restrict__ W2) {
    int idx = blockIdx.x*256 + threadIdx.x;
    if (idx >= NBLKS*DE*256) return;
    int k = idx & 255;
    int n = (idx >> 8) & 127;
    int blk = idx >> 15;
    split_store_h(W2[((size_t)blk*LDH + k)*DE + n], g_W2h, g_W2l, idx);
}
__global__ void prep_WE_kernel(const float* __restrict__ We) {
    int idx = blockIdx.x*256 + threadIdx.x;
    if (idx >= DE*TSD) return;
    int k = idx & 63;
    int n = idx >> 6;
    split_store(We[(size_t)k*DE + n], g_WEh, g_WEl, idx);
}

// ---------------- batchnorm stage-2 (parallel) ----------------
__global__ void bn_stats2_kernel(const float* __restrict__ scale,
                                 const float* __restrict__ bias) {
    __shared__ float ss[512], sq[512];
    int tid = threadIdx.x;           // 512
    int f = tid & 127;
    int grp = tid >> 7;              // 0..3
    float s = 0.f, s2 = 0.f;
    for (int i = grp; i < 512; i += 4) {
        s  += g_bnpart[i*(2*DE) + f];
        s2 += g_bnpart[i*(2*DE) + DE + f];
    }
    ss[tid] = s;
    sq[tid] = s2;
    __syncthreads();
    if (tid < 128) {
        s  = ss[tid] + ss[128+tid] + ss[256+tid] + ss[384+tid];
        s2 = sq[tid] + sq[128+tid] + sq[256+tid] + sq[384+tid];
        float mean = s * (1.f/NR);
        float var  = s2 * (1.f/NR) - mean*mean;
        float a = scale[tid] * rsqrtf(var + EPSV);
        g_bna[tid] = a;
        g_bnb[tid] = fmaf(-mean, a, bias[tid]);
    }
}

// ---------------- GEMM: 512 threads, 16 warps (4x4), 32x32 warp tiles ----------------
// AF16=0: A fp32 reg-staged -> bf16 split (3-term, MODE_A = BN affine). B = bf16 planes.
// AF16=1: A fp16 via cp.async; B = fp16-split weights; 2-term fp16 MMA (exact weights).
// EPI: 0 +bias?; 1 + (bna*aux+bnb)*dvec; 2 +bias + aux residual. DUAL: fused GLU.
// OUTH: output single fp16. STATS: per-CTA BN partials (grid.x must be 1).
#define PITCH 72
#define UNITE (128*PITCH)
#define SMEM_F32A (2*4*UNITE*2)   // 147456
#define SMEM_F16A (2*3*UNITE*2)   // 110592
#define NTHR 512

template<int KDIM, int OUTW, int MODE_A, int EPI, int DUAL, int AF16, int OUTH, int STATS>
__global__ void __launch_bounds__(NTHR) gemm_mma(
    const void* __restrict__ Av,
    const void* __restrict__ Bhi_, const void* __restrict__ Blo_,
    void* __restrict__ Cv,
    const float* __restrict__ bias,
    const float* __restrict__ auxf,
    const float* __restrict__ dvec)
{
    constexpr int NBUFS = AF16 ? 3 : 4;
    constexpr int O_AH = 0, O_AL = UNITE;
    constexpr int O_BH = AF16 ? UNITE : 2*UNITE;
    constexpr int O_BL = O_BH + UNITE;
    constexpr int STAGE = NBUFS*UNITE;
    constexpr int NCHK = KDIM / 64;

    extern __shared__ __nv_bfloat16 sm[];
    const uint32_t smb = smem_u32(sm);
    const int tid  = threadIdx.x;
    const int lane = tid & 31;
    const int wid  = tid >> 5;
    const int wr   = wid & 3;
    const int wc4  = wid >> 2;
    const int g    = lane >> 2;
    const int t    = lane & 3;
    const int bm   = blockIdx.y << 7;
    const int bn   = DUAL ? (blockIdx.x << 6) : (blockIdx.x << 7);

    const int aLaneE = (lane & 15)*PITCH + (lane >> 4)*8;
    const int bLaneE = (lane & 7)*PITCH + ((lane >> 4) & 1)*(8*PITCH) + ((lane >> 3) & 1)*8;

    float accg[2][DUAL ? 2 : 4][4];
    float accs[DUAL ? 2 : 1][DUAL ? 2 : 1][4];
    #pragma unroll
    for (int rb = 0; rb < 2; rb++)
        #pragma unroll
        for (int nb = 0; nb < (DUAL ? 2 : 4); nb++)
            #pragma unroll
            for (int j = 0; j < 4; j++) {
                accg[rb][nb][j] = 0.f;
                if (DUAL) accs[rb][nb][j] = 0.f;
            }

    float4 areg[4];
    auto loadA = [&](int cc) {
        const float* Af = (const float*)Av;
        #pragma unroll
        for (int i = 0; i < 4; i++) {
            int idx = tid + NTHR*i;
            int row = idx >> 4;
            int col4 = (idx & 15) << 2;
            areg[i] = *(const float4*)(Af + (size_t)(bm + row)*KDIM + cc*64 + col4);
        }
    };
    auto storeA = [&](int cc, int so) {
        #pragma unroll
        for (int i = 0; i < 4; i++) {
            int idx = tid + NTHR*i;
            int row = idx >> 4;
            int col4 = (idx & 15) << 2;
            float4 v = areg[i];
            if (MODE_A) {
                float4 aa = *(const float4*)(g_bna + cc*64 + col4);
                float4 ab = *(const float4*)(g_bnb + cc*64 + col4);
                v.x = fmaf(aa.x, v.x, ab.x);
                v.y = fmaf(aa.y, v.y, ab.y);
                v.z = fmaf(aa.z, v.z, ab.z);
                v.w = fmaf(aa.w, v.w, ab.w);
            }
            __nv_bfloat16 h0 = __float2bfloat16(v.x), h1 = __float2bfloat16(v.y);
            __nv_bfloat16 h2 = __float2bfloat16(v.z), h3 = __float2bfloat16(v.w);
            __nv_bfloat16 l0 = __float2bfloat16(v.x - __bfloat162float(h0));
            __nv_bfloat16 l1 = __float2bfloat16(v.y - __bfloat162float(h1));
            __nv_bfloat16 l2 = __float2bfloat16(v.z - __bfloat162float(h2));
            __nv_bfloat16 l3 = __float2bfloat16(v.w - __bfloat162float(h3));
            uint32_t hu0 = ((uint32_t)__bfloat16_as_ushort(h1) << 16) | __bfloat16_as_ushort(h0);
            uint32_t hu1 = ((uint32_t)__bfloat16_as_ushort(h3) << 16) | __bfloat16_as_ushort(h2);
            uint32_t lu0 = ((uint32_t)__bfloat16_as_ushort(l1) << 16) | __bfloat16_as_ushort(l0);
            uint32_t lu1 = ((uint32_t)__bfloat16_as_ushort(l3) << 16) | __bfloat16_as_ushort(l2);
            int off = row*PITCH + col4;
            *(uint2*)(sm + so + O_AH + off) = make_uint2(hu0, hu1);
            *(uint2*)(sm + so + O_AL + off) = make_uint2(lu0, lu1);
        }
    };
    auto cpA16 = [&](int cc, int so) {
        const __half* Ahalf = (const __half*)Av;
        #pragma unroll
        for (int i = 0; i < 2; i++) {
            int idx = tid + NTHR*i;     // 1024 transfers
            int r = idx >> 3;
            int q = idx & 7;
            cp16(smb + (uint32_t)((so + O_AH + r*PITCH + q*8)*2),
                 Ahalf + (size_t)(bm + r)*KDIM + cc*64 + q*8);
        }
    };
    auto cpB = [&](int cc, int so) {
        const __nv_bfloat16* Bh = (const __nv_bfloat16*)Bhi_;
        const __nv_bfloat16* Bl = (const __nv_bfloat16*)Blo_;
        #pragma unroll
        for (int i = 0; i < 4; i++) {
            int idx = tid + NTHR*i;     // 2048
            int pl  = idx >> 10;
            int rem = idx & 1023;
            int r   = rem >> 3;
            int q   = rem & 7;
            int rowg = DUAL ? (r < 64 ? bn + r : bn + 256 + (r - 64)) : (bn + r);
            const __nv_bfloat16* src = pl ? Bl : Bh;
            cp16(smb + (uint32_t)((so + (pl ? O_BL : O_BH) + r*PITCH + q*8)*2),
                 src + (size_t)rowg*KDIM + cc*64 + q*8);
        }
    };

    // prologue
    if (AF16) cpA16(0, 0); else loadA(0);
    cpB(0, 0);
    CP_COMMIT();
    if (!AF16) {
        storeA(0, 0);
        if (NCHK > 1) loadA(1);
    }

    #pragma unroll 1
    for (int c = 0; c < NCHK; c++) {
        const int so = (c & 1)*STAGE;
        CP_WAIT0();
        __syncthreads();
        if (c + 1 < NCHK) {
            const int nso = ((c+1) & 1)*STAGE;
            cpB(c+1, nso);
            if (AF16) cpA16(c+1, nso);
            CP_COMMIT();
            if (!AF16) {
                storeA(c+1, nso);
                if (c + 2 < NCHK) loadA(c+2);
            }
        }

        #pragma unroll
        for (int kk = 0; kk < 4; kk++) {
            const int kkE = kk*16;
            uint32_t ah[2][4], al[2][4];
            #pragma unroll
            for (int rb = 0; rb < 2; rb++) {
                int abase = so + (32*wr + 16*rb)*PITCH + kkE + aLaneE;
                LDSM4(ah[rb], smb + (uint32_t)((O_AH + abase)*2));
                if (!AF16) LDSM4(al[rb], smb + (uint32_t)((O_AL + abase)*2));
            }
            if (!DUAL) {
                #pragma unroll
                for (int nb2 = 0; nb2 < 2; nb2++) {
                    uint32_t bh[4], bl[4];
                    int bbase = so + (32*wc4 + 16*nb2)*PITCH + kkE + bLaneE;
                    LDSM4(bh, smb + (uint32_t)((O_BH + bbase)*2));
                    LDSM4(bl, smb + (uint32_t)((O_BL + bbase)*2));
                    #pragma unroll
                    for (int rb = 0; rb < 2; rb++)
                        #pragma unroll
                        for (int j = 0; j < 2; j++) {
                            float* d = accg[rb][2*nb2 + j];
                            if (AF16) {
                                MMA_F16(d, ah[rb], bh[2*j], bh[2*j+1]);
                                MMA_F16(d, ah[rb], bl[2*j], bl[2*j+1]);
                            } else {
                                MMA_BF16(d, ah[rb], bh[2*j], bh[2*j+1]);
                                MMA_BF16(d, al[rb], bh[2*j], bh[2*j+1]);
                                MMA_BF16(d, ah[rb], bl[2*j], bl[2*j+1]);
                            }
                        }
                }
            } else {
                uint32_t bh[4], bl[4], dh[4], el[4];
                int bbase = so + (16*wc4)*PITCH + kkE + bLaneE;
                int sbase = bbase + 64*PITCH;
                LDSM4(bh, smb + (uint32_t)((O_BH + bbase)*2));
                LDSM4(bl, smb + (uint32_t)((O_BL + bbase)*2));
                LDSM4(dh, smb + (uint32_t)((O_BH + sbase)*2));
                LDSM4(el, smb + (uint32_t)((O_BL + sbase)*2));
                #pragma unroll
                for (int rb = 0; rb < 2; rb++)
                    #pragma unroll
                    for (int j = 0; j < 2; j++) {
                        float* dg = accg[rb][j];
                        float* ds = accs[rb][j];
                        if (AF16) {
                            MMA_F16(dg, ah[rb], bh[2*j], bh[2*j+1]);
                            MMA_F16(dg, ah[rb], bl[2*j], bl[2*j+1]);
                            MMA_F16(ds, ah[rb], dh[2*j], dh[2*j+1]);
                            MMA_F16(ds, ah[rb], el[2*j], el[2*j+1]);
                        } else {
                            MMA_BF16(dg, ah[rb], bh[2*j], bh[2*j+1]);
                            MMA_BF16(dg, al[rb], bh[2*j], bh[2*j+1]);
                            MMA_BF16(dg, ah[rb], bl[2*j], bl[2*j+1]);
                            MMA_BF16(ds, ah[rb], dh[2*j], dh[2*j+1]);
                            MMA_BF16(ds, al[rb], dh[2*j], dh[2*j+1]);
                            MMA_BF16(ds, ah[rb], el[2*j], el[2*j+1]);
                        }
                    }
            }
        }
    }

    // ---- epilogue ----
    float cs0[STATS ? 4 : 1], cs1[STATS ? 4 : 1], cq0[STATS ? 4 : 1], cq1[STATS ? 4 : 1];
    if (STATS) {
        #pragma unroll
        for (int nb = 0; nb < 4; nb++) { cs0[nb]=0.f; cs1[nb]=0.f; cq0[nb]=0.f; cq1[nb]=0.f; }
    }
    #pragma unroll
    for (int rb = 0; rb < 2; rb++) {
        int m0 = bm + 32*wr + 16*rb + g;
        #pragma unroll
        for (int nb = 0; nb < (DUAL ? 2 : 4); nb++) {
            if (!DUAL) {
                int col = bn + 32*wc4 + 8*nb + 2*t;
                float2 v0 = make_float2(accg[rb][nb][0], accg[rb][nb][1]);
                float2 v1 = make_float2(accg[rb][nb][2], accg[rb][nb][3]);
                if (EPI == 0) {
                    if (bias != nullptr) {
                        float2 bv = *(const float2*)(bias + col);
                        v0.x += bv.x; v0.y += bv.y; v1.x += bv.x; v1.y += bv.y;
                    }
                } else if (EPI == 1) {
                    float2 aa = *(const float2*)(g_bna + col);
                    float2 ab = *(const float2*)(g_bnb + col);
                    float2 dv = *(const float2*)(dvec + col);
                    float2 h0 = *(const float2*)(auxf + (size_t)m0*DE + col);
                    float2 h1 = *(const float2*)(auxf + (size_t)(m0+8)*DE + col);
                    v0.x += fmaf(aa.x, h0.x, ab.x)*dv.x;
                    v0.y += fmaf(aa.y, h0.y, ab.y)*dv.y;
                    v1.x += fmaf(aa.x, h1.x, ab.x)*dv.x;
                    v1.y += fmaf(aa.y, h1.y, ab.y)*dv.y;
                } else if (EPI == 2) {
                    float2 bv = *(const float2*)(bias + col);
                    float2 y0 = *(const float2*)(auxf + (size_t)m0*OUTW + col);
                    float2 y1 = *(const float2*)(auxf + (size_t)(m0+8)*OUTW + col);
                    v0.x += bv.x + y0.x; v0.y += bv.y + y0.y;
                    v1.x += bv.x + y1.x; v1.y += bv.y + y1.y;
                }
                if (STATS) {
                    cs0[nb] += v0.x + v1.x;
                    cs1[nb] += v0.y + v1.y;
                    cq0[nb] += v0.x*v0.x + v1.x*v1.x;
                    cq1[nb] += v0.y*v0.y + v1.y*v1.y;
                }
                if (OUTH) {
                    __half* Ch = (__half*)Cv;
                    *(__half2*)(Ch + (size_t)m0*OUTW + col)     = __floats2half2_rn(v0.x, v0.y);
                    *(__half2*)(Ch + (size_t)(m0+8)*OUTW + col) = __floats2half2_rn(v1.x, v1.y);
                } else {
                    float* Cf = (float*)Cv;
                    *(float2*)(Cf + (size_t)m0*OUTW + col)     = v0;
                    *(float2*)(Cf + (size_t)(m0+8)*OUTW + col) = v1;
                }
            } else {
                int jc = bn + 16*wc4 + 8*nb + 2*t;
                float2 bg = *(const float2*)(bias + jc);
                float2 bs = *(const float2*)(bias + 256 + jc);
                float g0 = accg[rb][nb][0] + bg.x, s0 = accs[rb][nb][0] + bs.x;
                float g1 = accg[rb][nb][1] + bg.y, s1 = accs[rb][nb][1] + bs.y;
                float g2 = accg[rb][nb][2] + bg.x, s2 = accs[rb][nb][2] + bs.x;
                float g3 = accg[rb][nb][3] + bg.y, s3 = accs[rb][nb][3] + bs.y;
                float2 v0, v1;
                v0.x = g0 * (1.f/(1.f + expf(-s0)));
                v0.y = g1 * (1.f/(1.f + expf(-s1)));
                v1.x = g2 * (1.f/(1.f + expf(-s2)));
                v1.y = g3 * (1.f/(1.f + expf(-s3)));
                if (OUTH) {
                    __half* Ch = (__half*)Cv;
                    *(__half2*)(Ch + (size_t)m0*OUTW + jc)     = __floats2half2_rn(v0.x, v0.y);
                    *(__half2*)(Ch + (size_t)(m0+8)*OUTW + jc) = __floats2half2_rn(v1.x, v1.y);
                } else {
                    float* Cf = (float*)Cv;
                    *(float2*)(Cf + (size_t)m0*OUTW + jc)     = v0;
                    *(float2*)(Cf + (size_t)(m0+8)*OUTW + jc) = v1;
                }
            }
        }
    }

    if (STATS && !DUAL) {
        #pragma unroll
        for (int nb = 0; nb < 4; nb++) {
            #pragma unroll
            for (int m = 4; m <= 16; m <<= 1) {
                cs0[nb] += __shfl_xor_sync(0xffffffffu, cs0[nb], m);
                cs1[nb] += __shfl_xor_sync(0xffffffffu, cs1[nb], m);
                cq0[nb] += __shfl_xor_sync(0xffffffffu, cq0[nb], m);
                cq1[nb] += __shfl_xor_sync(0xffffffffu, cq1[nb], m);
            }
        }
        __syncthreads();
        float* spart = (float*)sm;
        if (lane < 4) {
            #pragma unroll
            for (int nb = 0; nb < 4; nb++) {
                int col = 32*wc4 + 8*nb + 2*lane;
                spart[wr*128 + col]           = cs0[nb];
                spart[wr*128 + col + 1]       = cs1[nb];
                spart[512 + wr*128 + col]     = cq0[nb];
                spart[512 + wr*128 + col + 1] = cq1[nb];
            }
        }
        __syncthreads();
        if (tid < 128) {
            float s  = spart[tid] + spart[128+tid] + spart[256+tid] + spart[384+tid];
            float s2 = spart[512+tid] + spart[640+tid] + spart[768+tid] + spart[896+tid];
            g_bnpart[blockIdx.y*(2*DE) + tid]      = s;
            g_bnpart[blockIdx.y*(2*DE) + DE + tid] = s2;
        }
    }
}

// ---------------- LRU scan (fp16 Bu in, in-place fp16 state out) ----------------
__device__ __forceinline__ float2 cstep(float2 lam, float2 s, float2 u) {
    float2 t;
    t.x = fmaf(lam.x, s.x, fmaf(-lam.y, s.y, u.x));
    t.y = fmaf(lam.x, s.y, fmaf( lam.y, s.x, u.y));
    return t;
}
__device__ __forceinline__ float2 ldh2(const uint32_t* p, size_t off) {
    uint32_t r = p[off];
    return __half22float2(*(__half2*)&r);
}
__global__ void scanA_kernel(int blk) {
    int g  = blockIdx.x*256 + threadIdx.x;
    int h  = g & 255;
    int bc = g >> 8;
    int b  = bc >> 4;
    int c  = bc & 15;
    float2 lam = g_lam[blk*HH + h];
    float2 s = make_float2(0.f, 0.f);
    const uint32_t* p = (const uint32_t*)g_bu;
    size_t base = (size_t)(b*TT + c*CLEN)*256 + h;
    #pragma unroll 8
    for (int i = 0; i < CLEN; i++)
        s = cstep(lam, s, ldh2(p, base + (size_t)i*256));
    g_carry[bc*HH + h] = s;
}
__global__ void scanB_kernel(int blk) {
    int b = blockIdx.x;
    int h = threadIdx.x;
    float2 lam = g_lam[blk*HH + h];
    float2 lp = lam;
    #pragma unroll
    for (int i = 0; i < 8; i++) {
        float2 t;
        t.x = lp.x*lp.x - lp.y*lp.y;
        t.y = 2.f*lp.x*lp.y;
        lp = t;
    }
    float2 s = make_float2(0.f, 0.f);
    for (int c = 0; c < NCH; c++) {
        g_inc[(b*NCH + c)*HH + h] = s;
        float2 cr = g_carry[(b*NCH + c)*HH + h];
        s = cstep(lp, s, cr);
    }
}
__global__ void scanC_kernel(int blk) {
    int g  = blockIdx.x*256 + threadIdx.x;
    int h  = g & 255;
    int bc = g >> 8;
    int b  = bc >> 4;
    int c  = bc & 15;
    float2 lam = g_lam[blk*HH + h];
    float2 s = g_inc[bc*HH + h];
    uint32_t* p = (uint32_t*)g_bu;
    size_t base = (size_t)(b*TT + c*CLEN)*256 + h;
    #pragma unroll 8
    for (int i = 0; i < CLEN; i++) {
        size_t off = base + (size_t)i*256;
        s = cstep(lam, s, ldh2(p, off));
        __half2 sv = __floats2half2_rn(s.x, s.y);
        p[off] = *(uint32_t*)&sv;
    }
}

// ---------------- final: mean-pool + head ----------------
__global__ void final_kernel(const float* __restrict__ h,
                             const float* __restrict__ Wout,
                             const float* __restrict__ bout,
                             float* __restrict__ out) {
    __shared__ float pooled[DE];
    int b = blockIdx.x;
    int f = threadIdx.x;
    float s = 0.f;
    const float* p = h + (size_t)b*TT*DE + f;
    #pragma unroll 4
    for (int t = 0; t < TT; t++) s += p[(size_t)t*DE];
    pooled[f] = s * (1.f/TT);
    __syncthreads();
    if (f < OD) {
        float acc = bout[f];
        #pragma unroll 4
        for (int d = 0; d < DE; d++) acc = fmaf(pooled[d], Wout[d*OD + f], acc);
        out[b*OD + f] = acc;
    }
}

// ---------------- launch ----------------
extern "C" void kernel_launch(void* const* d_in, const int* in_sizes, int n_in,
                              void* d_out, int out_size) {
    const float* x         = (const float*)d_in[0];
    const float* nu_log    = (const float*)d_in[1];
    const float* theta_log = (const float*)d_in[2];
    const float* B_re      = (const float*)d_in[3];
    const float* B_im      = (const float*)d_in[4];
    const float* C_re      = (const float*)d_in[5];
    const float* C_im      = (const float*)d_in[6];
    const float* D_lru     = (const float*)d_in[7];
    const float* W1        = (const float*)d_in[8];
    const float* b1        = (const float*)d_in[9];
    const float* W2        = (const float*)d_in[10];
    const float* b2        = (const float*)d_in[11];
    const float* bn_scale  = (const float*)d_in[12];
    const float* bn_bias   = (const float*)d_in[13];
    const float* W_enc     = (const float*)d_in[14];
    const float* b_enc     = (const float*)d_in[15];
    const float* W_out     = (const float*)d_in[16];
    const float* b_out     = (const float*)d_in[17];
    float* out = (float*)d_out;

    float *yenc, *h;
    __half *bu, *lru, *glu, *wch, *wcl, *w1h, *w1l, *w2h, *w2l;
    __nv_bfloat16 *wbh, *wbl, *weh, *wel;
    cudaGetSymbolAddress((void**)&yenc, g_yenc);
    cudaGetSymbolAddress((void**)&h,    g_h);
    cudaGetSymbolAddress((void**)&bu,   g_bu);
    cudaGetSymbolAddress((void**)&lru,  g_lru);
    cudaGetSymbolAddress((void**)&glu,  g_glu);
    cudaGetSymbolAddress((void**)&wbh,  g_WBh);
    cudaGetSymbolAddress((void**)&wbl,  g_WBl);
    cudaGetSymbolAddress((void**)&weh,  g_WEh);
    cudaGetSymbolAddress((void**)&wel,  g_WEl);
    cudaGetSymbolAddress((void**)&wch,  g_WCh);
    cudaGetSymbolAddress((void**)&wcl,  g_WCl);
    cudaGetSymbolAddress((void**)&w1h,  g_W1h);
    cudaGetSymbolAddress((void**)&w1l,  g_W1l);
    cudaGetSymbolAddress((void**)&w2h,  g_W2h);
    cudaGetSymbolAddress((void**)&w2l,  g_W2l);

    cudaFuncSetAttribute(gemm_mma<64, 128, 0, 0, 0, 0, 0, 1>,  cudaFuncAttributeMaxDynamicSharedMemorySize, SMEM_F32A);
    cudaFuncSetAttribute(gemm_mma<128, 512, 1, 0, 0, 0, 1, 0>, cudaFuncAttributeMaxDynamicSharedMemorySize, SMEM_F32A);
    cudaFuncSetAttribute(gemm_mma<512, 128, 0, 1, 0, 1, 1, 0>, cudaFuncAttributeMaxDynamicSharedMemorySize, SMEM_F16A);
    cudaFuncSetAttribute(gemm_mma<128, 256, 0, 0, 1, 1, 1, 0>, cudaFuncAttributeMaxDynamicSharedMemorySize, SMEM_F16A);
    cudaFuncSetAttribute(gemm_mma<256, 128, 0, 2, 0, 1, 0, 1>, cudaFuncAttributeMaxDynamicSharedMemorySize, SMEM_F16A);

    prep_lam_kernel<<<NBLKS, HH>>>(nu_log, theta_log);
    prep_WE_kernel<<<(DE*TSD + 255)/256, 256>>>(W_enc);
    prep_WB_kernel<<<(NBLKS*512*DE + 255)/256, 256>>>(B_re, B_im);

    // encoder: yenc = x @ W_enc + b_enc  (+ BN partials for block 0)
    gemm_mma<64, 128, 0, 0, 0, 0, 0, 1><<<dim3(1, NR/128), NTHR, SMEM_F32A>>>(
        x, weh, wel, yenc, b_enc, nullptr, nullptr);

    prep_WC_kernel<<<(NBLKS*DE*512 + 255)/256, 256>>>(C_re, C_im);
    prep_W1_kernel<<<(NBLKS*512*DE + 255)/256, 256>>>(W1);
    prep_W2_kernel<<<(NBLKS*DE*256 + 255)/256, 256>>>(W2);

    const float* hp = yenc;
    for (int blk = 0; blk < NBLKS; blk++) {
        bn_stats2_kernel<<<1, 512>>>(bn_scale + blk*DE, bn_bias + blk*DE);

        // Bu = BN(h) @ WB  (fp16 output)
        gemm_mma<128, 512, 1, 0, 0, 0, 1, 0><<<dim3(4, NR/128), NTHR, SMEM_F32A>>>(
            hp, wbh + (size_t)blk*512*128, wbl + (size_t)blk*512*128,
            bu, nullptr, nullptr, nullptr);

        scanA_kernel<<<NR/256, 256>>>(blk);
        scanB_kernel<<<BB, HH>>>(blk);
        scanC_kernel<<<NR/256, 256>>>(blk);

        // lru = Re(state @ C) + BN(h) * D   (fp16 A, fp16-split weights, 2-term)
        gemm_mma<512, 128, 0, 1, 0, 1, 1, 0><<<dim3(1, NR/128), NTHR, SMEM_F16A>>>(
            bu, wch + (size_t)blk*128*512, wcl + (size_t)blk*128*512,
            lru, nullptr, hp, D_lru + blk*DE);

        // glu = GLU(lru @ W1 + b1)   (fp16 A, 2-term, fp16 out)
        gemm_mma<128, 256, 0, 0, 1, 1, 1, 0><<<dim3(4, NR/128), NTHR, SMEM_F16A>>>(
            lru, w1h + (size_t)blk*512*128, w1l + (size_t)blk*512*128,
            glu, b1 + (size_t)blk*LDF, nullptr, nullptr);

        // h = glu @ W2 + b2 + yenc  (fp16 A, 2-term; + BN partials for next block)
        gemm_mma<256, 128, 0, 2, 0, 1, 0, 1><<<dim3(1, NR/128), NTHR, SMEM_F16A>>>(
            glu, w2h + (size_t)blk*128*256, w2l + (size_t)blk*128*256,
            h, b2 + blk*DE, yenc, nullptr);

        hp = h;
    }

    final_kernel<<<BB, DE>>>(hp, W_out, b_out, out);
}

// round 11
// speedup vs baseline: 1.9436x; 1.0512x over previous
#include <cuda_runtime.h>
#include <cuda_bf16.h>
#include <cuda_fp16.h>
#include <math.h>
#include <stdint.h>

// ---------------- problem constants ----------------
#define BB   16
#define TT   4096
#define NR   (BB*TT)
#define TSD  64
#define DE   128
#define HH   256
#define LDF  512
#define LDH  256
#define OD   10
#define NBLKS 6
#define EPSV 1e-5f
#define NCH  16
#define CLEN 256

// ---------------- scratch ----------------
static __device__ __align__(256) float g_yenc[(size_t)NR*DE];
static __device__ __align__(256) float g_h   [(size_t)NR*DE];
static __device__ __align__(256) __half g_lru[(size_t)NR*DE];
static __device__ __align__(256) __half g_glu[(size_t)NR*LDH];
static __device__ __align__(256) __half g_bu [(size_t)NR*512];   // Bu -> state (in place), fp16
static __device__ float2 g_lam [NBLKS*HH];
static __device__ float  g_gamma[NBLKS*HH];
static __device__ float  g_bnpart[512*2*DE];
static __device__ float  g_bna[DE];
static __device__ float  g_bnb[DE];
static __device__ float2 g_carry[BB*NCH*HH];
static __device__ float2 g_inc  [BB*NCH*HH];

// weights: bf16 split for fp32-A GEMMs (encoder, Bu); fp16 split for fp16-A GEMMs
static __device__ __align__(256) __nv_bfloat16 g_WBh[(size_t)NBLKS*512*128];
static __device__ __align__(256) __nv_bfloat16 g_WBl[(size_t)NBLKS*512*128];
static __device__ __align__(256) __nv_bfloat16 g_WEh[128*64];
static __device__ __align__(256) __nv_bfloat16 g_WEl[128*64];
static __device__ __align__(256) __half g_WCh[(size_t)NBLKS*128*512];
static __device__ __align__(256) __half g_WCl[(size_t)NBLKS*128*512];
static __device__ __align__(256) __half g_W1h[(size_t)NBLKS*512*128];
static __device__ __align__(256) __half g_W1l[(size_t)NBLKS*512*128];
static __device__ __align__(256) __half g_W2h[(size_t)NBLKS*128*256];
static __device__ __align__(256) __half g_W2l[(size_t)NBLKS*128*256];

// ---------------- helpers ----------------
__device__ __forceinline__ uint32_t smem_u32(const void* p) {
    uint32_t a;
    asm("{ .reg .u64 t; cvta.to.shared.u64 t, %1; cvt.u32.u64 %0, t; }" : "=r"(a) : "l"(p));
    return a;
}
__device__ __forceinline__ void cp16(uint32_t dst, const void* src) {
    asm volatile("cp.async.cg.shared.global [%0], [%1], 16;" :: "r"(dst), "l"(src));
}
#define CP_COMMIT() asm volatile("cp.async.commit_group;" ::: "memory")
#define CP_WAIT0()  asm volatile("cp.async.wait_group 0;" ::: "memory")

#define MMA_BF16(d, a, b0, b1) \
    asm volatile("mma.sync.aligned.m16n8k16.row.col.f32.bf16.bf16.f32 " \
        "{%0,%1,%2,%3}, {%4,%5,%6,%7}, {%8,%9}, {%0,%1,%2,%3};" \
        : "+f"((d)[0]), "+f"((d)[1]), "+f"((d)[2]), "+f"((d)[3]) \
        : "r"((a)[0]), "r"((a)[1]), "r"((a)[2]), "r"((a)[3]), "r"(b0), "r"(b1))

#define MMA_F16(d, a, b0, b1) \
    asm volatile("mma.sync.aligned.m16n8k16.row.col.f32.f16.f16.f32 " \
        "{%0,%1,%2,%3}, {%4,%5,%6,%7}, {%8,%9}, {%0,%1,%2,%3};" \
        : "+f"((d)[0]), "+f"((d)[1]), "+f"((d)[2]), "+f"((d)[3]) \
        : "r"((a)[0]), "r"((a)[1]), "r"((a)[2]), "r"((a)[3]), "r"(b0), "r"(b1))

#define LDSM4(r, addr) \
    asm volatile("ldmatrix.sync.aligned.m8n8.x4.shared.b16 {%0,%1,%2,%3}, [%4];" \
        : "=r"((r)[0]), "=r"((r)[1]), "=r"((r)[2]), "=r"((r)[3]) : "r"(addr))

__device__ __forceinline__ void split_store(float v, __nv_bfloat16* hi, __nv_bfloat16* lo, size_t i) {
    __nv_bfloat16 h = __float2bfloat16(v);
    hi[i] = h;
    lo[i] = __float2bfloat16(v - __bfloat162float(h));
}
__device__ __forceinline__ void split_store_h(float v, __half* hi, __half* lo, size_t i) {
    __half h = __float2half_rn(v);
    hi[i] = h;
    lo[i] = __float2half_rn(v - __half2float(h));
}

// ---------------- prep ----------------
__global__ void prep_lam_kernel(const float* __restrict__ nu_log,
                                const float* __restrict__ theta_log) {
    int blk = blockIdx.x;
    int h   = threadIdx.x;
    float nu = nu_log[blk*HH + h];
    float th = theta_log[blk*HH + h];
    float r  = expf(-expf(nu));
    float ang = expf(th);
    float sn, cs;
    sincosf(ang, &sn, &cs);
    float2 lam; lam.x = r*cs; lam.y = r*sn;
    g_lam[blk*HH + h]   = lam;
    g_gamma[blk*HH + h] = sqrtf(fmaxf(1.f - r*r, 1e-8f));
}
__global__ void prep_WB_kernel(const float* __restrict__ Bre, const float* __restrict__ Bim) {
    int idx = blockIdx.x*256 + threadIdx.x;
    if (idx >= NBLKS*512*DE) return;
    int k = idx & 127;
    int n = (idx >> 7) & 511;
    int blk = idx >> 16;
    int h = n >> 1;
    float g = g_gamma[blk*HH + h];
    float v = ((n & 1) ? Bim : Bre)[((size_t)blk*HH + h)*DE + k] * g;
    split_store(v, g_WBh, g_WBl, idx);
}
__global__ void prep_WC_kernel(const float* __restrict__ Cre, const float* __restrict__ Cim) {
    int idx = blockIdx.x*256 + threadIdx.x;
    if (idx >= NBLKS*DE*512) return;
    int k = idx & 511;
    int n = (idx >> 9) & 127;
    int blk = idx >> 16;
    int h = k >> 1;
    float v = (k & 1) ? -Cim[((size_t)blk*DE + n)*HH + h] : Cre[((size_t)blk*DE + n)*HH + h];
    split_store_h(v, g_WCh, g_WCl, idx);
}
__global__ void prep_W1_kernel(const float* __restrict__ W1) {
    int idx = blockIdx.x*256 + threadIdx.x;
    if (idx >= NBLKS*512*DE) return;
    int k = idx & 127;
    int n = (idx >> 7) & 511;
    int blk = idx >> 16;
    split_store_h(W1[((size_t)blk*DE + k)*LDF + n], g_W1h, g_W1l, idx);
}
__global__ void prep_W2_kernel(const float* __restrict__ W2) {
    int idx = blockIdx.x*256 + threadIdx.x;
    if (idx >= NBLKS*DE*256) return;
    int k = idx & 255;
    int n = (idx >> 8) & 127;
    int blk = idx >> 15;
    split_store_h(W2[((size_t)blk*LDH + k)*DE + n], g_W2h, g_W2l, idx);
}
__global__ void prep_WE_kernel(const float* __restrict__ We) {
    int idx = blockIdx.x*256 + threadIdx.x;
    if (idx >= DE*TSD) return;
    int k = idx & 63;
    int n = idx >> 6;
    split_store(We[(size_t)k*DE + n], g_WEh, g_WEl, idx);
}

// ---------------- batchnorm stage-2 (parallel) ----------------
__global__ void bn_stats2_kernel(const float* __restrict__ scale,
                                 const float* __restrict__ bias) {
    __shared__ float ss[512], sq[512];
    int tid = threadIdx.x;
    int f = tid & 127;
    int grp = tid >> 7;
    float s = 0.f, s2 = 0.f;
    for (int i = grp; i < 512; i += 4) {
        s  += g_bnpart[i*(2*DE) + f];
        s2 += g_bnpart[i*(2*DE) + DE + f];
    }
    ss[tid] = s;
    sq[tid] = s2;
    __syncthreads();
    if (tid < 128) {
        s  = ss[tid] + ss[128+tid] + ss[256+tid] + ss[384+tid];
        s2 = sq[tid] + sq[128+tid] + sq[256+tid] + sq[384+tid];
        float mean = s * (1.f/NR);
        float var  = s2 * (1.f/NR) - mean*mean;
        float a = scale[tid] * rsqrtf(var + EPSV);
        g_bna[tid] = a;
        g_bnb[tid] = fmaf(-mean, a, bias[tid]);
    }
}

// ---------------- GEMM: 512 threads, 16 warps (4x4), variable N tile ----------------
// NBT = n8-tiles per warp. non-dual: CTA covers 32*NBT cols. dual: 32*NBT gate cols (+ sig).
// AF16=0: A fp32 reg-staged -> bf16 split (3-term, MODE_A = BN affine). B = bf16 planes.
// AF16=1: A fp16 via cp.async; B = fp16-split weights; 2-term fp16 MMA.
// EPI: 0 +bias?; 1 cproj; 2 +bias+residual. DUAL: fused GLU. OUTH: fp16 out.
// STATS: per-CTA BN partials (grid.x must be 1, NBT==4, !DUAL).
#define PITCH 72
#define UNITE (128*PITCH)
#define NTHR 512

template<int KDIM, int OUTW, int MODE_A, int EPI, int DUAL, int AF16, int OUTH, int STATS, int NBT>
__global__ void __launch_bounds__(NTHR) gemm_mma(
    const void* __restrict__ Av,
    const void* __restrict__ Bhi_, const void* __restrict__ Blo_,
    void* __restrict__ Cv,
    const float* __restrict__ bias,
    const float* __restrict__ auxf,
    const float* __restrict__ dvec)
{
    constexpr int ABUFS = AF16 ? 1 : 2;
    constexpr int BROWS = (DUAL ? 64 : 32) * NBT;
    constexpr int BUNIT = BROWS * PITCH;
    constexpr int O_AH = 0, O_AL = UNITE;          // O_AL unused if AF16
    constexpr int O_BH = ABUFS*UNITE;
    constexpr int O_BL = O_BH + BUNIT;
    constexpr int STAGE = ABUFS*UNITE + 2*BUNIT;
    constexpr int NCHK = KDIM / 64;
    constexpr int CPB_IT = (BROWS*16)/NTHR;        // cp16 per thread for B

    extern __shared__ __nv_bfloat16 sm[];
    const uint32_t smb = smem_u32(sm);
    const int tid  = threadIdx.x;
    const int lane = tid & 31;
    const int wid  = tid >> 5;
    const int wr   = wid & 3;
    const int wc4  = wid >> 2;
    const int g    = lane >> 2;
    const int t    = lane & 3;
    const int bm   = blockIdx.y << 7;
    const int bn   = blockIdx.x * (32*NBT);

    const int aLaneE = (lane & 15)*PITCH + (lane >> 4)*8;
    const int bLaneE = (lane & 7)*PITCH + ((lane >> 4) & 1)*(8*PITCH) + ((lane >> 3) & 1)*8;

    float accg[2][NBT][4];
    float accs[DUAL ? 2 : 1][DUAL ? NBT : 1][4];
    #pragma unroll
    for (int rb = 0; rb < 2; rb++)
        #pragma unroll
        for (int nb = 0; nb < NBT; nb++)
            #pragma unroll
            for (int j = 0; j < 4; j++) {
                accg[rb][nb][j] = 0.f;
                if (DUAL) accs[rb][nb][j] = 0.f;
            }

    float4 areg[4];
    auto loadA = [&](int cc) {
        const float* Af = (const float*)Av;
        #pragma unroll
        for (int i = 0; i < 4; i++) {
            int idx = tid + NTHR*i;
            int row = idx >> 4;
            int col4 = (idx & 15) << 2;
            areg[i] = *(const float4*)(Af + (size_t)(bm + row)*KDIM + cc*64 + col4);
        }
    };
    auto storeA = [&](int cc, int so) {
        #pragma unroll
        for (int i = 0; i < 4; i++) {
            int idx = tid + NTHR*i;
            int row = idx >> 4;
            int col4 = (idx & 15) << 2;
            float4 v = areg[i];
            if (MODE_A) {
                float4 aa = *(const float4*)(g_bna + cc*64 + col4);
                float4 ab = *(const float4*)(g_bnb + cc*64 + col4);
                v.x = fmaf(aa.x, v.x, ab.x);
                v.y = fmaf(aa.y, v.y, ab.y);
                v.z = fmaf(aa.z, v.z, ab.z);
                v.w = fmaf(aa.w, v.w, ab.w);
            }
            __nv_bfloat16 h0 = __float2bfloat16(v.x), h1 = __float2bfloat16(v.y);
            __nv_bfloat16 h2 = __float2bfloat16(v.z), h3 = __float2bfloat16(v.w);
            __nv_bfloat16 l0 = __float2bfloat16(v.x - __bfloat162float(h0));
            __nv_bfloat16 l1 = __float2bfloat16(v.y - __bfloat162float(h1));
            __nv_bfloat16 l2 = __float2bfloat16(v.z - __bfloat162float(h2));
            __nv_bfloat16 l3 = __float2bfloat16(v.w - __bfloat162float(h3));
            uint32_t hu0 = ((uint32_t)__bfloat16_as_ushort(h1) << 16) | __bfloat16_as_ushort(h0);
            uint32_t hu1 = ((uint32_t)__bfloat16_as_ushort(h3) << 16) | __bfloat16_as_ushort(h2);
            uint32_t lu0 = ((uint32_t)__bfloat16_as_ushort(l1) << 16) | __bfloat16_as_ushort(l0);
            uint32_t lu1 = ((uint32_t)__bfloat16_as_ushort(l3) << 16) | __bfloat16_as_ushort(l2);
            int off = row*PITCH + col4;
            *(uint2*)(sm + so + O_AH + off) = make_uint2(hu0, hu1);
            *(uint2*)(sm + so + O_AL + off) = make_uint2(lu0, lu1);
        }
    };
    auto cpA16 = [&](int cc, int so) {
        const __half* Ahalf = (const __half*)Av;
        #pragma unroll
        for (int i = 0; i < 2; i++) {
            int idx = tid + NTHR*i;
            int r = idx >> 3;
            int q = idx & 7;
            cp16(smb + (uint32_t)((so + O_AH + r*PITCH + q*8)*2),
                 Ahalf + (size_t)(bm + r)*KDIM + cc*64 + q*8);
        }
    };
    auto cpB = [&](int cc, int so) {
        const __nv_bfloat16* Bh = (const __nv_bfloat16*)Bhi_;
        const __nv_bfloat16* Bl = (const __nv_bfloat16*)Blo_;
        #pragma unroll
        for (int i = 0; i < CPB_IT; i++) {
            int idx = tid + NTHR*i;
            int pl  = idx / (BROWS*8);
            int rem = idx % (BROWS*8);
            int r   = rem >> 3;
            int q   = rem & 7;
            int rowg = DUAL ? (r < BROWS/2 ? bn + r : bn + 256 + (r - BROWS/2)) : (bn + r);
            const __nv_bfloat16* src = pl ? Bl : Bh;
            cp16(smb + (uint32_t)((so + (pl ? O_BL : O_BH) + r*PITCH + q*8)*2),
                 src + (size_t)rowg*KDIM + cc*64 + q*8);
        }
    };

    // prologue
    if (AF16) cpA16(0, 0); else loadA(0);
    cpB(0, 0);
    CP_COMMIT();
    if (!AF16) {
        storeA(0, 0);
        if (NCHK > 1) loadA(1);
    }

    #pragma unroll 1
    for (int c = 0; c < NCHK; c++) {
        const int so = (c & 1)*STAGE;
        CP_WAIT0();
        __syncthreads();
        if (c + 1 < NCHK) {
            const int nso = ((c+1) & 1)*STAGE;
            cpB(c+1, nso);
            if (AF16) cpA16(c+1, nso);
            CP_COMMIT();
            if (!AF16) {
                storeA(c+1, nso);
                if (c + 2 < NCHK) loadA(c+2);
            }
        }

        #pragma unroll
        for (int kk = 0; kk < 4; kk++) {
            const int kkE = kk*16;
            uint32_t ah[2][4], al[2][4];
            #pragma unroll
            for (int rb = 0; rb < 2; rb++) {
                int abase = so + (32*wr + 16*rb)*PITCH + kkE + aLaneE;
                LDSM4(ah[rb], smb + (uint32_t)((O_AH + abase)*2));
                if (!AF16) LDSM4(al[rb], smb + (uint32_t)((O_AL + abase)*2));
            }
            if (!DUAL) {
                #pragma unroll
                for (int nb2 = 0; nb2 < NBT/2; nb2++) {
                    uint32_t bh[4], bl[4];
                    int bbase = so + (8*NBT*wc4 + 16*nb2)*PITCH + kkE + bLaneE;
                    LDSM4(bh, smb + (uint32_t)((O_BH + bbase)*2));
                    LDSM4(bl, smb + (uint32_t)((O_BL + bbase)*2));
                    #pragma unroll
                    for (int rb = 0; rb < 2; rb++)
                        #pragma unroll
                        for (int j = 0; j < 2; j++) {
                            float* d = accg[rb][2*nb2 + j];
                            if (AF16) {
                                MMA_F16(d, ah[rb], bh[2*j], bh[2*j+1]);
                                MMA_F16(d, ah[rb], bl[2*j], bl[2*j+1]);
                            } else {
                                MMA_BF16(d, ah[rb], bh[2*j], bh[2*j+1]);
                                MMA_BF16(d, al[rb], bh[2*j], bh[2*j+1]);
                                MMA_BF16(d, ah[rb], bl[2*j], bl[2*j+1]);
                            }
                        }
                }
            } else {
                #pragma unroll
                for (int nb2 = 0; nb2 < NBT/2; nb2++) {
                    uint32_t bh[4], bl[4], dh[4], el[4];
                    int bbase = so + (8*NBT*wc4 + 16*nb2)*PITCH + kkE + bLaneE;
                    int sbase = bbase + (32*NBT)*PITCH;
                    LDSM4(bh, smb + (uint32_t)((O_BH + bbase)*2));
                    LDSM4(bl, smb + (uint32_t)((O_BL + bbase)*2));
                    LDSM4(dh, smb + (uint32_t)((O_BH + sbase)*2));
                    LDSM4(el, smb + (uint32_t)((O_BL + sbase)*2));
                    #pragma unroll
                    for (int rb = 0; rb < 2; rb++)
                        #pragma unroll
                        for (int j = 0; j < 2; j++) {
                            float* dg = accg[rb][2*nb2 + j];
                            float* ds = accs[rb][2*nb2 + j];
                            if (AF16) {
                                MMA_F16(dg, ah[rb], bh[2*j], bh[2*j+1]);
                                MMA_F16(dg, ah[rb], bl[2*j], bl[2*j+1]);
                                MMA_F16(ds, ah[rb], dh[2*j], dh[2*j+1]);
                                MMA_F16(ds, ah[rb], el[2*j], el[2*j+1]);
                            } else {
                                MMA_BF16(dg, ah[rb], bh[2*j], bh[2*j+1]);
                                MMA_BF16(dg, al[rb], bh[2*j], bh[2*j+1]);
                                MMA_BF16(dg, ah[rb], bl[2*j], bl[2*j+1]);
                                MMA_BF16(ds, ah[rb], dh[2*j], dh[2*j+1]);
                                MMA_BF16(ds, al[rb], dh[2*j], dh[2*j+1]);
                                MMA_BF16(ds, ah[rb], el[2*j], el[2*j+1]);
                            }
                        }
                }
            }
        }
    }

    // ---- epilogue ----
    float cs0[STATS ? NBT : 1], cs1[STATS ? NBT : 1], cq0[STATS ? NBT : 1], cq1[STATS ? NBT : 1];
    if (STATS) {
        #pragma unroll
        for (int nb = 0; nb < NBT; nb++) { cs0[nb]=0.f; cs1[nb]=0.f; cq0[nb]=0.f; cq1[nb]=0.f; }
    }
    #pragma unroll
    for (int rb = 0; rb < 2; rb++) {
        int m0 = bm + 32*wr + 16*rb + g;
        #pragma unroll
        for (int nb = 0; nb < NBT; nb++) {
            if (!DUAL) {
                int col = bn + 8*NBT*wc4 + 8*nb + 2*t;
                float2 v0 = make_float2(accg[rb][nb][0], accg[rb][nb][1]);
                float2 v1 = make_float2(accg[rb][nb][2], accg[rb][nb][3]);
                if (EPI == 0) {
                    if (bias != nullptr) {
                        float2 bv = *(const float2*)(bias + col);
                        v0.x += bv.x; v0.y += bv.y; v1.x += bv.x; v1.y += bv.y;
                    }
                } else if (EPI == 1) {
                    float2 aa = *(const float2*)(g_bna + col);
                    float2 ab = *(const float2*)(g_bnb + col);
                    float2 dv = *(const float2*)(dvec + col);
                    float2 h0 = *(const float2*)(auxf + (size_t)m0*DE + col);
                    float2 h1 = *(const float2*)(auxf + (size_t)(m0+8)*DE + col);
                    v0.x += fmaf(aa.x, h0.x, ab.x)*dv.x;
                    v0.y += fmaf(aa.y, h0.y, ab.y)*dv.y;
                    v1.x += fmaf(aa.x, h1.x, ab.x)*dv.x;
                    v1.y += fmaf(aa.y, h1.y, ab.y)*dv.y;
                } else if (EPI == 2) {
                    float2 bv = *(const float2*)(bias + col);
                    float2 y0 = *(const float2*)(auxf + (size_t)m0*OUTW + col);
                    float2 y1 = *(const float2*)(auxf + (size_t)(m0+8)*OUTW + col);
                    v0.x += bv.x + y0.x; v0.y += bv.y + y0.y;
                    v1.x += bv.x + y1.x; v1.y += bv.y + y1.y;
                }
                if (STATS) {
                    cs0[nb] += v0.x + v1.x;
                    cs1[nb] += v0.y + v1.y;
                    cq0[nb] += v0.x*v0.x + v1.x*v1.x;
                    cq1[nb] += v0.y*v0.y + v1.y*v1.y;
                }
                if (OUTH) {
                    __half* Ch = (__half*)Cv;
                    *(__half2*)(Ch + (size_t)m0*OUTW + col)     = __floats2half2_rn(v0.x, v0.y);
                    *(__half2*)(Ch + (size_t)(m0+8)*OUTW + col) = __floats2half2_rn(v1.x, v1.y);
                } else {
                    float* Cf = (float*)Cv;
                    *(float2*)(Cf + (size_t)m0*OUTW + col)     = v0;
                    *(float2*)(Cf + (size_t)(m0+8)*OUTW + col) = v1;
                }
            } else {
                int jc = bn + 8*NBT*wc4 + 8*nb + 2*t;
                float2 bg = *(const float2*)(bias + jc);
                float2 bs = *(const float2*)(bias + 256 + jc);
                float g0 = accg[rb][nb][0] + bg.x, s0 = accs[rb][nb][0] + bs.x;
                float g1 = accg[rb][nb][1] + bg.y, s1 = accs[rb][nb][1] + bs.y;
                float g2 = accg[rb][nb][2] + bg.x, s2 = accs[rb][nb][2] + bs.x;
                float g3 = accg[rb][nb][3] + bg.y, s3 = accs[rb][nb][3] + bs.y;
                float2 v0, v1;
                v0.x = g0 * (1.f/(1.f + expf(-s0)));
                v0.y = g1 * (1.f/(1.f + expf(-s1)));
                v1.x = g2 * (1.f/(1.f + expf(-s2)));
                v1.y = g3 * (1.f/(1.f + expf(-s3)));
                if (OUTH) {
                    __half* Ch = (__half*)Cv;
                    *(__half2*)(Ch + (size_t)m0*OUTW + jc)     = __floats2half2_rn(v0.x, v0.y);
                    *(__half2*)(Ch + (size_t)(m0+8)*OUTW + jc) = __floats2half2_rn(v1.x, v1.y);
                } else {
                    float* Cf = (float*)Cv;
                    *(float2*)(Cf + (size_t)m0*OUTW + jc)     = v0;
                    *(float2*)(Cf + (size_t)(m0+8)*OUTW + jc) = v1;
                }
            }
        }
    }

    if (STATS && !DUAL) {
        #pragma unroll
        for (int nb = 0; nb < NBT; nb++) {
            #pragma unroll
            for (int m = 4; m <= 16; m <<= 1) {
                cs0[nb] += __shfl_xor_sync(0xffffffffu, cs0[nb], m);
                cs1[nb] += __shfl_xor_sync(0xffffffffu, cs1[nb], m);
                cq0[nb] += __shfl_xor_sync(0xffffffffu, cq0[nb], m);
                cq1[nb] += __shfl_xor_sync(0xffffffffu, cq1[nb], m);
            }
        }
        __syncthreads();
        float* spart = (float*)sm;
        if (lane < 4) {
            #pragma unroll
            for (int nb = 0; nb < NBT; nb++) {
                int col = 8*NBT*wc4 + 8*nb + 2*lane;
                spart[wr*128 + col]           = cs0[nb];
                spart[wr*128 + col + 1]       = cs1[nb];
                spart[512 + wr*128 + col]     = cq0[nb];
                spart[512 + wr*128 + col + 1] = cq1[nb];
            }
        }
        __syncthreads();
        if (tid < 128) {
            float s  = spart[tid] + spart[128+tid] + spart[256+tid] + spart[384+tid];
            float s2 = spart[512+tid] + spart[640+tid] + spart[768+tid] + spart[896+tid];
            g_bnpart[blockIdx.y*(2*DE) + tid]      = s;
            g_bnpart[blockIdx.y*(2*DE) + DE + tid] = s2;
        }
    }
}

// ---------------- LRU scan (fp16 Bu in, in-place fp16 state out) ----------------
__device__ __forceinline__ float2 cstep(float2 lam, float2 s, float2 u) {
    float2 t;
    t.x = fmaf(lam.x, s.x, fmaf(-lam.y, s.y, u.x));
    t.y = fmaf(lam.x, s.y, fmaf( lam.y, s.x, u.y));
    return t;
}
__device__ __forceinline__ float2 ldh2(const uint32_t* p, size_t off) {
    uint32_t r = p[off];
    return __half22float2(*(__half2*)&r);
}
__global__ void scanA_kernel(int blk) {
    int g  = blockIdx.x*256 + threadIdx.x;
    int h  = g & 255;
    int bc = g >> 8;
    int b  = bc >> 4;
    int c  = bc & 15;
    float2 lam = g_lam[blk*HH + h];
    float2 s = make_float2(0.f, 0.f);
    const uint32_t* p = (const uint32_t*)g_bu;
    size_t base = (size_t)(b*TT + c*CLEN)*256 + h;
    #pragma unroll 8
    for (int i = 0; i < CLEN; i++)
        s = cstep(lam, s, ldh2(p, base + (size_t)i*256));
    g_carry[bc*HH + h] = s;
}
__global__ void scanB_kernel(int blk) {
    int b = blockIdx.x;
    int h = threadIdx.x;
    float2 lam = g_lam[blk*HH + h];
    float2 lp = lam;
    #pragma unroll
    for (int i = 0; i < 8; i++) {
        float2 t;
        t.x = lp.x*lp.x - lp.y*lp.y;
        t.y = 2.f*lp.x*lp.y;
        lp = t;
    }
    float2 s = make_float2(0.f, 0.f);
    for (int c = 0; c < NCH; c++) {
        g_inc[(b*NCH + c)*HH + h] = s;
        float2 cr = g_carry[(b*NCH + c)*HH + h];
        s = cstep(lp, s, cr);
    }
}
__global__ void scanC_kernel(int blk) {
    int g  = blockIdx.x*256 + threadIdx.x;
    int h  = g & 255;
    int bc = g >> 8;
    int b  = bc >> 4;
    int c  = bc & 15;
    float2 lam = g_lam[blk*HH + h];
    float2 s = g_inc[bc*HH + h];
    uint32_t* p = (uint32_t*)g_bu;
    size_t base = (size_t)(b*TT + c*CLEN)*256 + h;
    #pragma unroll 8
    for (int i = 0; i < CLEN; i++) {
        size_t off = base + (size_t)i*256;
        s = cstep(lam, s, ldh2(p, off));
        __half2 sv = __floats2half2_rn(s.x, s.y);
        p[off] = *(uint32_t*)&sv;
    }
}

// ---------------- final: mean-pool + head ----------------
__global__ void final_kernel(const float* __restrict__ h,
                             const float* __restrict__ Wout,
                             const float* __restrict__ bout,
                             float* __restrict__ out) {
    __shared__ float pooled[DE];
    int b = blockIdx.x;
    int f = threadIdx.x;
    float s = 0.f;
    const float* p = h + (size_t)b*TT*DE + f;
    #pragma unroll 4
    for (int t = 0; t < TT; t++) s += p[(size_t)t*DE];
    pooled[f] = s * (1.f/TT);
    __syncthreads();
    if (f < OD) {
        float acc = bout[f];
        #pragma unroll 4
        for (int d = 0; d < DE; d++) acc = fmaf(pooled[d], Wout[d*OD + f], acc);
        out[b*OD + f] = acc;
    }
}

// ---------------- launch ----------------
#define SMEM_ENC  147456   // f32A, NBT=4
#define SMEM_BU   221184   // f32A, NBT=8
#define SMEM_F16N4 110592  // f16A, NBT=4
#define SMEM_GLU  184320   // f16A, DUAL NBT=4

extern "C" void kernel_launch(void* const* d_in, const int* in_sizes, int n_in,
                              void* d_out, int out_size) {
    const float* x         = (const float*)d_in[0];
    const float* nu_log    = (const float*)d_in[1];
    const float* theta_log = (const float*)d_in[2];
    const float* B_re      = (const float*)d_in[3];
    const float* B_im      = (const float*)d_in[4];
    const float* C_re      = (const float*)d_in[5];
    const float* C_im      = (const float*)d_in[6];
    const float* D_lru     = (const float*)d_in[7];
    const float* W1        = (const float*)d_in[8];
    const float* b1        = (const float*)d_in[9];
    const float* W2        = (const float*)d_in[10];
    const float* b2        = (const float*)d_in[11];
    const float* bn_scale  = (const float*)d_in[12];
    const float* bn_bias   = (const float*)d_in[13];
    const float* W_enc     = (const float*)d_in[14];
    const float* b_enc     = (const float*)d_in[15];
    const float* W_out     = (const float*)d_in[16];
    const float* b_out     = (const float*)d_in[17];
    float* out = (float*)d_out;

    float *yenc, *h;
    __half *bu, *lru, *glu, *wch, *wcl, *w1h, *w1l, *w2h, *w2l;
    __nv_bfloat16 *wbh, *wbl, *weh, *wel;
    cudaGetSymbolAddress((void**)&yenc, g_yenc);
    cudaGetSymbolAddress((void**)&h,    g_h);
    cudaGetSymbolAddress((void**)&bu,   g_bu);
    cudaGetSymbolAddress((void**)&lru,  g_lru);
    cudaGetSymbolAddress((void**)&glu,  g_glu);
    cudaGetSymbolAddress((void**)&wbh,  g_WBh);
    cudaGetSymbolAddress((void**)&wbl,  g_WBl);
    cudaGetSymbolAddress((void**)&weh,  g_WEh);
    cudaGetSymbolAddress((void**)&wel,  g_WEl);
    cudaGetSymbolAddress((void**)&wch,  g_WCh);
    cudaGetSymbolAddress((void**)&wcl,  g_WCl);
    cudaGetSymbolAddress((void**)&w1h,  g_W1h);
    cudaGetSymbolAddress((void**)&w1l,  g_W1l);
    cudaGetSymbolAddress((void**)&w2h,  g_W2h);
    cudaGetSymbolAddress((void**)&w2l,  g_W2l);

    cudaFuncSetAttribute(gemm_mma<64, 128, 0, 0, 0, 0, 0, 1, 4>,  cudaFuncAttributeMaxDynamicSharedMemorySize, SMEM_ENC);
    cudaFuncSetAttribute(gemm_mma<128, 512, 1, 0, 0, 0, 1, 0, 8>, cudaFuncAttributeMaxDynamicSharedMemorySize, SMEM_BU);
    cudaFuncSetAttribute(gemm_mma<512, 128, 0, 1, 0, 1, 1, 0, 4>, cudaFuncAttributeMaxDynamicSharedMemorySize, SMEM_F16N4);
    cudaFuncSetAttribute(gemm_mma<128, 256, 0, 0, 1, 1, 1, 0, 4>, cudaFuncAttributeMaxDynamicSharedMemorySize, SMEM_GLU);
    cudaFuncSetAttribute(gemm_mma<256, 128, 0, 2, 0, 1, 0, 1, 4>, cudaFuncAttributeMaxDynamicSharedMemorySize, SMEM_F16N4);

    prep_lam_kernel<<<NBLKS, HH>>>(nu_log, theta_log);
    prep_WE_kernel<<<(DE*TSD + 255)/256, 256>>>(W_enc);
    prep_WB_kernel<<<(NBLKS*512*DE + 255)/256, 256>>>(B_re, B_im);

    // encoder: yenc = x @ W_enc + b_enc  (+ BN partials for block 0)
    gemm_mma<64, 128, 0, 0, 0, 0, 0, 1, 4><<<dim3(1, NR/128), NTHR, SMEM_ENC>>>(
        x, weh, wel, yenc, b_enc, nullptr, nullptr);

    prep_WC_kernel<<<(NBLKS*DE*512 + 255)/256, 256>>>(C_re, C_im);
    prep_W1_kernel<<<(NBLKS*512*DE + 255)/256, 256>>>(W1);
    prep_W2_kernel<<<(NBLKS*DE*256 + 255)/256, 256>>>(W2);

    const float* hp = yenc;
    for (int blk = 0; blk < NBLKS; blk++) {
        bn_stats2_kernel<<<1, 512>>>(bn_scale + blk*DE, bn_bias + blk*DE);

        // Bu = BN(h) @ WB  (fp16 output; 256-wide tiles)
        gemm_mma<128, 512, 1, 0, 0, 0, 1, 0, 8><<<dim3(2, NR/128), NTHR, SMEM_BU>>>(
            hp, wbh + (size_t)blk*512*128, wbl + (size_t)blk*512*128,
            bu, nullptr, nullptr, nullptr);

        scanA_kernel<<<NR/256, 256>>>(blk);
        scanB_kernel<<<BB, HH>>>(blk);
        scanC_kernel<<<NR/256, 256>>>(blk);

        // lru = Re(state @ C) + BN(h) * D
        gemm_mma<512, 128, 0, 1, 0, 1, 1, 0, 4><<<dim3(1, NR/128), NTHR, SMEM_F16N4>>>(
            bu, wch + (size_t)blk*128*512, wcl + (size_t)blk*128*512,
            lru, nullptr, hp, D_lru + blk*DE);

        // glu = GLU(lru @ W1 + b1)  (128 gate cols per CTA)
        gemm_mma<128, 256, 0, 0, 1, 1, 1, 0, 4><<<dim3(2, NR/128), NTHR, SMEM_GLU>>>(
            lru, w1h + (size_t)blk*512*128, w1l + (size_t)blk*512*128,
            glu, b1 + (size_t)blk*LDF, nullptr, nullptr);

        // h = glu @ W2 + b2 + yenc  (+ BN partials for next block)
        gemm_mma<256, 128, 0, 2, 0, 1, 0, 1, 4><<<dim3(1, NR/128), NTHR, SMEM_F16N4>>>(
            glu, w2h + (size_t)blk*128*256, w2l + (size_t)blk*128*256,
            h, b2 + blk*DE, yenc, nullptr);

        hp = h;
    }

    final_kernel<<<BB, DE>>>(hp, W_out, b_out, out);
}

// round 12
// speedup vs baseline: 2.0443x; 1.0518x over previous
#include <cuda_runtime.h>
#include <cuda_bf16.h>
#include <cuda_fp16.h>
#include <math.h>
#include <stdint.h>

// ---------------- problem constants ----------------
#define BB   16
#define TT   4096
#define NR   (BB*TT)
#define TSD  64
#define DE   128
#define HH   256
#define LDF  512
#define LDH  256
#define OD   10
#define NBLKS 6
#define EPSV 1e-5f
#define NCH  16
#define CLEN 256

// ---------------- scratch ----------------
static __device__ __align__(256) float  g_yenc[(size_t)NR*DE];  // fp32 residual anchor
static __device__ __align__(256) __half g_h  [(size_t)NR*DE];   // running hidden, fp16
static __device__ __align__(256) __half g_lru[(size_t)NR*DE];
static __device__ __align__(256) __half g_glu[(size_t)NR*LDH];
static __device__ __align__(256) __half g_bu [(size_t)NR*512];  // Bu -> state (in place), fp16
static __device__ float2 g_lam [NBLKS*HH];
static __device__ float  g_gamma[NBLKS*HH];
static __device__ float  g_bnpart[512*2*DE];
static __device__ float  g_bna[DE];
static __device__ float  g_bnb[DE];
static __device__ float  g_bubias[512];
static __device__ float2 g_carry[BB*NCH*HH];
static __device__ float2 g_inc  [BB*NCH*HH];

// weights
static __device__ __align__(256) float  g_WBf[(size_t)NBLKS*512*128]; // gamma-scaled fp32 master
static __device__ __align__(256) __half g_WBfh[512*128];              // per-block BN-folded, fp16 split
static __device__ __align__(256) __half g_WBfl[512*128];
static __device__ __align__(256) __nv_bfloat16 g_WEh[128*64];
static __device__ __align__(256) __nv_bfloat16 g_WEl[128*64];
static __device__ __align__(256) __half g_WCh[(size_t)NBLKS*128*512];
static __device__ __align__(256) __half g_WCl[(size_t)NBLKS*128*512];
static __device__ __align__(256) __half g_W1h[(size_t)NBLKS*512*128];
static __device__ __align__(256) __half g_W1l[(size_t)NBLKS*512*128];
static __device__ __align__(256) __half g_W2h[(size_t)NBLKS*128*256];
static __device__ __align__(256) __half g_W2l[(size_t)NBLKS*128*256];

// ---------------- helpers ----------------
__device__ __forceinline__ uint32_t smem_u32(const void* p) {
    uint32_t a;
    asm("{ .reg .u64 t; cvta.to.shared.u64 t, %1; cvt.u32.u64 %0, t; }" : "=r"(a) : "l"(p));
    return a;
}
__device__ __forceinline__ void cp16(uint32_t dst, const void* src) {
    asm volatile("cp.async.cg.shared.global [%0], [%1], 16;" :: "r"(dst), "l"(src));
}
#define CP_COMMIT() asm volatile("cp.async.commit_group;" ::: "memory")
#define CP_WAIT0()  asm volatile("cp.async.wait_group 0;" ::: "memory")

#define MMA_BF16(d, a, b0, b1) \
    asm volatile("mma.sync.aligned.m16n8k16.row.col.f32.bf16.bf16.f32 " \
        "{%0,%1,%2,%3}, {%4,%5,%6,%7}, {%8,%9}, {%0,%1,%2,%3};" \
        : "+f"((d)[0]), "+f"((d)[1]), "+f"((d)[2]), "+f"((d)[3]) \
        : "r"((a)[0]), "r"((a)[1]), "r"((a)[2]), "r"((a)[3]), "r"(b0), "r"(b1))

#define MMA_F16(d, a, b0, b1) \
    asm volatile("mma.sync.aligned.m16n8k16.row.col.f32.f16.f16.f32 " \
        "{%0,%1,%2,%3}, {%4,%5,%6,%7}, {%8,%9}, {%0,%1,%2,%3};" \
        : "+f"((d)[0]), "+f"((d)[1]), "+f"((d)[2]), "+f"((d)[3]) \
        : "r"((a)[0]), "r"((a)[1]), "r"((a)[2]), "r"((a)[3]), "r"(b0), "r"(b1))

#define LDSM4(r, addr) \
    asm volatile("ldmatrix.sync.aligned.m8n8.x4.shared.b16 {%0,%1,%2,%3}, [%4];" \
        : "=r"((r)[0]), "=r"((r)[1]), "=r"((r)[2]), "=r"((r)[3]) : "r"(addr))

__device__ __forceinline__ void split_store(float v, __nv_bfloat16* hi, __nv_bfloat16* lo, size_t i) {
    __nv_bfloat16 h = __float2bfloat16(v);
    hi[i] = h;
    lo[i] = __float2bfloat16(v - __bfloat162float(h));
}
__device__ __forceinline__ void split_store_h(float v, __half* hi, __half* lo, size_t i) {
    __half h = __float2half_rn(v);
    hi[i] = h;
    lo[i] = __float2half_rn(v - __half2float(h));
}

// ---------------- prep ----------------
__global__ void prep_lam_kernel(const float* __restrict__ nu_log,
                                const float* __restrict__ theta_log) {
    int blk = blockIdx.x;
    int h   = threadIdx.x;
    float nu = nu_log[blk*HH + h];
    float th = theta_log[blk*HH + h];
    float r  = expf(-expf(nu));
    float ang = expf(th);
    float sn, cs;
    sincosf(ang, &sn, &cs);
    float2 lam; lam.x = r*cs; lam.y = r*sn;
    g_lam[blk*HH + h]   = lam;
    g_gamma[blk*HH + h] = sqrtf(fmaxf(1.f - r*r, 1e-8f));
}
__global__ void prep_WBf_kernel(const float* __restrict__ Bre, const float* __restrict__ Bim) {
    int idx = blockIdx.x*256 + threadIdx.x;
    if (idx >= NBLKS*512*DE) return;
    int k = idx & 127;
    int n = (idx >> 7) & 511;
    int blk = idx >> 16;
    int h = n >> 1;
    float g = g_gamma[blk*HH + h];
    g_WBf[idx] = ((n & 1) ? Bim : Bre)[((size_t)blk*HH + h)*DE + k] * g;
}
__global__ void prep_WC_kernel(const float* __restrict__ Cre, const float* __restrict__ Cim) {
    int idx = blockIdx.x*256 + threadIdx.x;
    if (idx >= NBLKS*DE*512) return;
    int k = idx & 511;
    int n = (idx >> 9) & 127;
    int blk = idx >> 16;
    int h = k >> 1;
    float v = (k & 1) ? -Cim[((size_t)blk*DE + n)*HH + h] : Cre[((size_t)blk*DE + n)*HH + h];
    split_store_h(v, g_WCh, g_WCl, idx);
}
__global__ void prep_W1_kernel(const float* __restrict__ W1) {
    int idx = blockIdx.x*256 + threadIdx.x;
    if (idx >= NBLKS*512*DE) return;
    int k = idx & 127;
    int n = (idx >> 7) & 511;
    int blk = idx >> 16;
    split_store_h(W1[((size_t)blk*DE + k)*LDF + n], g_W1h, g_W1l, idx);
}
__global__ void prep_W2_kernel(const float* __restrict__ W2) {
    int idx = blockIdx.x*256 + threadIdx.x;
    if (idx >= NBLKS*DE*256) return;
    int k = idx & 255;
    int n = (idx >> 8) & 127;
    int blk = idx >> 15;
    split_store_h(W2[((size_t)blk*LDH + k)*DE + n], g_W2h, g_W2l, idx);
}
__global__ void prep_WE_kernel(const float* __restrict__ We) {
    int idx = blockIdx.x*256 + threadIdx.x;
    if (idx >= DE*TSD) return;
    int k = idx & 63;
    int n = idx >> 6;
    split_store(We[(size_t)k*DE + n], g_WEh, g_WEl, idx);
}

// ---------------- batchnorm stage-2 + BN fold into Bu weights ----------------
__global__ void bn_stats2_kernel(const float* __restrict__ scale,
                                 const float* __restrict__ bias) {
    __shared__ float ss[512], sq[512];
    int tid = threadIdx.x;
    int f = tid & 127;
    int grp = tid >> 7;
    float s = 0.f, s2 = 0.f;
    for (int i = grp; i < 512; i += 4) {
        s  += g_bnpart[i*(2*DE) + f];
        s2 += g_bnpart[i*(2*DE) + DE + f];
    }
    ss[tid] = s;
    sq[tid] = s2;
    __syncthreads();
    if (tid < 128) {
        s  = ss[tid] + ss[128+tid] + ss[256+tid] + ss[384+tid];
        s2 = sq[tid] + sq[128+tid] + sq[256+tid] + sq[384+tid];
        float mean = s * (1.f/NR);
        float var  = s2 * (1.f/NR) - mean*mean;
        float a = scale[tid] * rsqrtf(var + EPSV);
        g_bna[tid] = a;
        g_bnb[tid] = fmaf(-mean, a, bias[tid]);
    }
}
__global__ void fold_WB_kernel(int blk) {
    int idx = blockIdx.x*256 + threadIdx.x;   // 65536
    int k = idx & 127;
    float v = g_WBf[(size_t)blk*512*128 + idx] * g_bna[k];
    split_store_h(v, g_WBfh, g_WBfl, idx);
}
__global__ void fold_bias_kernel(int blk) {
    int n = threadIdx.x;                      // 512
    const float* w = g_WBf + (size_t)blk*512*128 + (size_t)n*128;
    float s = 0.f;
    #pragma unroll 4
    for (int k = 0; k < 128; k++) s = fmaf(g_bnb[k], w[k], s);
    g_bubias[n] = s;
}

// ---------------- GEMM: 512 threads, 16 warps (4x4), variable N tile ----------------
// AF16=0: A fp32 reg-staged -> bf16 split (3-term). AF16=1: A fp16, 2-term fp16 MMA.
// EPI: 0 +bias?; 1 cproj (+(a*aux+b)*d, aux fp16 if AUXH); 2 +bias+aux residual (fp32).
// OUTH: 0 fp32 out; 1 fp16 out; 2 fp32 out + fp16 copy into g_h.
// STATS: per-CTA BN partials (grid.x==1, NBT==4, !DUAL). NBT: n8-tiles per warp.
#define PITCH 72
#define UNITE (128*PITCH)
#define NTHR 512

template<int KDIM, int OUTW, int MODE_A, int EPI, int DUAL, int AF16, int OUTH, int STATS, int NBT, int AUXH>
__global__ void __launch_bounds__(NTHR) gemm_mma(
    const void* __restrict__ Av,
    const void* __restrict__ Bhi_, const void* __restrict__ Blo_,
    void* __restrict__ Cv,
    const float* __restrict__ bias,
    const void* __restrict__ auxv,
    const float* __restrict__ dvec)
{
    constexpr int ABUFS = AF16 ? 1 : 2;
    constexpr int BROWS = (DUAL ? 64 : 32) * NBT;
    constexpr int BUNIT = BROWS * PITCH;
    constexpr int O_AH = 0, O_AL = UNITE;
    constexpr int O_BH = ABUFS*UNITE;
    constexpr int O_BL = O_BH + BUNIT;
    constexpr int STAGE = ABUFS*UNITE + 2*BUNIT;
    constexpr int NCHK = KDIM / 64;
    constexpr int CPB_IT = (BROWS*16)/NTHR;

    extern __shared__ __nv_bfloat16 sm[];
    const uint32_t smb = smem_u32(sm);
    const int tid  = threadIdx.x;
    const int lane = tid & 31;
    const int wid  = tid >> 5;
    const int wr   = wid & 3;
    const int wc4  = wid >> 2;
    const int g    = lane >> 2;
    const int t    = lane & 3;
    const int bm   = blockIdx.y << 7;
    const int bn   = blockIdx.x * (32*NBT);

    const int aLaneE = (lane & 15)*PITCH + (lane >> 4)*8;
    const int bLaneE = (lane & 7)*PITCH + ((lane >> 4) & 1)*(8*PITCH) + ((lane >> 3) & 1)*8;

    float accg[2][NBT][4];
    float accs[DUAL ? 2 : 1][DUAL ? NBT : 1][4];
    #pragma unroll
    for (int rb = 0; rb < 2; rb++)
        #pragma unroll
        for (int nb = 0; nb < NBT; nb++)
            #pragma unroll
            for (int j = 0; j < 4; j++) {
                accg[rb][nb][j] = 0.f;
                if (DUAL) accs[rb][nb][j] = 0.f;
            }

    float4 areg[4];
    auto loadA = [&](int cc) {
        const float* Af = (const float*)Av;
        #pragma unroll
        for (int i = 0; i < 4; i++) {
            int idx = tid + NTHR*i;
            int row = idx >> 4;
            int col4 = (idx & 15) << 2;
            areg[i] = *(const float4*)(Af + (size_t)(bm + row)*KDIM + cc*64 + col4);
        }
    };
    auto storeA = [&](int cc, int so) {
        #pragma unroll
        for (int i = 0; i < 4; i++) {
            int idx = tid + NTHR*i;
            int row = idx >> 4;
            int col4 = (idx & 15) << 2;
            float4 v = areg[i];
            if (MODE_A) {
                float4 aa = *(const float4*)(g_bna + cc*64 + col4);
                float4 ab = *(const float4*)(g_bnb + cc*64 + col4);
                v.x = fmaf(aa.x, v.x, ab.x);
                v.y = fmaf(aa.y, v.y, ab.y);
                v.z = fmaf(aa.z, v.z, ab.z);
                v.w = fmaf(aa.w, v.w, ab.w);
            }
            __nv_bfloat16 h0 = __float2bfloat16(v.x), h1 = __float2bfloat16(v.y);
            __nv_bfloat16 h2 = __float2bfloat16(v.z), h3 = __float2bfloat16(v.w);
            __nv_bfloat16 l0 = __float2bfloat16(v.x - __bfloat162float(h0));
            __nv_bfloat16 l1 = __float2bfloat16(v.y - __bfloat162float(h1));
            __nv_bfloat16 l2 = __float2bfloat16(v.z - __bfloat162float(h2));
            __nv_bfloat16 l3 = __float2bfloat16(v.w - __bfloat162float(h3));
            uint32_t hu0 = ((uint32_t)__bfloat16_as_ushort(h1) << 16) | __bfloat16_as_ushort(h0);
            uint32_t hu1 = ((uint32_t)__bfloat16_as_ushort(h3) << 16) | __bfloat16_as_ushort(h2);
            uint32_t lu0 = ((uint32_t)__bfloat16_as_ushort(l1) << 16) | __bfloat16_as_ushort(l0);
            uint32_t lu1 = ((uint32_t)__bfloat16_as_ushort(l3) << 16) | __bfloat16_as_ushort(l2);
            int off = row*PITCH + col4;
            *(uint2*)(sm + so + O_AH + off) = make_uint2(hu0, hu1);
            *(uint2*)(sm + so + O_AL + off) = make_uint2(lu0, lu1);
        }
    };
    auto cpA16 = [&](int cc, int so) {
        const __half* Ahalf = (const __half*)Av;
        #pragma unroll
        for (int i = 0; i < 2; i++) {
            int idx = tid + NTHR*i;
            int r = idx >> 3;
            int q = idx & 7;
            cp16(smb + (uint32_t)((so + O_AH + r*PITCH + q*8)*2),
                 Ahalf + (size_t)(bm + r)*KDIM + cc*64 + q*8);
        }
    };
    auto cpB = [&](int cc, int so) {
        const __nv_bfloat16* Bh = (const __nv_bfloat16*)Bhi_;
        const __nv_bfloat16* Bl = (const __nv_bfloat16*)Blo_;
        #pragma unroll
        for (int i = 0; i < CPB_IT; i++) {
            int idx = tid + NTHR*i;
            int pl  = idx / (BROWS*8);
            int rem = idx % (BROWS*8);
            int r   = rem >> 3;
            int q   = rem & 7;
            int rowg = DUAL ? (r < BROWS/2 ? bn + r : bn + 256 + (r - BROWS/2)) : (bn + r);
            const __nv_bfloat16* src = pl ? Bl : Bh;
            cp16(smb + (uint32_t)((so + (pl ? O_BL : O_BH) + r*PITCH + q*8)*2),
                 src + (size_t)rowg*KDIM + cc*64 + q*8);
        }
    };

    // prologue
    if (AF16) cpA16(0, 0); else loadA(0);
    cpB(0, 0);
    CP_COMMIT();
    if (!AF16) {
        storeA(0, 0);
        if (NCHK > 1) loadA(1);
    }

    #pragma unroll 1
    for (int c = 0; c < NCHK; c++) {
        const int so = (c & 1)*STAGE;
        CP_WAIT0();
        __syncthreads();
        if (c + 1 < NCHK) {
            const int nso = ((c+1) & 1)*STAGE;
            cpB(c+1, nso);
            if (AF16) cpA16(c+1, nso);
            CP_COMMIT();
            if (!AF16) {
                storeA(c+1, nso);
                if (c + 2 < NCHK) loadA(c+2);
            }
        }

        #pragma unroll
        for (int kk = 0; kk < 4; kk++) {
            const int kkE = kk*16;
            uint32_t ah[2][4], al[2][4];
            #pragma unroll
            for (int rb = 0; rb < 2; rb++) {
                int abase = so + (32*wr + 16*rb)*PITCH + kkE + aLaneE;
                LDSM4(ah[rb], smb + (uint32_t)((O_AH + abase)*2));
                if (!AF16) LDSM4(al[rb], smb + (uint32_t)((O_AL + abase)*2));
            }
            if (!DUAL) {
                #pragma unroll
                for (int nb2 = 0; nb2 < NBT/2; nb2++) {
                    uint32_t bh[4], bl[4];
                    int bbase = so + (8*NBT*wc4 + 16*nb2)*PITCH + kkE + bLaneE;
                    LDSM4(bh, smb + (uint32_t)((O_BH + bbase)*2));
                    LDSM4(bl, smb + (uint32_t)((O_BL + bbase)*2));
                    #pragma unroll
                    for (int rb = 0; rb < 2; rb++)
                        #pragma unroll
                        for (int j = 0; j < 2; j++) {
                            float* d = accg[rb][2*nb2 + j];
                            if (AF16) {
                                MMA_F16(d, ah[rb], bh[2*j], bh[2*j+1]);
                                MMA_F16(d, ah[rb], bl[2*j], bl[2*j+1]);
                            } else {
                                MMA_BF16(d, ah[rb], bh[2*j], bh[2*j+1]);
                                MMA_BF16(d, al[rb], bh[2*j], bh[2*j+1]);
                                MMA_BF16(d, ah[rb], bl[2*j], bl[2*j+1]);
                            }
                        }
                }
            } else {
                #pragma unroll
                for (int nb2 = 0; nb2 < NBT/2; nb2++) {
                    uint32_t bh[4], bl[4], dh[4], el[4];
                    int bbase = so + (8*NBT*wc4 + 16*nb2)*PITCH + kkE + bLaneE;
                    int sbase = bbase + (32*NBT)*PITCH;
                    LDSM4(bh, smb + (uint32_t)((O_BH + bbase)*2));
                    LDSM4(bl, smb + (uint32_t)((O_BL + bbase)*2));
                    LDSM4(dh, smb + (uint32_t)((O_BH + sbase)*2));
                    LDSM4(el, smb + (uint32_t)((O_BL + sbase)*2));
                    #pragma unroll
                    for (int rb = 0; rb < 2; rb++)
                        #pragma unroll
                        for (int j = 0; j < 2; j++) {
                            float* dg = accg[rb][2*nb2 + j];
                            float* ds = accs[rb][2*nb2 + j];
                            if (AF16) {
                                MMA_F16(dg, ah[rb], bh[2*j], bh[2*j+1]);
                                MMA_F16(dg, ah[rb], bl[2*j], bl[2*j+1]);
                                MMA_F16(ds, ah[rb], dh[2*j], dh[2*j+1]);
                                MMA_F16(ds, ah[rb], el[2*j], el[2*j+1]);
                            } else {
                                MMA_BF16(dg, ah[rb], bh[2*j], bh[2*j+1]);
                                MMA_BF16(dg, al[rb], bh[2*j], bh[2*j+1]);
                                MMA_BF16(dg, ah[rb], bl[2*j], bl[2*j+1]);
                                MMA_BF16(ds, ah[rb], dh[2*j], dh[2*j+1]);
                                MMA_BF16(ds, al[rb], dh[2*j], dh[2*j+1]);
                                MMA_BF16(ds, ah[rb], el[2*j], el[2*j+1]);
                            }
                        }
                }
            }
        }
    }

    // ---- epilogue ----
    float cs0[STATS ? NBT : 1], cs1[STATS ? NBT : 1], cq0[STATS ? NBT : 1], cq1[STATS ? NBT : 1];
    if (STATS) {
        #pragma unroll
        for (int nb = 0; nb < NBT; nb++) { cs0[nb]=0.f; cs1[nb]=0.f; cq0[nb]=0.f; cq1[nb]=0.f; }
    }
    #pragma unroll
    for (int rb = 0; rb < 2; rb++) {
        int m0 = bm + 32*wr + 16*rb + g;
        #pragma unroll
        for (int nb = 0; nb < NBT; nb++) {
            if (!DUAL) {
                int col = bn + 8*NBT*wc4 + 8*nb + 2*t;
                float2 v0 = make_float2(accg[rb][nb][0], accg[rb][nb][1]);
                float2 v1 = make_float2(accg[rb][nb][2], accg[rb][nb][3]);
                if (EPI == 0) {
                    if (bias != nullptr) {
                        float2 bv = *(const float2*)(bias + col);
                        v0.x += bv.x; v0.y += bv.y; v1.x += bv.x; v1.y += bv.y;
                    }
                } else if (EPI == 1) {
                    float2 aa = *(const float2*)(g_bna + col);
                    float2 ab = *(const float2*)(g_bnb + col);
                    float2 dv = *(const float2*)(dvec + col);
                    float2 h0, h1;
                    if (AUXH) {
                        const __half* ah2 = (const __half*)auxv;
                        h0 = __half22float2(*(const __half2*)(ah2 + (size_t)m0*DE + col));
                        h1 = __half22float2(*(const __half2*)(ah2 + (size_t)(m0+8)*DE + col));
                    } else {
                        const float* af = (const float*)auxv;
                        h0 = *(const float2*)(af + (size_t)m0*DE + col);
                        h1 = *(const float2*)(af + (size_t)(m0+8)*DE + col);
                    }
                    v0.x += fmaf(aa.x, h0.x, ab.x)*dv.x;
                    v0.y += fmaf(aa.y, h0.y, ab.y)*dv.y;
                    v1.x += fmaf(aa.x, h1.x, ab.x)*dv.x;
                    v1.y += fmaf(aa.y, h1.y, ab.y)*dv.y;
                } else if (EPI == 2) {
                    float2 bv = *(const float2*)(bias + col);
                    const float* af = (const float*)auxv;
                    float2 y0 = *(const float2*)(af + (size_t)m0*OUTW + col);
                    float2 y1 = *(const float2*)(af + (size_t)(m0+8)*OUTW + col);
                    v0.x += bv.x + y0.x; v0.y += bv.y + y0.y;
                    v1.x += bv.x + y1.x; v1.y += bv.y + y1.y;
                }
                if (STATS) {
                    cs0[nb] += v0.x + v1.x;
                    cs1[nb] += v0.y + v1.y;
                    cq0[nb] += v0.x*v0.x + v1.x*v1.x;
                    cq1[nb] += v0.y*v0.y + v1.y*v1.y;
                }
                if (OUTH == 1) {
                    __half* Ch = (__half*)Cv;
                    *(__half2*)(Ch + (size_t)m0*OUTW + col)     = __floats2half2_rn(v0.x, v0.y);
                    *(__half2*)(Ch + (size_t)(m0+8)*OUTW + col) = __floats2half2_rn(v1.x, v1.y);
                } else if (OUTH == 2) {
                    float* Cf = (float*)Cv;
                    *(float2*)(Cf + (size_t)m0*OUTW + col)     = v0;
                    *(float2*)(Cf + (size_t)(m0+8)*OUTW + col) = v1;
                    *(__half2*)(g_h + (size_t)m0*OUTW + col)     = __floats2half2_rn(v0.x, v0.y);
                    *(__half2*)(g_h + (size_t)(m0+8)*OUTW + col) = __floats2half2_rn(v1.x, v1.y);
                } else {
                    float* Cf = (float*)Cv;
                    *(float2*)(Cf + (size_t)m0*OUTW + col)     = v0;
                    *(float2*)(Cf + (size_t)(m0+8)*OUTW + col) = v1;
                }
            } else {
                int jc = bn + 8*NBT*wc4 + 8*nb + 2*t;
                float2 bg = *(const float2*)(bias + jc);
                float2 bs = *(const float2*)(bias + 256 + jc);
                float g0 = accg[rb][nb][0] + bg.x, s0 = accs[rb][nb][0] + bs.x;
                float g1 = accg[rb][nb][1] + bg.y, s1 = accs[rb][nb][1] + bs.y;
                float g2 = accg[rb][nb][2] + bg.x, s2 = accs[rb][nb][2] + bs.x;
                float g3 = accg[rb][nb][3] + bg.y, s3 = accs[rb][nb][3] + bs.y;
                float2 v0, v1;
                v0.x = g0 * (1.f/(1.f + expf(-s0)));
                v0.y = g1 * (1.f/(1.f + expf(-s1)));
                v1.x = g2 * (1.f/(1.f + expf(-s2)));
                v1.y = g3 * (1.f/(1.f + expf(-s3)));
                __half* Ch = (__half*)Cv;
                *(__half2*)(Ch + (size_t)m0*OUTW + jc)     = __floats2half2_rn(v0.x, v0.y);
                *(__half2*)(Ch + (size_t)(m0+8)*OUTW + jc) = __floats2half2_rn(v1.x, v1.y);
            }
        }
    }

    if (STATS && !DUAL) {
        #pragma unroll
        for (int nb = 0; nb < NBT; nb++) {
            #pragma unroll
            for (int m = 4; m <= 16; m <<= 1) {
                cs0[nb] += __shfl_xor_sync(0xffffffffu, cs0[nb], m);
                cs1[nb] += __shfl_xor_sync(0xffffffffu, cs1[nb], m);
                cq0[nb] += __shfl_xor_sync(0xffffffffu, cq0[nb], m);
                cq1[nb] += __shfl_xor_sync(0xffffffffu, cq1[nb], m);
            }
        }
        __syncthreads();
        float* spart = (float*)sm;
        if (lane < 4) {
            #pragma unroll
            for (int nb = 0; nb < NBT; nb++) {
                int col = 8*NBT*wc4 + 8*nb + 2*lane;
                spart[wr*128 + col]           = cs0[nb];
                spart[wr*128 + col + 1]       = cs1[nb];
                spart[512 + wr*128 + col]     = cq0[nb];
                spart[512 + wr*128 + col + 1] = cq1[nb];
            }
        }
        __syncthreads();
        if (tid < 128) {
            float s  = spart[tid] + spart[128+tid] + spart[256+tid] + spart[384+tid];
            float s2 = spart[512+tid] + spart[640+tid] + spart[768+tid] + spart[896+tid];
            g_bnpart[blockIdx.y*(2*DE) + tid]      = s;
            g_bnpart[blockIdx.y*(2*DE) + DE + tid] = s2;
        }
    }
}

// ---------------- LRU scan (fp16 Bu in, in-place fp16 state out) ----------------
__device__ __forceinline__ float2 cstep(float2 lam, float2 s, float2 u) {
    float2 t;
    t.x = fmaf(lam.x, s.x, fmaf(-lam.y, s.y, u.x));
    t.y = fmaf(lam.x, s.y, fmaf( lam.y, s.x, u.y));
    return t;
}
__device__ __forceinline__ float2 ldh2(const uint32_t* p, size_t off) {
    uint32_t r = p[off];
    return __half22float2(*(__half2*)&r);
}
__global__ void scanA_kernel(int blk) {
    int g  = blockIdx.x*256 + threadIdx.x;
    int h  = g & 255;
    int bc = g >> 8;
    int b  = bc >> 4;
    int c  = bc & 15;
    float2 lam = g_lam[blk*HH + h];
    float2 s = make_float2(0.f, 0.f);
    const uint32_t* p = (const uint32_t*)g_bu;
    size_t base = (size_t)(b*TT + c*CLEN)*256 + h;
    #pragma unroll 8
    for (int i = 0; i < CLEN; i++)
        s = cstep(lam, s, ldh2(p, base + (size_t)i*256));
    g_carry[bc*HH + h] = s;
}
__global__ void scanB_kernel(int blk) {
    int b = blockIdx.x;
    int h = threadIdx.x;
    float2 lam = g_lam[blk*HH + h];
    float2 lp = lam;
    #pragma unroll
    for (int i = 0; i < 8; i++) {
        float2 t;
        t.x = lp.x*lp.x - lp.y*lp.y;
        t.y = 2.f*lp.x*lp.y;
        lp = t;
    }
    float2 s = make_float2(0.f, 0.f);
    for (int c = 0; c < NCH; c++) {
        g_inc[(b*NCH + c)*HH + h] = s;
        float2 cr = g_carry[(b*NCH + c)*HH + h];
        s = cstep(lp, s, cr);
    }
}
__global__ void scanC_kernel(int blk) {
    int g  = blockIdx.x*256 + threadIdx.x;
    int h  = g & 255;
    int bc = g >> 8;
    int b  = bc >> 4;
    int c  = bc & 15;
    float2 lam = g_lam[blk*HH + h];
    float2 s = g_inc[bc*HH + h];
    uint32_t* p = (uint32_t*)g_bu;
    size_t base = (size_t)(b*TT + c*CLEN)*256 + h;
    #pragma unroll 8
    for (int i = 0; i < CLEN; i++) {
        size_t off = base + (size_t)i*256;
        s = cstep(lam, s, ldh2(p, off));
        __half2 sv = __floats2half2_rn(s.x, s.y);
        p[off] = *(uint32_t*)&sv;
    }
}

// ---------------- final: mean-pool + head (fp16 h) ----------------
__global__ void final_kernel(const float* __restrict__ Wout,
                             const float* __restrict__ bout,
                             float* __restrict__ out) {
    __shared__ float pooled[DE];
    int b = blockIdx.x;
    int f = threadIdx.x;
    float s = 0.f;
    const __half* p = g_h + (size_t)b*TT*DE + f;
    #pragma unroll 4
    for (int t = 0; t < TT; t++) s += __half2float(p[(size_t)t*DE]);
    pooled[f] = s * (1.f/TT);
    __syncthreads();
    if (f < OD) {
        float acc = bout[f];
        #pragma unroll 4
        for (int d = 0; d < DE; d++) acc = fmaf(pooled[d], Wout[d*OD + f], acc);
        out[b*OD + f] = acc;
    }
}

// ---------------- launch ----------------
#define SMEM_ENC   147456   // f32A, NBT=4
#define SMEM_BU16  184320   // f16A, NBT=8
#define SMEM_F16N4 110592   // f16A, NBT=4
#define SMEM_GLU   184320   // f16A, DUAL NBT=4

extern "C" void kernel_launch(void* const* d_in, const int* in_sizes, int n_in,
                              void* d_out, int out_size) {
    const float* x         = (const float*)d_in[0];
    const float* nu_log    = (const float*)d_in[1];
    const float* theta_log = (const float*)d_in[2];
    const float* B_re      = (const float*)d_in[3];
    const float* B_im      = (const float*)d_in[4];
    const float* C_re      = (const float*)d_in[5];
    const float* C_im      = (const float*)d_in[6];
    const float* D_lru     = (const float*)d_in[7];
    const float* W1        = (const float*)d_in[8];
    const float* b1        = (const float*)d_in[9];
    const float* W2        = (const float*)d_in[10];
    const float* b2        = (const float*)d_in[11];
    const float* bn_scale  = (const float*)d_in[12];
    const float* bn_bias   = (const float*)d_in[13];
    const float* W_enc     = (const float*)d_in[14];
    const float* b_enc     = (const float*)d_in[15];
    const float* W_out     = (const float*)d_in[16];
    const float* b_out     = (const float*)d_in[17];
    float* out = (float*)d_out;

    float *yenc, *bubias;
    __half *hh, *bu, *lru, *glu, *wbfh, *wbfl, *wch, *wcl, *w1h, *w1l, *w2h, *w2l;
    __nv_bfloat16 *weh, *wel;
    cudaGetSymbolAddress((void**)&yenc, g_yenc);
    cudaGetSymbolAddress((void**)&hh,   g_h);
    cudaGetSymbolAddress((void**)&bu,   g_bu);
    cudaGetSymbolAddress((void**)&lru,  g_lru);
    cudaGetSymbolAddress((void**)&glu,  g_glu);
    cudaGetSymbolAddress((void**)&wbfh, g_WBfh);
    cudaGetSymbolAddress((void**)&wbfl, g_WBfl);
    cudaGetSymbolAddress((void**)&weh,  g_WEh);
    cudaGetSymbolAddress((void**)&wel,  g_WEl);
    cudaGetSymbolAddress((void**)&wch,  g_WCh);
    cudaGetSymbolAddress((void**)&wcl,  g_WCl);
    cudaGetSymbolAddress((void**)&w1h,  g_W1h);
    cudaGetSymbolAddress((void**)&w1l,  g_W1l);
    cudaGetSymbolAddress((void**)&w2h,  g_W2h);
    cudaGetSymbolAddress((void**)&w2l,  g_W2l);
    cudaGetSymbolAddress((void**)&bubias, g_bubias);

    cudaFuncSetAttribute(gemm_mma<64, 128, 0, 0, 0, 0, 2, 1, 4, 0>,  cudaFuncAttributeMaxDynamicSharedMemorySize, SMEM_ENC);
    cudaFuncSetAttribute(gemm_mma<128, 512, 0, 0, 0, 1, 1, 0, 8, 0>, cudaFuncAttributeMaxDynamicSharedMemorySize, SMEM_BU16);
    cudaFuncSetAttribute(gemm_mma<512, 128, 0, 1, 0, 1, 1, 0, 4, 1>, cudaFuncAttributeMaxDynamicSharedMemorySize, SMEM_F16N4);
    cudaFuncSetAttribute(gemm_mma<128, 256, 0, 0, 1, 1, 1, 0, 4, 0>, cudaFuncAttributeMaxDynamicSharedMemorySize, SMEM_GLU);
    cudaFuncSetAttribute(gemm_mma<256, 128, 0, 2, 0, 1, 1, 1, 4, 0>, cudaFuncAttributeMaxDynamicSharedMemorySize, SMEM_F16N4);

    prep_lam_kernel<<<NBLKS, HH>>>(nu_log, theta_log);
    prep_WE_kernel<<<(DE*TSD + 255)/256, 256>>>(W_enc);
    prep_WBf_kernel<<<(NBLKS*512*DE + 255)/256, 256>>>(B_re, B_im);

    // encoder: yenc(fp32) + h copy(fp16) = x @ W_enc + b_enc  (+ BN partials for block 0)
    gemm_mma<64, 128, 0, 0, 0, 0, 2, 1, 4, 0><<<dim3(1, NR/128), NTHR, SMEM_ENC>>>(
        x, weh, wel, yenc, b_enc, nullptr, nullptr);

    prep_WC_kernel<<<(NBLKS*DE*512 + 255)/256, 256>>>(C_re, C_im);
    prep_W1_kernel<<<(NBLKS*512*DE + 255)/256, 256>>>(W1);
    prep_W2_kernel<<<(NBLKS*DE*256 + 255)/256, 256>>>(W2);

    for (int blk = 0; blk < NBLKS; blk++) {
        bn_stats2_kernel<<<1, 512>>>(bn_scale + blk*DE, bn_bias + blk*DE);
        fold_WB_kernel<<<256, 256>>>(blk);
        fold_bias_kernel<<<1, 512>>>(blk);

        // Bu = h @ (diag(a)WB) + (b.WB)   (fp16 A, 2-term, 256-wide tiles)
        gemm_mma<128, 512, 0, 0, 0, 1, 1, 0, 8, 0><<<dim3(2, NR/128), NTHR, SMEM_BU16>>>(
            hh, wbfh, wbfl, bu, bubias, nullptr, nullptr);

        scanA_kernel<<<NR/256, 256>>>(blk);
        scanB_kernel<<<BB, HH>>>(blk);
        scanC_kernel<<<NR/256, 256>>>(blk);

        // lru = Re(state @ C) + BN(h) * D   (aux h fp16)
        gemm_mma<512, 128, 0, 1, 0, 1, 1, 0, 4, 1><<<dim3(1, NR/128), NTHR, SMEM_F16N4>>>(
            bu, wch + (size_t)blk*128*512, wcl + (size_t)blk*128*512,
            lru, nullptr, hh, D_lru + blk*DE);

        // glu = GLU(lru @ W1 + b1)
        gemm_mma<128, 256, 0, 0, 1, 1, 1, 0, 4, 0><<<dim3(2, NR/128), NTHR, SMEM_GLU>>>(
            lru, w1h + (size_t)blk*512*128, w1l + (size_t)blk*512*128,
            glu, b1 + (size_t)blk*LDF, nullptr, nullptr);

        // h(fp16) = glu @ W2 + b2 + yenc(fp32)  (+ BN partials for next block)
        gemm_mma<256, 128, 0, 2, 0, 1, 1, 1, 4, 0><<<dim3(1, NR/128), NTHR, SMEM_F16N4>>>(
            glu, w2h + (size_t)blk*128*256, w2l + (size_t)blk*128*256,
            hh, b2 + blk*DE, yenc, nullptr);
    }

    final_kernel<<<BB, DE>>>(W_out, b_out, out);
}